// round 3
// baseline (speedup 1.0000x reference)
#include <cuda_runtime.h>
#include <math.h>

#define EMB    2048
#define SEQ    2048
#define BATCH  2
#define NHEADS 16
#define NKVH   4
#define HDIM   128
#define KVDIM  (NKVH * HDIM)      /* 512  */
#define MROWS  (BATCH * SEQ)      /* 4096 */

// -------- scratch (device globals: no allocations allowed) ----------------
__device__ float g_q[(size_t)MROWS * EMB];
__device__ float g_k[(size_t)MROWS * KVDIM];
__device__ float g_v[(size_t)MROWS * KVDIM];
__device__ float g_z[(size_t)MROWS * EMB];

// ===========================================================================
// SGEMM: C[M,N] = A[M,K] * B[N,K]^T   (row-major A, B, C)
// 128x128 tile, BK=16, 256 threads, 8x8 per thread, double-buffered smem.
// Optional fused RoPE (+ 1/sqrt(HDIM) scale) epilogue for Q/K projections.
// Requires: M%128==0, N%128==0, K%16==0, and for ROPE: N tile == head (128).
// ===========================================================================
template <bool ROPE, bool QSC>
__global__ __launch_bounds__(256)
void sgemm_nt(const float* __restrict__ A, const float* __restrict__ Bw,
              float* __restrict__ C, int Md, int Nd, int Kd)
{
    __shared__ float As[2][16][132];
    __shared__ float Bs[2][16][132];

    const int tid = threadIdx.x;
    const int tx  = tid & 15;
    const int ty  = tid >> 4;
    const int bn  = blockIdx.x;
    const int bm  = blockIdx.y;

    const float* Ab = A  + (size_t)bm * 128 * Kd;
    const float* Bb = Bw + (size_t)bn * 128 * Kd;

    float acc[8][8];
#pragma unroll
    for (int i = 0; i < 8; i++)
#pragma unroll
        for (int j = 0; j < 8; j++) acc[i][j] = 0.f;

    const int r0  = tid >> 2,        c40 = tid & 3;
    const int r1  = (tid + 256) >> 2, c41 = (tid + 256) & 3;

    float4 ra0, ra1, rb0, rb1;

    // prologue: load tile 0
    ra0 = *(const float4*)(Ab + (size_t)r0 * Kd + c40 * 4);
    ra1 = *(const float4*)(Ab + (size_t)r1 * Kd + c41 * 4);
    rb0 = *(const float4*)(Bb + (size_t)r0 * Kd + c40 * 4);
    rb1 = *(const float4*)(Bb + (size_t)r1 * Kd + c41 * 4);
    As[0][c40*4+0][r0] = ra0.x; As[0][c40*4+1][r0] = ra0.y;
    As[0][c40*4+2][r0] = ra0.z; As[0][c40*4+3][r0] = ra0.w;
    As[0][c41*4+0][r1] = ra1.x; As[0][c41*4+1][r1] = ra1.y;
    As[0][c41*4+2][r1] = ra1.z; As[0][c41*4+3][r1] = ra1.w;
    Bs[0][c40*4+0][r0] = rb0.x; Bs[0][c40*4+1][r0] = rb0.y;
    Bs[0][c40*4+2][r0] = rb0.z; Bs[0][c40*4+3][r0] = rb0.w;
    Bs[0][c41*4+0][r1] = rb1.x; Bs[0][c41*4+1][r1] = rb1.y;
    Bs[0][c41*4+2][r1] = rb1.z; Bs[0][c41*4+3][r1] = rb1.w;

    const int NK = Kd >> 4;
    for (int kt = 0; kt < NK; ++kt) {
        __syncthreads();
        const int  cur  = kt & 1;
        const bool more = (kt + 1 < NK);
        if (more) {
            const float* Ak = Ab + (size_t)(kt + 1) * 16;
            const float* Bk = Bb + (size_t)(kt + 1) * 16;
            ra0 = *(const float4*)(Ak + (size_t)r0 * Kd + c40 * 4);
            ra1 = *(const float4*)(Ak + (size_t)r1 * Kd + c41 * 4);
            rb0 = *(const float4*)(Bk + (size_t)r0 * Kd + c40 * 4);
            rb1 = *(const float4*)(Bk + (size_t)r1 * Kd + c41 * 4);
        }
#pragma unroll
        for (int kk = 0; kk < 16; ++kk) {
            float a[8], b[8];
            *(float4*)(a)     = *(const float4*)(&As[cur][kk][ty * 4]);
            *(float4*)(a + 4) = *(const float4*)(&As[cur][kk][64 + ty * 4]);
            *(float4*)(b)     = *(const float4*)(&Bs[cur][kk][tx * 4]);
            *(float4*)(b + 4) = *(const float4*)(&Bs[cur][kk][64 + tx * 4]);
#pragma unroll
            for (int i = 0; i < 8; i++)
#pragma unroll
                for (int j = 0; j < 8; j++)
                    acc[i][j] = fmaf(a[i], b[j], acc[i][j]);
        }
        if (more) {
            const int nxt = cur ^ 1;
            As[nxt][c40*4+0][r0] = ra0.x; As[nxt][c40*4+1][r0] = ra0.y;
            As[nxt][c40*4+2][r0] = ra0.z; As[nxt][c40*4+3][r0] = ra0.w;
            As[nxt][c41*4+0][r1] = ra1.x; As[nxt][c41*4+1][r1] = ra1.y;
            As[nxt][c41*4+2][r1] = ra1.z; As[nxt][c41*4+3][r1] = ra1.w;
            Bs[nxt][c40*4+0][r0] = rb0.x; Bs[nxt][c40*4+1][r0] = rb0.y;
            Bs[nxt][c40*4+2][r0] = rb0.z; Bs[nxt][c40*4+3][r0] = rb0.w;
            Bs[nxt][c41*4+0][r1] = rb1.x; Bs[nxt][c41*4+1][r1] = rb1.y;
            Bs[nxt][c41*4+2][r1] = rb1.z; Bs[nxt][c41*4+3][r1] = rb1.w;
        }
    }

    // ---------------- epilogue (optional fused RoPE + scale) --------------
    const float qscale = 0.08838834764831844f; // 1/sqrt(128)
    float freqv[4];
    if (ROPE) {
#pragma unroll
        for (int g = 0; g < 4; ++g) {
            int jb = g * 2;
            int d0 = (jb < 4) ? (tx * 4 + jb) : (64 + tx * 4 + (jb - 4));
            int ip = d0 >> 1;                       // pair index 0..63
            // 10000^(-ip/64) computed in double, rounded to fp32
            freqv[g] = (float)exp((double)ip * -0.14391156831212787);
        }
    }
#pragma unroll
    for (int i = 0; i < 8; i++) {
        int    r  = (i < 4) ? (ty * 4 + i) : (64 + ty * 4 + (i - 4));
        size_t mg = (size_t)bm * 128 + r;
        float  vals[8];
#pragma unroll
        for (int j = 0; j < 8; j++) vals[j] = acc[i][j];
        if (ROPE) {
            int   s = (int)(mg % SEQ);
            float t = (float)s * 6.28318530717958647692f;  // s * 2pi (fp32)
#pragma unroll
            for (int g = 0; g < 4; ++g) {
                float ang = t * freqv[g];
                // Cody-Waite reduction (safe even under fast-math)
                float kq = rintf(ang * 0.15915494309189535f);
                float x  = fmaf(kq, -6.28125f, ang);
                x        = fmaf(kq, -0.0019353071795864769f, x);
                float sn = sinf(x), cs = cosf(x);
                int   jb = g * 2;
                float v0 = vals[jb], v1 = vals[jb + 1];
                vals[jb]     = v0 * cs - v1 * sn;
                vals[jb + 1] = v0 * sn + v1 * cs;
            }
        }
        if (QSC) {
#pragma unroll
            for (int j = 0; j < 8; j++) vals[j] *= qscale;
        }
        float* Cr = C + mg * Nd + (size_t)bn * 128;
        *(float4*)(Cr + tx * 4)      = make_float4(vals[0], vals[1], vals[2], vals[3]);
        *(float4*)(Cr + 64 + tx * 4) = make_float4(vals[4], vals[5], vals[6], vals[7]);
    }
}

// ===========================================================================
// Flash attention, fp32, BM=BN=64, D=128, 256 threads, GQA (kv = h/4).
// q already scaled by 1/sqrt(D) and RoPE'd; k RoPE'd.
// smem: Qt[128][65] + Kt[128][65] (k-major, conflict-free) +
//       Vs[64][129] + Ps[64][65]  => 116224 bytes dynamic.
// ===========================================================================
__global__ __launch_bounds__(256)
void flash_attn(const float* __restrict__ q, const float* __restrict__ k,
                const float* __restrict__ v, float* __restrict__ z,
                const int* __restrict__ is_causal)
{
    extern __shared__ float sm[];
    float* Qt = sm;                    // 128*65
    float* Kt = Qt + 128 * 65;         // 128*65
    float* Vs = Kt + 128 * 65;         // 64*129
    float* Ps = Vs + 64 * 129;         // 64*65

    const int tid = threadIdx.x;
    const int tx  = tid & 15;
    const int ty  = tid >> 4;
    const int qt  = blockIdx.x;
    const int h   = blockIdx.y;
    const int b   = blockIdx.z;
    const int kvh = h >> 2;            // GROUP = 4
    const bool causal = (*is_causal) != 0;

    // ---- load Q tile (transposed to k-major) ----
    const float* qb = q + ((size_t)(b * SEQ + qt * 64)) * EMB + h * HDIM;
#pragma unroll
    for (int p = 0; p < 8; p++) {
        int lin = tid + p * 256;
        int r = lin >> 5, c4 = lin & 31;
        float4 t4 = *(const float4*)(qb + (size_t)r * EMB + c4 * 4);
        Qt[(c4 * 4 + 0) * 65 + r] = t4.x;
        Qt[(c4 * 4 + 1) * 65 + r] = t4.y;
        Qt[(c4 * 4 + 2) * 65 + r] = t4.z;
        Qt[(c4 * 4 + 3) * 65 + r] = t4.w;
    }

    float mrow[4], lrow[4], Oa[4][8];
#pragma unroll
    for (int i = 0; i < 4; i++) {
        mrow[i] = -1e30f; lrow[i] = 0.f;
#pragma unroll
        for (int c = 0; c < 8; c++) Oa[i][c] = 0.f;
    }

    const int ktend = causal ? qt : (SEQ / 64 - 1);
    for (int kt = 0; kt <= ktend; ++kt) {
        __syncthreads();  // previous PV done before overwriting Kt/Vs
        const float* kb = k + ((size_t)(b * SEQ + kt * 64)) * KVDIM + kvh * HDIM;
        const float* vb = v + ((size_t)(b * SEQ + kt * 64)) * KVDIM + kvh * HDIM;
#pragma unroll
        for (int p = 0; p < 8; p++) {
            int lin = tid + p * 256;
            int r = lin >> 5, c4 = lin & 31;
            float4 k4 = *(const float4*)(kb + (size_t)r * KVDIM + c4 * 4);
            Kt[(c4 * 4 + 0) * 65 + r] = k4.x;
            Kt[(c4 * 4 + 1) * 65 + r] = k4.y;
            Kt[(c4 * 4 + 2) * 65 + r] = k4.z;
            Kt[(c4 * 4 + 3) * 65 + r] = k4.w;
            float4 v4 = *(const float4*)(vb + (size_t)r * KVDIM + c4 * 4);
            Vs[r * 129 + c4 * 4 + 0] = v4.x;
            Vs[r * 129 + c4 * 4 + 1] = v4.y;
            Vs[r * 129 + c4 * 4 + 2] = v4.z;
            Vs[r * 129 + c4 * 4 + 3] = v4.w;
        }
        __syncthreads();

        // ---- scores: S = Q @ K^T (4x4 per thread) ----
        float sc[4][4];
#pragma unroll
        for (int i = 0; i < 4; i++)
#pragma unroll
            for (int j = 0; j < 4; j++) sc[i][j] = 0.f;
#pragma unroll 8
        for (int kk = 0; kk < 128; ++kk) {
            const float* qrow = &Qt[kk * 65 + ty * 4];
            const float* krow = &Kt[kk * 65 + tx * 4];
            float qa0 = qrow[0], qa1 = qrow[1], qa2 = qrow[2], qa3 = qrow[3];
#pragma unroll
            for (int j = 0; j < 4; j++) {
                float kv = krow[j];
                sc[0][j] = fmaf(qa0, kv, sc[0][j]);
                sc[1][j] = fmaf(qa1, kv, sc[1][j]);
                sc[2][j] = fmaf(qa2, kv, sc[2][j]);
                sc[3][j] = fmaf(qa3, kv, sc[3][j]);
            }
        }

        if (causal && kt == qt) {
#pragma unroll
            for (int i = 0; i < 4; i++)
#pragma unroll
                for (int j = 0; j < 4; j++)
                    if (tx * 4 + j > ty * 4 + i) sc[i][j] = -1e30f;
        }

        // ---- online softmax update (reduce across the 16 tx lanes) ----
#pragma unroll
        for (int i = 0; i < 4; i++) {
            float tm = fmaxf(fmaxf(sc[i][0], sc[i][1]), fmaxf(sc[i][2], sc[i][3]));
#pragma unroll
            for (int off = 1; off < 16; off <<= 1)
                tm = fmaxf(tm, __shfl_xor_sync(0xffffffffu, tm, off));
            float mnew  = fmaxf(mrow[i], tm);
            float alpha = __expf(mrow[i] - mnew);
            mrow[i] = mnew;
            float ps = 0.f;
#pragma unroll
            for (int j = 0; j < 4; j++) {
                sc[i][j] = __expf(sc[i][j] - mnew);
                ps += sc[i][j];
            }
#pragma unroll
            for (int off = 1; off < 16; off <<= 1)
                ps += __shfl_xor_sync(0xffffffffu, ps, off);
            lrow[i] = lrow[i] * alpha + ps;
#pragma unroll
            for (int c = 0; c < 8; c++) Oa[i][c] *= alpha;
            Ps[(ty * 4 + i) * 65 + tx * 4 + 0] = sc[i][0];
            Ps[(ty * 4 + i) * 65 + tx * 4 + 1] = sc[i][1];
            Ps[(ty * 4 + i) * 65 + tx * 4 + 2] = sc[i][2];
            Ps[(ty * 4 + i) * 65 + tx * 4 + 3] = sc[i][3];
        }
        __syncthreads();

        // ---- O += P @ V ----
#pragma unroll 4
        for (int j = 0; j < 64; ++j) {
            float p0 = Ps[(ty * 4 + 0) * 65 + j];
            float p1 = Ps[(ty * 4 + 1) * 65 + j];
            float p2 = Ps[(ty * 4 + 2) * 65 + j];
            float p3 = Ps[(ty * 4 + 3) * 65 + j];
            const float* vr = &Vs[j * 129 + tx * 4];
#pragma unroll
            for (int c = 0; c < 4; c++) {
                float vv = vr[c];
                Oa[0][c] = fmaf(p0, vv, Oa[0][c]);
                Oa[1][c] = fmaf(p1, vv, Oa[1][c]);
                Oa[2][c] = fmaf(p2, vv, Oa[2][c]);
                Oa[3][c] = fmaf(p3, vv, Oa[3][c]);
            }
#pragma unroll
            for (int c = 0; c < 4; c++) {
                float vv = vr[64 + c];
                Oa[0][4 + c] = fmaf(p0, vv, Oa[0][4 + c]);
                Oa[1][4 + c] = fmaf(p1, vv, Oa[1][4 + c]);
                Oa[2][4 + c] = fmaf(p2, vv, Oa[2][4 + c]);
                Oa[3][4 + c] = fmaf(p3, vv, Oa[3][4 + c]);
            }
        }
    }

    // ---- finalize: O / l, write z ----
    float* zb = z + ((size_t)(b * SEQ + qt * 64)) * EMB + h * HDIM;
#pragma unroll
    for (int i = 0; i < 4; i++) {
        float inv = 1.0f / lrow[i];
        int   r   = ty * 4 + i;
        float4 o0 = make_float4(Oa[i][0] * inv, Oa[i][1] * inv,
                                Oa[i][2] * inv, Oa[i][3] * inv);
        float4 o1 = make_float4(Oa[i][4] * inv, Oa[i][5] * inv,
                                Oa[i][6] * inv, Oa[i][7] * inv);
        *(float4*)(zb + (size_t)r * EMB + tx * 4)      = o0;
        *(float4*)(zb + (size_t)r * EMB + 64 + tx * 4) = o1;
    }
}

// ===========================================================================
extern "C" void kernel_launch(void* const* d_in, const int* in_sizes, int n_in,
                              void* d_out, int out_size)
{
    (void)in_sizes; (void)n_in; (void)out_size;
    const float* x   = (const float*)d_in[0];
    const float* Wq  = (const float*)d_in[1];
    const float* Wk  = (const float*)d_in[2];
    const float* Wv  = (const float*)d_in[3];
    const float* Wo  = (const float*)d_in[4];
    const int*   isc = (const int*)d_in[5];

    float *q, *k, *v, *z;
    cudaGetSymbolAddress((void**)&q, g_q);
    cudaGetSymbolAddress((void**)&k, g_k);
    cudaGetSymbolAddress((void**)&v, g_v);
    cudaGetSymbolAddress((void**)&z, g_z);

    dim3 blk(256);

    // projections (RoPE fused into Q and K; Q also pre-scaled by 1/sqrt(d))
    sgemm_nt<true,  true ><<<dim3(EMB   / 128, MROWS / 128), blk>>>(x, Wq, q, MROWS, EMB,   EMB);
    sgemm_nt<true,  false><<<dim3(KVDIM / 128, MROWS / 128), blk>>>(x, Wk, k, MROWS, KVDIM, EMB);
    sgemm_nt<false, false><<<dim3(KVDIM / 128, MROWS / 128), blk>>>(x, Wv, v, MROWS, KVDIM, EMB);

    // attention
    size_t shm = (size_t)(2 * 128 * 65 + 64 * 129 + 64 * 65) * sizeof(float); // 116224
    cudaFuncSetAttribute(flash_attn, cudaFuncAttributeMaxDynamicSharedMemorySize, (int)shm);
    flash_attn<<<dim3(SEQ / 64, NHEADS, BATCH), blk, shm>>>(q, k, v, z, isc);

    // output projection -> d_out
    sgemm_nt<false, false><<<dim3(EMB / 128, MROWS / 128), blk>>>(z, Wo, (float*)d_out,
                                                                  MROWS, EMB, EMB);
}

// round 5
// speedup vs baseline: 1.0183x; 1.0183x over previous
#include <cuda_runtime.h>
#include <math.h>
#include <stdint.h>

#define EMB    2048
#define SEQ    2048
#define BATCH  2
#define NHEADS 16
#define NKVH   4
#define HDIM   128
#define KVDIM  (NKVH * HDIM)      /* 512  */
#define MROWS  (BATCH * SEQ)      /* 4096 */

// -------- scratch (device globals: no allocations allowed) ----------------
__device__ float g_q[(size_t)MROWS * EMB];
__device__ float g_k[(size_t)MROWS * KVDIM];
__device__ float g_v[(size_t)MROWS * KVDIM];
__device__ float g_z[(size_t)MROWS * EMB];

// ===========================================================================
// fp32 -> (tf32 hi, tf32 lo) split for 3xTF32 emulation
// ===========================================================================
__device__ __forceinline__ void tf32_split(float x, uint32_t& h, uint32_t& l) {
    asm("cvt.rna.tf32.f32 %0, %1;" : "=r"(h) : "f"(x));
    float hf = __uint_as_float(h);
    float lo = x - hf;                 // exact in fp32
    asm("cvt.rna.tf32.f32 %0, %1;" : "=r"(l) : "f"(lo));
}

// warp-level tf32 MMA m16n8k8 (sm_80+ instruction; works on plain sm_100)
__device__ __forceinline__ void mma_tf32(float* d,
                                         uint32_t a0, uint32_t a1,
                                         uint32_t a2, uint32_t a3,
                                         uint32_t b0, uint32_t b1) {
    asm volatile(
        "mma.sync.aligned.m16n8k8.row.col.f32.tf32.tf32.f32 "
        "{%0,%1,%2,%3}, {%4,%5,%6,%7}, {%8,%9}, {%0,%1,%2,%3};"
        : "+f"(d[0]), "+f"(d[1]), "+f"(d[2]), "+f"(d[3])
        : "r"(a0), "r"(a1), "r"(a2), "r"(a3), "r"(b0), "r"(b1));
}

// ===========================================================================
// tf32x3 GEMM on mma.sync: C[M,N] = A[M,K] * B[N,K]^T  (all row-major)
// CTA tile 128x128, BK=32, 256 threads = 8 warps (2m x 4n), warp tile 64x32.
// smem layout: per 128-row operand, fragment-permuted [row][kp] with
//   kp(k) = (k&3)*8 + 2*(k>>3) + ((k>>2)&1)   (so element j of float4 at
//   column c lands at kp = 8*j + c), row stride 34 floats (conflict-free v2
//   fragment reads). Four arrays: Ah, Al, Bh, Bl (hi/lo tf32 splits).
// Optional fused RoPE (+1/sqrt(128) scale) epilogue (head width 128 == BN).
// Requires M%128==0, N%128==0, K%32==0.
// ===========================================================================
#define GSTRIDE 34
#define GARR    (128 * GSTRIDE)                    /* 4352 words */
#define GEMM_SMEM_BYTES (4 * GARR * 4)             /* 69632 bytes */

template <bool ROPE, bool QSC>
__global__ __launch_bounds__(256, 2)
void mma_gemm(const float* __restrict__ A, const float* __restrict__ Bw,
              float* __restrict__ C, int Nd, int Kd)
{
    extern __shared__ uint32_t sm[];
    uint32_t* Ah = sm;
    uint32_t* Al = Ah + GARR;
    uint32_t* Bh = Al + GARR;
    uint32_t* Bl = Bh + GARR;

    const int tid  = threadIdx.x;
    const int wid  = tid >> 5;
    const int lane = tid & 31;
    const int g    = lane >> 2;        // 0..7
    const int tig  = lane & 3;         // 0..3
    const int wm   = wid >> 2;         // 0..1
    const int wn   = wid & 3;          // 0..3
    const int bn   = blockIdx.x;
    const int bm   = blockIdx.y;

    const float* Abase = A  + (size_t)(bm * 128) * Kd;
    const float* Bbase = Bw + (size_t)(bn * 128) * Kd;

    float acc[4][4][4];
#pragma unroll
    for (int mt = 0; mt < 4; ++mt)
#pragma unroll
        for (int nt = 0; nt < 4; ++nt)
#pragma unroll
            for (int e = 0; e < 4; ++e) acc[mt][nt][e] = 0.f;

    const int NK = Kd >> 5;
    for (int kt = 0; kt < NK; ++kt) {
        // ---- stage gmem tile in registers (overlaps previous compute) ----
        float4 ra[4], rb[4];
        const float* Ak = Abase + kt * 32;
        const float* Bk = Bbase + kt * 32;
#pragma unroll
        for (int it = 0; it < 4; ++it) {
            const int idx = tid + it * 256;
            const int row = idx >> 3, c = idx & 7;
            ra[it] = *(const float4*)(Ak + (size_t)row * Kd + c * 4);
            rb[it] = *(const float4*)(Bk + (size_t)row * Kd + c * 4);
        }
        __syncthreads();   // previous tile's fragment reads are done

        // ---- split + permuted store to smem ----
#pragma unroll
        for (int it = 0; it < 4; ++it) {
            const int idx = tid + it * 256;
            const int row = idx >> 3, c = idx & 7;
            const int base = row * GSTRIDE + c;
            float va[4] = { ra[it].x, ra[it].y, ra[it].z, ra[it].w };
            float vb[4] = { rb[it].x, rb[it].y, rb[it].z, rb[it].w };
#pragma unroll
            for (int j = 0; j < 4; ++j) {
                uint32_t h, l;
                tf32_split(va[j], h, l);
                Ah[base + 8 * j] = h;  Al[base + 8 * j] = l;
                tf32_split(vb[j], h, l);
                Bh[base + 8 * j] = h;  Bl[base + 8 * j] = l;
            }
        }
        __syncthreads();

        // ---- compute: 4 k-steps of m16n8k8, 3 products each ----
#pragma unroll
        for (int ks = 0; ks < 4; ++ks) {
            uint2 bh[4], bl[4];
#pragma unroll
            for (int nt = 0; nt < 4; ++nt) {
                const int off = (wn * 32 + nt * 8 + g) * GSTRIDE + tig * 8 + 2 * ks;
                bh[nt] = *(const uint2*)(Bh + off);
                bl[nt] = *(const uint2*)(Bl + off);
            }
#pragma unroll
            for (int mt = 0; mt < 4; ++mt) {
                const int r0 = wm * 64 + mt * 16 + g;
                const int o0 = r0 * GSTRIDE + tig * 8 + 2 * ks;
                const uint2 ah0 = *(const uint2*)(Ah + o0);
                const uint2 ah1 = *(const uint2*)(Ah + o0 + 8 * GSTRIDE);
                const uint2 al0 = *(const uint2*)(Al + o0);
                const uint2 al1 = *(const uint2*)(Al + o0 + 8 * GSTRIDE);
#pragma unroll
                for (int nt = 0; nt < 4; ++nt) {
                    mma_tf32(acc[mt][nt], ah0.x, ah1.x, ah0.y, ah1.y, bh[nt].x, bh[nt].y);
                    mma_tf32(acc[mt][nt], ah0.x, ah1.x, ah0.y, ah1.y, bl[nt].x, bl[nt].y);
                    mma_tf32(acc[mt][nt], al0.x, al1.x, al0.y, al1.y, bh[nt].x, bh[nt].y);
                }
            }
        }
    }

    // ------------------ epilogue: (RoPE/scale) + store -------------------
    const float qscale = 0.08838834764831844f;    // 1/sqrt(128)
    float freqv[4];
    if (ROPE) {
#pragma unroll
        for (int nt = 0; nt < 4; ++nt) {
            const int col = bn * 128 + wn * 32 + nt * 8 + tig * 2;
            const int p   = (col & 127) >> 1;     // RoPE pair index 0..63
            freqv[nt] = (float)exp((double)p * -0.14391156831212787); // 10000^(-p/64)
        }
    }
#pragma unroll
    for (int mt = 0; mt < 4; ++mt) {
        const int r0 = bm * 128 + wm * 64 + mt * 16 + g;
        const int r1 = r0 + 8;
        float t0 = 0.f, t1 = 0.f;
        if (ROPE) {
            t0 = (float)(r0 & (SEQ - 1)) * 6.28318530717958647692f;
            t1 = (float)(r1 & (SEQ - 1)) * 6.28318530717958647692f;
        }
#pragma unroll
        for (int nt = 0; nt < 4; ++nt) {
            float* a = acc[mt][nt];
            if (ROPE) {
#pragma unroll
                for (int hrow = 0; hrow < 2; ++hrow) {
                    const float ang = (hrow ? t1 : t0) * freqv[nt];
                    // Cody-Waite reduction (fast-math safe)
                    float kq = rintf(ang * 0.15915494309189535f);
                    float xx = fmaf(kq, -6.28125f, ang);
                    xx       = fmaf(kq, -0.0019353071795864769f, xx);
                    const float sn = sinf(xx), cs = cosf(xx);
                    const float v0 = a[hrow * 2 + 0], v1 = a[hrow * 2 + 1];
                    a[hrow * 2 + 0] = v0 * cs - v1 * sn;
                    a[hrow * 2 + 1] = v0 * sn + v1 * cs;
                }
            }
            if (QSC) {
#pragma unroll
                for (int e = 0; e < 4; ++e) a[e] *= qscale;
            }
            const int col = bn * 128 + wn * 32 + nt * 8 + tig * 2;
            *(float2*)(C + (size_t)r0 * Nd + col) = make_float2(a[0], a[1]);
            *(float2*)(C + (size_t)r1 * Nd + col) = make_float2(a[2], a[3]);
        }
    }
}

// ===========================================================================
// Flash attention, fp32, BM=BN=64, D=128, 256 threads, GQA (kv = h/4).
// (identical to the round-2 passing version)
// ===========================================================================
__global__ __launch_bounds__(256)
void flash_attn(const float* __restrict__ q, const float* __restrict__ k,
                const float* __restrict__ v, float* __restrict__ z,
                const int* __restrict__ is_causal)
{
    extern __shared__ float smf[];
    float* Qt = smf;                   // 128*65
    float* Kt = Qt + 128 * 65;         // 128*65
    float* Vs = Kt + 128 * 65;         // 64*129
    float* Ps = Vs + 64 * 129;         // 64*65

    const int tid = threadIdx.x;
    const int tx  = tid & 15;
    const int ty  = tid >> 4;
    const int qt  = blockIdx.x;
    const int h   = blockIdx.y;
    const int b   = blockIdx.z;
    const int kvh = h >> 2;            // GROUP = 4
    const bool causal = (*is_causal) != 0;

    const float* qb = q + ((size_t)(b * SEQ + qt * 64)) * EMB + h * HDIM;
#pragma unroll
    for (int p = 0; p < 8; p++) {
        int lin = tid + p * 256;
        int r = lin >> 5, c4 = lin & 31;
        float4 t4 = *(const float4*)(qb + (size_t)r * EMB + c4 * 4);
        Qt[(c4 * 4 + 0) * 65 + r] = t4.x;
        Qt[(c4 * 4 + 1) * 65 + r] = t4.y;
        Qt[(c4 * 4 + 2) * 65 + r] = t4.z;
        Qt[(c4 * 4 + 3) * 65 + r] = t4.w;
    }

    float mrow[4], lrow[4], Oa[4][8];
#pragma unroll
    for (int i = 0; i < 4; i++) {
        mrow[i] = -1e30f; lrow[i] = 0.f;
#pragma unroll
        for (int c = 0; c < 8; c++) Oa[i][c] = 0.f;
    }

    const int ktend = causal ? qt : (SEQ / 64 - 1);
    for (int kt = 0; kt <= ktend; ++kt) {
        __syncthreads();
        const float* kb = k + ((size_t)(b * SEQ + kt * 64)) * KVDIM + kvh * HDIM;
        const float* vb = v + ((size_t)(b * SEQ + kt * 64)) * KVDIM + kvh * HDIM;
#pragma unroll
        for (int p = 0; p < 8; p++) {
            int lin = tid + p * 256;
            int r = lin >> 5, c4 = lin & 31;
            float4 k4 = *(const float4*)(kb + (size_t)r * KVDIM + c4 * 4);
            Kt[(c4 * 4 + 0) * 65 + r] = k4.x;
            Kt[(c4 * 4 + 1) * 65 + r] = k4.y;
            Kt[(c4 * 4 + 2) * 65 + r] = k4.z;
            Kt[(c4 * 4 + 3) * 65 + r] = k4.w;
            float4 v4 = *(const float4*)(vb + (size_t)r * KVDIM + c4 * 4);
            Vs[r * 129 + c4 * 4 + 0] = v4.x;
            Vs[r * 129 + c4 * 4 + 1] = v4.y;
            Vs[r * 129 + c4 * 4 + 2] = v4.z;
            Vs[r * 129 + c4 * 4 + 3] = v4.w;
        }
        __syncthreads();

        float sc[4][4];
#pragma unroll
        for (int i = 0; i < 4; i++)
#pragma unroll
            for (int j = 0; j < 4; j++) sc[i][j] = 0.f;
#pragma unroll 8
        for (int kk = 0; kk < 128; ++kk) {
            const float* qrow = &Qt[kk * 65 + ty * 4];
            const float* krow = &Kt[kk * 65 + tx * 4];
            float qa0 = qrow[0], qa1 = qrow[1], qa2 = qrow[2], qa3 = qrow[3];
#pragma unroll
            for (int j = 0; j < 4; j++) {
                float kv = krow[j];
                sc[0][j] = fmaf(qa0, kv, sc[0][j]);
                sc[1][j] = fmaf(qa1, kv, sc[1][j]);
                sc[2][j] = fmaf(qa2, kv, sc[2][j]);
                sc[3][j] = fmaf(qa3, kv, sc[3][j]);
            }
        }

        if (causal && kt == qt) {
#pragma unroll
            for (int i = 0; i < 4; i++)
#pragma unroll
                for (int j = 0; j < 4; j++)
                    if (tx * 4 + j > ty * 4 + i) sc[i][j] = -1e30f;
        }

#pragma unroll
        for (int i = 0; i < 4; i++) {
            float tm = fmaxf(fmaxf(sc[i][0], sc[i][1]), fmaxf(sc[i][2], sc[i][3]));
#pragma unroll
            for (int off = 1; off < 16; off <<= 1)
                tm = fmaxf(tm, __shfl_xor_sync(0xffffffffu, tm, off));
            float mnew  = fmaxf(mrow[i], tm);
            float alpha = __expf(mrow[i] - mnew);
            mrow[i] = mnew;
            float ps = 0.f;
#pragma unroll
            for (int j = 0; j < 4; j++) {
                sc[i][j] = __expf(sc[i][j] - mnew);
                ps += sc[i][j];
            }
#pragma unroll
            for (int off = 1; off < 16; off <<= 1)
                ps += __shfl_xor_sync(0xffffffffu, ps, off);
            lrow[i] = lrow[i] * alpha + ps;
#pragma unroll
            for (int c = 0; c < 8; c++) Oa[i][c] *= alpha;
            Ps[(ty * 4 + i) * 65 + tx * 4 + 0] = sc[i][0];
            Ps[(ty * 4 + i) * 65 + tx * 4 + 1] = sc[i][1];
            Ps[(ty * 4 + i) * 65 + tx * 4 + 2] = sc[i][2];
            Ps[(ty * 4 + i) * 65 + tx * 4 + 3] = sc[i][3];
        }
        __syncthreads();

#pragma unroll 4
        for (int j = 0; j < 64; ++j) {
            float p0 = Ps[(ty * 4 + 0) * 65 + j];
            float p1 = Ps[(ty * 4 + 1) * 65 + j];
            float p2 = Ps[(ty * 4 + 2) * 65 + j];
            float p3 = Ps[(ty * 4 + 3) * 65 + j];
            const float* vr = &Vs[j * 129 + tx * 4];
#pragma unroll
            for (int c = 0; c < 4; c++) {
                float vv = vr[c];
                Oa[0][c] = fmaf(p0, vv, Oa[0][c]);
                Oa[1][c] = fmaf(p1, vv, Oa[1][c]);
                Oa[2][c] = fmaf(p2, vv, Oa[2][c]);
                Oa[3][c] = fmaf(p3, vv, Oa[3][c]);
            }
#pragma unroll
            for (int c = 0; c < 4; c++) {
                float vv = vr[64 + c];
                Oa[0][4 + c] = fmaf(p0, vv, Oa[0][4 + c]);
                Oa[1][4 + c] = fmaf(p1, vv, Oa[1][4 + c]);
                Oa[2][4 + c] = fmaf(p2, vv, Oa[2][4 + c]);
                Oa[3][4 + c] = fmaf(p3, vv, Oa[3][4 + c]);
            }
        }
    }

    float* zb = z + ((size_t)(b * SEQ + qt * 64)) * EMB + h * HDIM;
#pragma unroll
    for (int i = 0; i < 4; i++) {
        float inv = 1.0f / lrow[i];
        int   r   = ty * 4 + i;
        float4 o0 = make_float4(Oa[i][0] * inv, Oa[i][1] * inv,
                                Oa[i][2] * inv, Oa[i][3] * inv);
        float4 o1 = make_float4(Oa[i][4] * inv, Oa[i][5] * inv,
                                Oa[i][6] * inv, Oa[i][7] * inv);
        *(float4*)(zb + (size_t)r * EMB + tx * 4)      = o0;
        *(float4*)(zb + (size_t)r * EMB + 64 + tx * 4) = o1;
    }
}

// ===========================================================================
extern "C" void kernel_launch(void* const* d_in, const int* in_sizes, int n_in,
                              void* d_out, int out_size)
{
    (void)in_sizes; (void)n_in; (void)out_size;
    const float* x   = (const float*)d_in[0];
    const float* Wq  = (const float*)d_in[1];
    const float* Wk  = (const float*)d_in[2];
    const float* Wv  = (const float*)d_in[3];
    const float* Wo  = (const float*)d_in[4];
    const int*   isc = (const int*)d_in[5];

    float *q, *k, *v, *z;
    cudaGetSymbolAddress((void**)&q, g_q);
    cudaGetSymbolAddress((void**)&k, g_k);
    cudaGetSymbolAddress((void**)&v, g_v);
    cudaGetSymbolAddress((void**)&z, g_z);

    cudaFuncSetAttribute(mma_gemm<true,  true >, cudaFuncAttributeMaxDynamicSharedMemorySize, GEMM_SMEM_BYTES);
    cudaFuncSetAttribute(mma_gemm<true,  false>, cudaFuncAttributeMaxDynamicSharedMemorySize, GEMM_SMEM_BYTES);
    cudaFuncSetAttribute(mma_gemm<false, false>, cudaFuncAttributeMaxDynamicSharedMemorySize, GEMM_SMEM_BYTES);

    dim3 blk(256);

    // projections (tf32x3 mma.sync): RoPE fused into Q and K epilogues
    mma_gemm<true,  true ><<<dim3(EMB   / 128, MROWS / 128), blk, GEMM_SMEM_BYTES>>>(x, Wq, q, EMB,   EMB);
    mma_gemm<true,  false><<<dim3(KVDIM / 128, MROWS / 128), blk, GEMM_SMEM_BYTES>>>(x, Wk, k, KVDIM, EMB);
    mma_gemm<false, false><<<dim3(KVDIM / 128, MROWS / 128), blk, GEMM_SMEM_BYTES>>>(x, Wv, v, KVDIM, EMB);

    // attention (fp32 flash, unchanged)
    size_t shm = (size_t)(2 * 128 * 65 + 64 * 129 + 64 * 65) * sizeof(float); // 116224
    cudaFuncSetAttribute(flash_attn, cudaFuncAttributeMaxDynamicSharedMemorySize, (int)shm);
    flash_attn<<<dim3(SEQ / 64, NHEADS, BATCH), blk, shm>>>(q, k, v, z, isc);

    // output projection -> d_out
    mma_gemm<false, false><<<dim3(EMB / 128, MROWS / 128), blk, GEMM_SMEM_BYTES>>>(z, Wo, (float*)d_out, EMB, EMB);
}

// round 6
// speedup vs baseline: 1.1988x; 1.1774x over previous
#include <cuda_runtime.h>
#include <math.h>
#include <stdint.h>

#define EMB    2048
#define SEQ    2048
#define BATCH  2
#define NHEADS 16
#define NKVH   4
#define HDIM   128
#define KVDIM  (NKVH * HDIM)      /* 512  */
#define MROWS  (BATCH * SEQ)      /* 4096 */
#define NKT    64                 /* K / 32 (K = 2048 for every GEMM) */

// -------- scratch (device globals: no allocations allowed) ----------------
__device__ float g_q[(size_t)MROWS * EMB];
__device__ float g_k[(size_t)MROWS * KVDIM];
__device__ float g_v[(size_t)MROWS * KVDIM];
__device__ float g_z[(size_t)MROWS * EMB];

// tf32 hi/lo pre-split operand buffers (fragment-permuted tiled layout)
__device__ uint32_t g_xh[(size_t)MROWS * EMB];
__device__ uint32_t g_xl[(size_t)MROWS * EMB];
__device__ uint32_t g_zh[(size_t)MROWS * EMB];
__device__ uint32_t g_zl[(size_t)MROWS * EMB];
__device__ uint32_t g_wqh[(size_t)EMB * EMB];
__device__ uint32_t g_wql[(size_t)EMB * EMB];
__device__ uint32_t g_wkh[(size_t)KVDIM * EMB];
__device__ uint32_t g_wkl[(size_t)KVDIM * EMB];
__device__ uint32_t g_wvh[(size_t)KVDIM * EMB];
__device__ uint32_t g_wvl[(size_t)KVDIM * EMB];
__device__ uint32_t g_woh[(size_t)EMB * EMB];
__device__ uint32_t g_wol[(size_t)EMB * EMB];

// ===========================================================================
// helpers
// ===========================================================================
__device__ __forceinline__ uint32_t smem_u32(const void* p) {
    uint32_t a;
    asm("{ .reg .u64 t; cvta.to.shared.u64 t, %1; cvt.u32.u64 %0, t; }"
        : "=r"(a) : "l"(p));
    return a;
}

__device__ __forceinline__ void tf32_split(float x, uint32_t& h, uint32_t& l) {
    asm("cvt.rna.tf32.f32 %0, %1;" : "=r"(h) : "f"(x));
    float hf = __uint_as_float(h);
    float lo = x - hf;                 // exact in fp32
    asm("cvt.rna.tf32.f32 %0, %1;" : "=r"(l) : "f"(lo));
}

__device__ __forceinline__ void mma_tf32(float* d,
                                         uint32_t a0, uint32_t a1,
                                         uint32_t a2, uint32_t a3,
                                         uint32_t b0, uint32_t b1) {
    asm volatile(
        "mma.sync.aligned.m16n8k8.row.col.f32.tf32.tf32.f32 "
        "{%0,%1,%2,%3}, {%4,%5,%6,%7}, {%8,%9}, {%0,%1,%2,%3};"
        : "+f"(d[0]), "+f"(d[1]), "+f"(d[2]), "+f"(d[3])
        : "r"(a0), "r"(a1), "r"(a2), "r"(a3), "r"(b0), "r"(b1));
}

__device__ __forceinline__ void cp16(uint32_t smem_dst, const void* gmem_src) {
    asm volatile("cp.async.cg.shared.global [%0], [%1], 16;"
                 :: "r"(smem_dst), "l"(gmem_src));
}
#define CP_COMMIT()  asm volatile("cp.async.commit_group;" ::: "memory")
#define CP_WAIT2()   asm volatile("cp.async.wait_group 2;" ::: "memory")

// ===========================================================================
// split: fp32 row-major [Mrows][2048]  ->  tf32 hi/lo in fragment-permuted,
// bank-swizzled tile layout:  word[(kt*Mrows + row)*32 + ((8*(k&3)+((k&31)>>2)) ^ ((row&7)<<2))]
// ===========================================================================
__global__ void split_tf32(const float* __restrict__ in, uint32_t* __restrict__ hi,
                           uint32_t* __restrict__ lo, int Mrows)
{
    const int n4 = Mrows * (EMB >> 2);
    for (int t = blockIdx.x * blockDim.x + threadIdx.x; t < n4;
         t += gridDim.x * blockDim.x) {
        const int cg  = t & ((EMB >> 2) - 1);     // float4 column
        const int row = t >> 9;                   // EMB/4 = 512
        float4 v = *(const float4*)(in + (size_t)row * EMB + cg * 4);
        const int kt = cg >> 3;
        const int c7 = cg & 7;
        const size_t base = ((size_t)kt * Mrows + row) * 32;
        const int sw = (row & 7) << 2;
        float va[4] = { v.x, v.y, v.z, v.w };
#pragma unroll
        for (int j = 0; j < 4; ++j) {
            uint32_t h, l;
            tf32_split(va[j], h, l);
            const int w = ((j << 3) + c7) ^ sw;
            hi[base + w] = h;
            lo[base + w] = l;
        }
    }
}

// ===========================================================================
// tf32x3 GEMM v2 (mma.sync): C[M,N] = A[M,K] * B[N,K]^T
// Pre-split operands in gmem, cp.async 3-stage pipeline, CTA 128x128, BK=32,
// 256 threads = 8 warps (2m x 4n), warp tile 64x32 (m16n8k8 fragments).
// smem: 3 stages x {Ah,Al,Bh,Bl} x 4096 words = 192 KB.
// Optional fused RoPE (+1/sqrt(128)) epilogue (head width 128 == BN).
// ===========================================================================
#define STG_WORDS 16384                       /* 4 arrays * 4096 */
#define GEMM_SMEM_BYTES (3 * STG_WORDS * 4)   /* 196608 */

__device__ __forceinline__ void issue_stage(
    uint32_t sm_stage_byte,
    const uint32_t* __restrict__ Ah, const uint32_t* __restrict__ Al,
    const uint32_t* __restrict__ Bh, const uint32_t* __restrict__ Bl,
    int kt, int Md, int Nd, int arow0, int brow0, int tid)
{
    const uint32_t* srcs[4] = {
        Ah + ((size_t)kt * Md + arow0) * 32,
        Al + ((size_t)kt * Md + arow0) * 32,
        Bh + ((size_t)kt * Nd + brow0) * 32,
        Bl + ((size_t)kt * Nd + brow0) * 32 };
#pragma unroll
    for (int arr = 0; arr < 4; ++arr) {
        const uint32_t dbase = sm_stage_byte + arr * 16384;
        const char* s = (const char*)srcs[arr];
#pragma unroll
        for (int i = 0; i < 4; ++i) {
            const int id = tid + i * 256;          // 16B chunk id, 0..1023
            cp16(dbase + id * 16, s + (size_t)id * 16);
        }
    }
}

template <bool ROPE, bool QSC>
__global__ __launch_bounds__(256)
void mma_gemm2(const uint32_t* __restrict__ Ah, const uint32_t* __restrict__ Al,
               const uint32_t* __restrict__ Bh, const uint32_t* __restrict__ Bl,
               float* __restrict__ C, int Md, int Nd)
{
    extern __shared__ uint32_t smx[];
    const uint32_t sbyte = smem_u32(smx);

    const int tid  = threadIdx.x;
    const int wid  = tid >> 5;
    const int lane = tid & 31;
    const int g    = lane >> 2;        // 0..7
    const int tig  = lane & 3;         // 0..3
    const int wm   = wid >> 2;         // 0..1
    const int wn   = wid & 3;          // 0..3
    const int bn   = blockIdx.x;
    const int bm   = blockIdx.y;
    const int arow0 = bm * 128;
    const int brow0 = bn * 128;

    float acc[4][4][4];
#pragma unroll
    for (int mt = 0; mt < 4; ++mt)
#pragma unroll
        for (int nt = 0; nt < 4; ++nt)
#pragma unroll
            for (int e = 0; e < 4; ++e) acc[mt][nt][e] = 0.f;

    // prologue: fill 3 stages
#pragma unroll
    for (int s = 0; s < 3; ++s) {
        issue_stage(sbyte + s * STG_WORDS * 4, Ah, Al, Bh, Bl, s,
                    Md, Nd, arow0, brow0, tid);
        CP_COMMIT();
    }

    const int gsw = g << 2;            // bank swizzle for this lane's rows

    for (int kt = 0; kt < NKT; ++kt) {
        const int buf = kt % 3;
        CP_WAIT2();
        __syncthreads();

        const uint32_t* sAh = smx + buf * STG_WORDS;
        const uint32_t* sAl = sAh + 4096;
        const uint32_t* sBh = sAh + 8192;
        const uint32_t* sBl = sAh + 12288;

#pragma unroll
        for (int kh = 0; kh < 2; ++kh) {
            const int wk = (tig * 8 + 4 * kh) ^ gsw;
            uint4 bh4[4], bl4[4];
#pragma unroll
            for (int nt = 0; nt < 4; ++nt) {
                const int rn = wn * 32 + nt * 8 + g;
                bh4[nt] = *(const uint4*)(sBh + rn * 32 + wk);
                bl4[nt] = *(const uint4*)(sBl + rn * 32 + wk);
            }
#pragma unroll
            for (int mt = 0; mt < 4; ++mt) {
                const int r = wm * 64 + mt * 16 + g;
                const uint4 ah0 = *(const uint4*)(sAh + r * 32 + wk);
                const uint4 ah1 = *(const uint4*)(sAh + (r + 8) * 32 + wk);
                const uint4 al0 = *(const uint4*)(sAl + r * 32 + wk);
                const uint4 al1 = *(const uint4*)(sAl + (r + 8) * 32 + wk);
#pragma unroll
                for (int nt = 0; nt < 4; ++nt) {
                    // ks even (k base 16*kh)
                    mma_tf32(acc[mt][nt], ah0.x, ah1.x, ah0.y, ah1.y, bh4[nt].x, bh4[nt].y);
                    mma_tf32(acc[mt][nt], ah0.x, ah1.x, ah0.y, ah1.y, bl4[nt].x, bl4[nt].y);
                    mma_tf32(acc[mt][nt], al0.x, al1.x, al0.y, al1.y, bh4[nt].x, bh4[nt].y);
                    // ks odd (k base 16*kh + 8)
                    mma_tf32(acc[mt][nt], ah0.z, ah1.z, ah0.w, ah1.w, bh4[nt].z, bh4[nt].w);
                    mma_tf32(acc[mt][nt], ah0.z, ah1.z, ah0.w, ah1.w, bl4[nt].z, bl4[nt].w);
                    mma_tf32(acc[mt][nt], al0.z, al1.z, al0.w, al1.w, bh4[nt].z, bh4[nt].w);
                }
            }
        }

        __syncthreads();
        if (kt + 3 < NKT)
            issue_stage(sbyte + buf * STG_WORDS * 4, Ah, Al, Bh, Bl, kt + 3,
                        Md, Nd, arow0, brow0, tid);
        CP_COMMIT();
    }

    // ------------------ epilogue: (RoPE/scale) + store -------------------
    const float qscale = 0.08838834764831844f;    // 1/sqrt(128)
    float freqv[4];
    if (ROPE) {
#pragma unroll
        for (int nt = 0; nt < 4; ++nt) {
            const int col = bn * 128 + wn * 32 + nt * 8 + tig * 2;
            const int p   = (col & 127) >> 1;     // RoPE pair index 0..63
            freqv[nt] = (float)exp((double)p * -0.14391156831212787);
        }
    }
#pragma unroll
    for (int mt = 0; mt < 4; ++mt) {
        const int r0 = bm * 128 + wm * 64 + mt * 16 + g;
        const int r1 = r0 + 8;
        float t0 = 0.f, t1 = 0.f;
        if (ROPE) {
            t0 = (float)(r0 & (SEQ - 1)) * 6.28318530717958647692f;
            t1 = (float)(r1 & (SEQ - 1)) * 6.28318530717958647692f;
        }
#pragma unroll
        for (int nt = 0; nt < 4; ++nt) {
            float* a = acc[mt][nt];
            if (ROPE) {
#pragma unroll
                for (int hrow = 0; hrow < 2; ++hrow) {
                    const float ang = (hrow ? t1 : t0) * freqv[nt];
                    float kq = rintf(ang * 0.15915494309189535f);
                    float xx = fmaf(kq, -6.28125f, ang);
                    xx       = fmaf(kq, -0.0019353071795864769f, xx);
                    const float sn = sinf(xx), cs = cosf(xx);
                    const float v0 = a[hrow * 2 + 0], v1 = a[hrow * 2 + 1];
                    a[hrow * 2 + 0] = v0 * cs - v1 * sn;
                    a[hrow * 2 + 1] = v0 * sn + v1 * cs;
                }
            }
            if (QSC) {
#pragma unroll
                for (int e = 0; e < 4; ++e) a[e] *= qscale;
            }
            const int col = bn * 128 + wn * 32 + nt * 8 + tig * 2;
            *(float2*)(C + (size_t)r0 * Nd + col) = make_float2(a[0], a[1]);
            *(float2*)(C + (size_t)r1 * Nd + col) = make_float2(a[2], a[3]);
        }
    }
}

// ===========================================================================
// Flash attention v2, fp32, BM=64, BN=128, D=128, 256 threads (8x4 per
// thread), GQA (kv = h/4). q pre-scaled + RoPE'd; k RoPE'd.
// smem words: Qt[128][68] + Kt[128][132] + Vs[128][132] + Ps[64][132]
// ===========================================================================
#define QT_STR 68
#define KT_STR 132
#define VS_STR 132
#define PS_STR 132
#define QT_OFF 0
#define KT_OFF 8704
#define VS_OFF 25600
#define PS_OFF 42496
#define FA_SMEM_BYTES (50944 * 4)    /* 203776 */

__global__ __launch_bounds__(256)
void flash_attn2(const float* __restrict__ q, const float* __restrict__ k,
                 const float* __restrict__ v, float* __restrict__ z,
                 const int* __restrict__ is_causal)
{
    extern __shared__ float smf[];
    float* Qt = smf + QT_OFF;
    float* Kt = smf + KT_OFF;
    float* Vs = smf + VS_OFF;
    float* Ps = smf + PS_OFF;

    const int tid = threadIdx.x;
    const int tx  = tid & 31;          // 32 n-col groups of 4 / d-col groups of 4
    const int ty  = tid >> 5;          // 8 row groups of 8
    const int qt  = blockIdx.x;
    const int h   = blockIdx.y;
    const int b   = blockIdx.z;
    const int kvh = h >> 2;
    const bool causal = (*is_causal) != 0;

    // ---- Q tile (64 x 128), transposed into Qt[d][m] ----
    const float* qb = q + ((size_t)(b * SEQ + qt * 64)) * EMB + h * HDIM;
#pragma unroll
    for (int p = 0; p < 8; ++p) {
        const int idx = tid + p * 256;
        const int m = idx & 63, c = idx >> 6;
        float4 t4 = *(const float4*)(qb + (size_t)m * EMB + c * 4);
        Qt[(c * 4 + 0) * QT_STR + m] = t4.x;
        Qt[(c * 4 + 1) * QT_STR + m] = t4.y;
        Qt[(c * 4 + 2) * QT_STR + m] = t4.z;
        Qt[(c * 4 + 3) * QT_STR + m] = t4.w;
    }

    float mrow[8], lrow[8], Oa[8][4];
#pragma unroll
    for (int i = 0; i < 8; ++i) {
        mrow[i] = -1e30f; lrow[i] = 0.f;
#pragma unroll
        for (int c = 0; c < 4; ++c) Oa[i][c] = 0.f;
    }

    const int kend = causal ? (qt >> 1) : (SEQ / 128 - 1);
    for (int kn = 0; kn <= kend; ++kn) {
        __syncthreads();     // previous iteration's Kt/Vs reads complete
        const float* kb = ((const float*)k) + ((size_t)(b * SEQ + kn * 128)) * KVDIM + kvh * HDIM;
        const float* vb = ((const float*)v) + ((size_t)(b * SEQ + kn * 128)) * KVDIM + kvh * HDIM;
        // K transposed into Kt[d][n] (conflict-free stores)
#pragma unroll
        for (int p = 0; p < 16; ++p) {
            const int idx = tid + p * 256;
            const int n = idx & 127, c = idx >> 7;
            float4 k4 = *(const float4*)(kb + (size_t)n * KVDIM + c * 4);
            Kt[(c * 4 + 0) * KT_STR + n] = k4.x;
            Kt[(c * 4 + 1) * KT_STR + n] = k4.y;
            Kt[(c * 4 + 2) * KT_STR + n] = k4.z;
            Kt[(c * 4 + 3) * KT_STR + n] = k4.w;
        }
        // V straight copy into Vs[n][d]
#pragma unroll
        for (int p = 0; p < 16; ++p) {
            const int idx = tid + p * 256;
            const int n = idx >> 5, c = idx & 31;
            float4 v4 = *(const float4*)(vb + (size_t)n * KVDIM + c * 4);
            *(float4*)(Vs + n * VS_STR + c * 4) = v4;
        }
        __syncthreads();

        // ---- scores S = Q K^T : 8x4 per thread ----
        float sc[8][4];
#pragma unroll
        for (int i = 0; i < 8; ++i)
#pragma unroll
            for (int j = 0; j < 4; ++j) sc[i][j] = 0.f;

#pragma unroll 2
        for (int kk = 0; kk < 128; ++kk) {
            float a[8], bf[4];
            *(float4*)(a)     = *(const float4*)(Qt + kk * QT_STR + ty * 8);
            *(float4*)(a + 4) = *(const float4*)(Qt + kk * QT_STR + ty * 8 + 4);
            *(float4*)(bf)    = *(const float4*)(Kt + kk * KT_STR + tx * 4);
#pragma unroll
            for (int i = 0; i < 8; ++i)
#pragma unroll
                for (int j = 0; j < 4; ++j)
                    sc[i][j] = fmaf(a[i], bf[j], sc[i][j]);
        }

        if (causal && kn == kend) {
            const int rbase = qt * 64 + ty * 8;
            const int cbase = kn * 128 + tx * 4;
#pragma unroll
            for (int i = 0; i < 8; ++i)
#pragma unroll
                for (int j = 0; j < 4; ++j)
                    if (cbase + j > rbase + i) sc[i][j] = -1e30f;
        }

        // ---- online softmax (row reductions across the full warp) ----
#pragma unroll
        for (int i = 0; i < 8; ++i) {
            float tm = fmaxf(fmaxf(sc[i][0], sc[i][1]), fmaxf(sc[i][2], sc[i][3]));
#pragma unroll
            for (int off = 16; off > 0; off >>= 1)
                tm = fmaxf(tm, __shfl_xor_sync(0xffffffffu, tm, off));
            const float mnew  = fmaxf(mrow[i], tm);
            const float alpha = __expf(mrow[i] - mnew);
            mrow[i] = mnew;
            float ps = 0.f;
#pragma unroll
            for (int j = 0; j < 4; ++j) {
                sc[i][j] = __expf(sc[i][j] - mnew);
                ps += sc[i][j];
            }
#pragma unroll
            for (int off = 16; off > 0; off >>= 1)
                ps += __shfl_xor_sync(0xffffffffu, ps, off);
            lrow[i] = lrow[i] * alpha + ps;
#pragma unroll
            for (int c = 0; c < 4; ++c) Oa[i][c] *= alpha;
            *(float4*)(Ps + (ty * 8 + i) * PS_STR + tx * 4) =
                make_float4(sc[i][0], sc[i][1], sc[i][2], sc[i][3]);
        }
        __syncwarp();   // Ps rows are warp-private (same ty) — warp sync suffices

        // ---- O += P V : 8x4 per thread ----
#pragma unroll 2
        for (int j = 0; j < 128; ++j) {
            float vv[4];
            *(float4*)vv = *(const float4*)(Vs + j * VS_STR + tx * 4);
#pragma unroll
            for (int i = 0; i < 8; ++i) {
                const float pij = Ps[(ty * 8 + i) * PS_STR + j];
#pragma unroll
                for (int c = 0; c < 4; ++c)
                    Oa[i][c] = fmaf(pij, vv[c], Oa[i][c]);
            }
        }
    }

    // ---- finalize ----
    float* zb = z + ((size_t)(b * SEQ + qt * 64)) * EMB + h * HDIM;
#pragma unroll
    for (int i = 0; i < 8; ++i) {
        const float inv = 1.0f / lrow[i];
        *(float4*)(zb + (size_t)(ty * 8 + i) * EMB + tx * 4) =
            make_float4(Oa[i][0] * inv, Oa[i][1] * inv,
                        Oa[i][2] * inv, Oa[i][3] * inv);
    }
}

// ===========================================================================
extern "C" void kernel_launch(void* const* d_in, const int* in_sizes, int n_in,
                              void* d_out, int out_size)
{
    (void)in_sizes; (void)n_in; (void)out_size;
    const float* x   = (const float*)d_in[0];
    const float* Wq  = (const float*)d_in[1];
    const float* Wk  = (const float*)d_in[2];
    const float* Wv  = (const float*)d_in[3];
    const float* Wo  = (const float*)d_in[4];
    const int*   isc = (const int*)d_in[5];

    float *q, *k, *v, *z;
    cudaGetSymbolAddress((void**)&q, g_q);
    cudaGetSymbolAddress((void**)&k, g_k);
    cudaGetSymbolAddress((void**)&v, g_v);
    cudaGetSymbolAddress((void**)&z, g_z);

    uint32_t *xh, *xl, *zh, *zl, *wqh, *wql, *wkh, *wkl, *wvh, *wvl, *woh, *wol;
    cudaGetSymbolAddress((void**)&xh,  g_xh);
    cudaGetSymbolAddress((void**)&xl,  g_xl);
    cudaGetSymbolAddress((void**)&zh,  g_zh);
    cudaGetSymbolAddress((void**)&zl,  g_zl);
    cudaGetSymbolAddress((void**)&wqh, g_wqh);
    cudaGetSymbolAddress((void**)&wql, g_wql);
    cudaGetSymbolAddress((void**)&wkh, g_wkh);
    cudaGetSymbolAddress((void**)&wkl, g_wkl);
    cudaGetSymbolAddress((void**)&wvh, g_wvh);
    cudaGetSymbolAddress((void**)&wvl, g_wvl);
    cudaGetSymbolAddress((void**)&woh, g_woh);
    cudaGetSymbolAddress((void**)&wol, g_wol);

    cudaFuncSetAttribute(mma_gemm2<true,  true >, cudaFuncAttributeMaxDynamicSharedMemorySize, GEMM_SMEM_BYTES);
    cudaFuncSetAttribute(mma_gemm2<true,  false>, cudaFuncAttributeMaxDynamicSharedMemorySize, GEMM_SMEM_BYTES);
    cudaFuncSetAttribute(mma_gemm2<false, false>, cudaFuncAttributeMaxDynamicSharedMemorySize, GEMM_SMEM_BYTES);
    cudaFuncSetAttribute(flash_attn2, cudaFuncAttributeMaxDynamicSharedMemorySize, FA_SMEM_BYTES);

    dim3 blk(256);

    // ---- pre-split operands into tf32 hi/lo tiled layout ----
    split_tf32<<<2048, 256>>>(x,  xh,  xl,  MROWS);
    split_tf32<<<1024, 256>>>(Wq, wqh, wql, EMB);
    split_tf32<<<512,  256>>>(Wk, wkh, wkl, KVDIM);
    split_tf32<<<512,  256>>>(Wv, wvh, wvl, KVDIM);
    split_tf32<<<1024, 256>>>(Wo, woh, wol, EMB);

    // ---- projections (RoPE fused into Q and K epilogues) ----
    mma_gemm2<true,  true ><<<dim3(EMB   / 128, MROWS / 128), blk, GEMM_SMEM_BYTES>>>(xh, xl, wqh, wql, q, MROWS, EMB);
    mma_gemm2<true,  false><<<dim3(KVDIM / 128, MROWS / 128), blk, GEMM_SMEM_BYTES>>>(xh, xl, wkh, wkl, k, MROWS, KVDIM);
    mma_gemm2<false, false><<<dim3(KVDIM / 128, MROWS / 128), blk, GEMM_SMEM_BYTES>>>(xh, xl, wvh, wvl, v, MROWS, KVDIM);

    // ---- attention ----
    flash_attn2<<<dim3(SEQ / 64, NHEADS, BATCH), blk, FA_SMEM_BYTES>>>(q, k, v, z, isc);

    // ---- output projection ----
    split_tf32<<<2048, 256>>>(z, zh, zl, MROWS);
    mma_gemm2<false, false><<<dim3(EMB / 128, MROWS / 128), blk, GEMM_SMEM_BYTES>>>(zh, zl, woh, wol, (float*)d_out, MROWS, EMB);
}

// round 7
// speedup vs baseline: 1.5205x; 1.2683x over previous
#include <cuda_runtime.h>
#include <math.h>
#include <stdint.h>

#define EMB    2048
#define SEQ    2048
#define BATCH  2
#define NHEADS 16
#define NKVH   4
#define HDIM   128
#define KVDIM  (NKVH * HDIM)      /* 512  */
#define MROWS  (BATCH * SEQ)      /* 4096 */
#define NKT    64                 /* K / 32 (K = 2048 for every GEMM) */

// -------- scratch (device globals: no allocations allowed) ----------------
__device__ float g_q[(size_t)MROWS * EMB];
__device__ float g_k[(size_t)MROWS * KVDIM];
__device__ float g_v[(size_t)MROWS * KVDIM];
__device__ float g_z[(size_t)MROWS * EMB];

// tf32 pre-split operand buffers (fragment-permuted tiled layout)
__device__ uint32_t g_xh[(size_t)MROWS * EMB];          // A operands: hi only
__device__ uint32_t g_zh[(size_t)MROWS * EMB];
__device__ uint32_t g_wqh[(size_t)EMB * EMB];           // B operands: hi+lo
__device__ uint32_t g_wql[(size_t)EMB * EMB];
__device__ uint32_t g_wkh[(size_t)KVDIM * EMB];
__device__ uint32_t g_wkl[(size_t)KVDIM * EMB];
__device__ uint32_t g_wvh[(size_t)KVDIM * EMB];
__device__ uint32_t g_wvl[(size_t)KVDIM * EMB];
__device__ uint32_t g_woh[(size_t)EMB * EMB];
__device__ uint32_t g_wol[(size_t)EMB * EMB];

// ===========================================================================
// helpers
// ===========================================================================
__device__ __forceinline__ uint32_t smem_u32(const void* p) {
    uint32_t a;
    asm("{ .reg .u64 t; cvta.to.shared.u64 t, %1; cvt.u32.u64 %0, t; }"
        : "=r"(a) : "l"(p));
    return a;
}

__device__ __forceinline__ void tf32_split(float x, uint32_t& h, uint32_t& l) {
    asm("cvt.rna.tf32.f32 %0, %1;" : "=r"(h) : "f"(x));
    float hf = __uint_as_float(h);
    float lo = x - hf;                 // exact in fp32
    asm("cvt.rna.tf32.f32 %0, %1;" : "=r"(l) : "f"(lo));
}
__device__ __forceinline__ uint32_t tf32_hi(float x) {
    uint32_t h;
    asm("cvt.rna.tf32.f32 %0, %1;" : "=r"(h) : "f"(x));
    return h;
}

__device__ __forceinline__ void mma_tf32(float* d,
                                         uint32_t a0, uint32_t a1,
                                         uint32_t a2, uint32_t a3,
                                         uint32_t b0, uint32_t b1) {
    asm volatile(
        "mma.sync.aligned.m16n8k8.row.col.f32.tf32.tf32.f32 "
        "{%0,%1,%2,%3}, {%4,%5,%6,%7}, {%8,%9}, {%0,%1,%2,%3};"
        : "+f"(d[0]), "+f"(d[1]), "+f"(d[2]), "+f"(d[3])
        : "r"(a0), "r"(a1), "r"(a2), "r"(a3), "r"(b0), "r"(b1));
}

__device__ __forceinline__ void cp16(uint32_t smem_dst, const void* gmem_src) {
    asm volatile("cp.async.cg.shared.global [%0], [%1], 16;"
                 :: "r"(smem_dst), "l"(gmem_src));
}
#define CP_COMMIT()  asm volatile("cp.async.commit_group;" ::: "memory")
#define CP_WAIT2()   asm volatile("cp.async.wait_group 2;" ::: "memory")

// ===========================================================================
// splits: fp32 row-major [Mrows][2048] -> tf32 fragment-permuted tile layout
//   word[(kt*Mrows + row)*32 + ((8*(k&3) + (k>>2)&7... ) ^ ((row&7)<<2))]
// (identical layout to the round-6 passing kernel)
// ===========================================================================
__global__ void split_hilo(const float* __restrict__ in, uint32_t* __restrict__ hi,
                           uint32_t* __restrict__ lo, int Mrows)
{
    const int n4 = Mrows * (EMB >> 2);
    for (int t = blockIdx.x * blockDim.x + threadIdx.x; t < n4;
         t += gridDim.x * blockDim.x) {
        const int cg  = t & ((EMB >> 2) - 1);
        const int row = t >> 9;
        float4 v = *(const float4*)(in + (size_t)row * EMB + cg * 4);
        const int kt = cg >> 3;
        const int c7 = cg & 7;
        const size_t base = ((size_t)kt * Mrows + row) * 32;
        const int sw = (row & 7) << 2;
        float va[4] = { v.x, v.y, v.z, v.w };
#pragma unroll
        for (int j = 0; j < 4; ++j) {
            uint32_t h, l;
            tf32_split(va[j], h, l);
            const int w = ((j << 3) + c7) ^ sw;
            hi[base + w] = h;
            lo[base + w] = l;
        }
    }
}

__global__ void split_hi(const float* __restrict__ in, uint32_t* __restrict__ hi,
                         int Mrows)
{
    const int n4 = Mrows * (EMB >> 2);
    for (int t = blockIdx.x * blockDim.x + threadIdx.x; t < n4;
         t += gridDim.x * blockDim.x) {
        const int cg  = t & ((EMB >> 2) - 1);
        const int row = t >> 9;
        float4 v = *(const float4*)(in + (size_t)row * EMB + cg * 4);
        const int kt = cg >> 3;
        const int c7 = cg & 7;
        const size_t base = ((size_t)kt * Mrows + row) * 32;
        const int sw = (row & 7) << 2;
        float va[4] = { v.x, v.y, v.z, v.w };
#pragma unroll
        for (int j = 0; j < 4; ++j)
            hi[base + (((j << 3) + c7) ^ sw)] = tf32_hi(va[j]);
    }
}

// ===========================================================================
// tf32x2 GEMM core (mma.sync): C[M,N] = A[M,K] * B[N,K]^T
// A truncated to tf32-hi; B = Bh + Bl (full precision).
// CTA 128x128, BK=32, 256 threads = 8 warps (2m x 4n), 4-stage cp.async.
// smem: 4 stages x {Ah,Bh,Bl} x 4096 words = 192 KB.
// ===========================================================================
#define STG_WORDS 12288                       /* 3 arrays * 4096 */
#define GEMM_SMEM_BYTES (4 * STG_WORDS * 4)   /* 196608 */

__device__ __forceinline__ void issue_stage(
    uint32_t sm_stage_byte,
    const uint32_t* __restrict__ Ah, const uint32_t* __restrict__ Bh,
    const uint32_t* __restrict__ Bl,
    int kt, int Md, int Nd, int arow0, int brow0, int tid)
{
    const uint32_t* srcs[3] = {
        Ah + ((size_t)kt * Md + arow0) * 32,
        Bh + ((size_t)kt * Nd + brow0) * 32,
        Bl + ((size_t)kt * Nd + brow0) * 32 };
#pragma unroll
    for (int arr = 0; arr < 3; ++arr) {
        const uint32_t dbase = sm_stage_byte + arr * 16384;
        const char* s = (const char*)srcs[arr];
#pragma unroll
        for (int i = 0; i < 4; ++i) {
            const int id = tid + i * 256;          // 16B chunk id, 0..1023
            cp16(dbase + id * 16, s + (size_t)id * 16);
        }
    }
}

__device__ __forceinline__ void gemm_core(
    const uint32_t* __restrict__ Ah, const uint32_t* __restrict__ Bh,
    const uint32_t* __restrict__ Bl, float* __restrict__ C,
    int Md, int Nd, int bm, int bn, bool rope, bool qsc, uint32_t* smx)
{
    const uint32_t sbyte = smem_u32(smx);
    const int tid  = threadIdx.x;
    const int wid  = tid >> 5;
    const int lane = tid & 31;
    const int g    = lane >> 2;
    const int tig  = lane & 3;
    const int wm   = wid >> 2;
    const int wn   = wid & 3;
    const int arow0 = bm * 128;
    const int brow0 = bn * 128;

    float acc[4][4][4];
#pragma unroll
    for (int mt = 0; mt < 4; ++mt)
#pragma unroll
        for (int nt = 0; nt < 4; ++nt)
#pragma unroll
            for (int e = 0; e < 4; ++e) acc[mt][nt][e] = 0.f;

#pragma unroll
    for (int s = 0; s < 3; ++s) {
        issue_stage(sbyte + s * STG_WORDS * 4, Ah, Bh, Bl, s,
                    Md, Nd, arow0, brow0, tid);
        CP_COMMIT();
    }

    const int gsw = g << 2;

    for (int kt = 0; kt < NKT; ++kt) {
        const int buf = kt & 3;
        CP_WAIT2();
        __syncthreads();

        const uint32_t* sAh = smx + buf * STG_WORDS;
        const uint32_t* sBh = sAh + 4096;
        const uint32_t* sBl = sAh + 8192;

#pragma unroll
        for (int kh = 0; kh < 2; ++kh) {
            const int wk = (tig * 8 + 4 * kh) ^ gsw;
            uint4 bh4[4], bl4[4];
#pragma unroll
            for (int nt = 0; nt < 4; ++nt) {
                const int rn = wn * 32 + nt * 8 + g;
                bh4[nt] = *(const uint4*)(sBh + rn * 32 + wk);
                bl4[nt] = *(const uint4*)(sBl + rn * 32 + wk);
            }
#pragma unroll
            for (int mt = 0; mt < 4; ++mt) {
                const int r = wm * 64 + mt * 16 + g;
                const uint4 ah0 = *(const uint4*)(sAh + r * 32 + wk);
                const uint4 ah1 = *(const uint4*)(sAh + (r + 8) * 32 + wk);
#pragma unroll
                for (int nt = 0; nt < 4; ++nt) {
                    mma_tf32(acc[mt][nt], ah0.x, ah1.x, ah0.y, ah1.y, bh4[nt].x, bh4[nt].y);
                    mma_tf32(acc[mt][nt], ah0.x, ah1.x, ah0.y, ah1.y, bl4[nt].x, bl4[nt].y);
                    mma_tf32(acc[mt][nt], ah0.z, ah1.z, ah0.w, ah1.w, bh4[nt].z, bh4[nt].w);
                    mma_tf32(acc[mt][nt], ah0.z, ah1.z, ah0.w, ah1.w, bl4[nt].z, bl4[nt].w);
                }
            }
        }

        __syncthreads();
        if (kt + 3 < NKT)
            issue_stage(sbyte + ((kt + 3) & 3) * STG_WORDS * 4, Ah, Bh, Bl,
                        kt + 3, Md, Nd, arow0, brow0, tid);
        CP_COMMIT();
    }

    // ------------------ epilogue: (RoPE/scale) + store -------------------
    const float qscale = 0.08838834764831844f;    // 1/sqrt(128)
    float freqv[4];
    if (rope) {
#pragma unroll
        for (int nt = 0; nt < 4; ++nt) {
            const int col = bn * 128 + wn * 32 + nt * 8 + tig * 2;
            const int p   = (col & 127) >> 1;
            freqv[nt] = (float)exp((double)p * -0.14391156831212787);
        }
    }
#pragma unroll
    for (int mt = 0; mt < 4; ++mt) {
        const int r0 = bm * 128 + wm * 64 + mt * 16 + g;
        const int r1 = r0 + 8;
        float t0 = 0.f, t1 = 0.f;
        if (rope) {
            t0 = (float)(r0 & (SEQ - 1)) * 6.28318530717958647692f;
            t1 = (float)(r1 & (SEQ - 1)) * 6.28318530717958647692f;
        }
#pragma unroll
        for (int nt = 0; nt < 4; ++nt) {
            float* a = acc[mt][nt];
            if (rope) {
#pragma unroll
                for (int hrow = 0; hrow < 2; ++hrow) {
                    const float ang = (hrow ? t1 : t0) * freqv[nt];
                    float kq = rintf(ang * 0.15915494309189535f);
                    float xx = fmaf(kq, -6.28125f, ang);
                    xx       = fmaf(kq, -0.0019353071795864769f, xx);
                    const float sn = sinf(xx), cs = cosf(xx);
                    const float v0 = a[hrow * 2 + 0], v1 = a[hrow * 2 + 1];
                    a[hrow * 2 + 0] = v0 * cs - v1 * sn;
                    a[hrow * 2 + 1] = v0 * sn + v1 * cs;
                }
            }
            if (qsc) {
#pragma unroll
                for (int e = 0; e < 4; ++e) a[e] *= qscale;
            }
            const int col = bn * 128 + wn * 32 + nt * 8 + tig * 2;
            *(float2*)(C + (size_t)r0 * Nd + col) = make_float2(a[0], a[1]);
            *(float2*)(C + (size_t)r1 * Nd + col) = make_float2(a[2], a[3]);
        }
    }
}

// fused Q/K/V projection: 768 CTAs (Q:512, K:128, V:128), one wave-packed launch
__global__ __launch_bounds__(256)
void qkv_gemm(const uint32_t* __restrict__ xh,
              const uint32_t* __restrict__ wqh, const uint32_t* __restrict__ wql,
              const uint32_t* __restrict__ wkh, const uint32_t* __restrict__ wkl,
              const uint32_t* __restrict__ wvh, const uint32_t* __restrict__ wvl,
              float* __restrict__ q, float* __restrict__ k, float* __restrict__ v)
{
    extern __shared__ uint32_t smx[];
    const int id = blockIdx.x;
    const uint32_t *Bh, *Bl;
    float* C;
    int bm, bn, Nd;
    bool rope, qsc;
    if (id < 512)      { bm = id >> 4;  bn = id & 15; Bh = wqh; Bl = wql; C = q; Nd = EMB;   rope = true;  qsc = true;  }
    else if (id < 640) { int t = id - 512; bm = t >> 2; bn = t & 3; Bh = wkh; Bl = wkl; C = k; Nd = KVDIM; rope = true;  qsc = false; }
    else               { int t = id - 640; bm = t >> 2; bn = t & 3; Bh = wvh; Bl = wvl; C = v; Nd = KVDIM; rope = false; qsc = false; }
    gemm_core(xh, Bh, Bl, C, MROWS, Nd, bm, bn, rope, qsc, smx);
}

__global__ __launch_bounds__(256)
void o_gemm(const uint32_t* __restrict__ zh,
            const uint32_t* __restrict__ woh, const uint32_t* __restrict__ wol,
            float* __restrict__ out)
{
    extern __shared__ uint32_t smx[];
    gemm_core(zh, woh, wol, out, MROWS, EMB, blockIdx.y, blockIdx.x,
              false, false, smx);
}

// ===========================================================================
// Flash attention v2.1, fp32, BM=64, BN=128, D=128, 256 threads (8x4/thread),
// GQA (kv = h/4). PV loop float4-blocked (12 LDS.128 + 128 FMA per j4 step).
// ===========================================================================
#define QT_STR 68
#define KT_STR 132
#define VS_STR 132
#define PS_STR 132
#define QT_OFF 0
#define KT_OFF 8704
#define VS_OFF 25600
#define PS_OFF 42496
#define FA_SMEM_BYTES (50944 * 4)    /* 203776 */

__global__ __launch_bounds__(256)
void flash_attn2(const float* __restrict__ q, const float* __restrict__ k,
                 const float* __restrict__ v, float* __restrict__ z,
                 const int* __restrict__ is_causal)
{
    extern __shared__ float smf[];
    float* Qt = smf + QT_OFF;
    float* Kt = smf + KT_OFF;
    float* Vs = smf + VS_OFF;
    float* Ps = smf + PS_OFF;

    const int tid = threadIdx.x;
    const int tx  = tid & 31;
    const int ty  = tid >> 5;
    const int qt  = blockIdx.x;
    const int h   = blockIdx.y;
    const int b   = blockIdx.z;
    const int kvh = h >> 2;
    const bool causal = (*is_causal) != 0;

    const float* qb = q + ((size_t)(b * SEQ + qt * 64)) * EMB + h * HDIM;
#pragma unroll
    for (int p = 0; p < 8; ++p) {
        const int idx = tid + p * 256;
        const int m = idx & 63, c = idx >> 6;
        float4 t4 = *(const float4*)(qb + (size_t)m * EMB + c * 4);
        Qt[(c * 4 + 0) * QT_STR + m] = t4.x;
        Qt[(c * 4 + 1) * QT_STR + m] = t4.y;
        Qt[(c * 4 + 2) * QT_STR + m] = t4.z;
        Qt[(c * 4 + 3) * QT_STR + m] = t4.w;
    }

    float mrow[8], lrow[8], Oa[8][4];
#pragma unroll
    for (int i = 0; i < 8; ++i) {
        mrow[i] = -1e30f; lrow[i] = 0.f;
#pragma unroll
        for (int c = 0; c < 4; ++c) Oa[i][c] = 0.f;
    }

    const int kend = causal ? (qt >> 1) : (SEQ / 128 - 1);
    for (int kn = 0; kn <= kend; ++kn) {
        __syncthreads();
        const float* kb = k + ((size_t)(b * SEQ + kn * 128)) * KVDIM + kvh * HDIM;
        const float* vb = v + ((size_t)(b * SEQ + kn * 128)) * KVDIM + kvh * HDIM;
#pragma unroll
        for (int p = 0; p < 16; ++p) {
            const int idx = tid + p * 256;
            const int n = idx & 127, c = idx >> 7;
            float4 k4 = *(const float4*)(kb + (size_t)n * KVDIM + c * 4);
            Kt[(c * 4 + 0) * KT_STR + n] = k4.x;
            Kt[(c * 4 + 1) * KT_STR + n] = k4.y;
            Kt[(c * 4 + 2) * KT_STR + n] = k4.z;
            Kt[(c * 4 + 3) * KT_STR + n] = k4.w;
        }
#pragma unroll
        for (int p = 0; p < 16; ++p) {
            const int idx = tid + p * 256;
            const int n = idx >> 5, c = idx & 31;
            float4 v4 = *(const float4*)(vb + (size_t)n * KVDIM + c * 4);
            *(float4*)(Vs + n * VS_STR + c * 4) = v4;
        }
        __syncthreads();

        // ---- scores S = Q K^T : 8x4 per thread ----
        float sc[8][4];
#pragma unroll
        for (int i = 0; i < 8; ++i)
#pragma unroll
            for (int j = 0; j < 4; ++j) sc[i][j] = 0.f;

#pragma unroll 2
        for (int kk = 0; kk < 128; ++kk) {
            float a[8], bf[4];
            *(float4*)(a)     = *(const float4*)(Qt + kk * QT_STR + ty * 8);
            *(float4*)(a + 4) = *(const float4*)(Qt + kk * QT_STR + ty * 8 + 4);
            *(float4*)(bf)    = *(const float4*)(Kt + kk * KT_STR + tx * 4);
#pragma unroll
            for (int i = 0; i < 8; ++i)
#pragma unroll
                for (int j = 0; j < 4; ++j)
                    sc[i][j] = fmaf(a[i], bf[j], sc[i][j]);
        }

        if (causal && kn == kend) {
            const int rbase = qt * 64 + ty * 8;
            const int cbase = kn * 128 + tx * 4;
#pragma unroll
            for (int i = 0; i < 8; ++i)
#pragma unroll
                for (int j = 0; j < 4; ++j)
                    if (cbase + j > rbase + i) sc[i][j] = -1e30f;
        }

        // ---- online softmax ----
#pragma unroll
        for (int i = 0; i < 8; ++i) {
            float tm = fmaxf(fmaxf(sc[i][0], sc[i][1]), fmaxf(sc[i][2], sc[i][3]));
#pragma unroll
            for (int off = 16; off > 0; off >>= 1)
                tm = fmaxf(tm, __shfl_xor_sync(0xffffffffu, tm, off));
            const float mnew  = fmaxf(mrow[i], tm);
            const float alpha = __expf(mrow[i] - mnew);
            mrow[i] = mnew;
            float ps = 0.f;
#pragma unroll
            for (int j = 0; j < 4; ++j) {
                sc[i][j] = __expf(sc[i][j] - mnew);
                ps += sc[i][j];
            }
#pragma unroll
            for (int off = 16; off > 0; off >>= 1)
                ps += __shfl_xor_sync(0xffffffffu, ps, off);
            lrow[i] = lrow[i] * alpha + ps;
#pragma unroll
            for (int c = 0; c < 4; ++c) Oa[i][c] *= alpha;
            *(float4*)(Ps + (ty * 8 + i) * PS_STR + tx * 4) =
                make_float4(sc[i][0], sc[i][1], sc[i][2], sc[i][3]);
        }
        __syncwarp();   // Ps rows are warp-private (same ty)

        // ---- O += P V : float4-blocked over j ----
#pragma unroll 2
        for (int j4 = 0; j4 < 32; ++j4) {
            float4 p4[8];
#pragma unroll
            for (int i = 0; i < 8; ++i)
                p4[i] = *(const float4*)(Ps + (ty * 8 + i) * PS_STR + j4 * 4);
            float4 v4[4];
#pragma unroll
            for (int jj = 0; jj < 4; ++jj)
                v4[jj] = *(const float4*)(Vs + (j4 * 4 + jj) * VS_STR + tx * 4);
#pragma unroll
            for (int i = 0; i < 8; ++i) {
                Oa[i][0] = fmaf(p4[i].x, v4[0].x, Oa[i][0]);
                Oa[i][1] = fmaf(p4[i].x, v4[0].y, Oa[i][1]);
                Oa[i][2] = fmaf(p4[i].x, v4[0].z, Oa[i][2]);
                Oa[i][3] = fmaf(p4[i].x, v4[0].w, Oa[i][3]);
                Oa[i][0] = fmaf(p4[i].y, v4[1].x, Oa[i][0]);
                Oa[i][1] = fmaf(p4[i].y, v4[1].y, Oa[i][1]);
                Oa[i][2] = fmaf(p4[i].y, v4[1].z, Oa[i][2]);
                Oa[i][3] = fmaf(p4[i].y, v4[1].w, Oa[i][3]);
                Oa[i][0] = fmaf(p4[i].z, v4[2].x, Oa[i][0]);
                Oa[i][1] = fmaf(p4[i].z, v4[2].y, Oa[i][1]);
                Oa[i][2] = fmaf(p4[i].z, v4[2].z, Oa[i][2]);
                Oa[i][3] = fmaf(p4[i].z, v4[2].w, Oa[i][3]);
                Oa[i][0] = fmaf(p4[i].w, v4[3].x, Oa[i][0]);
                Oa[i][1] = fmaf(p4[i].w, v4[3].y, Oa[i][1]);
                Oa[i][2] = fmaf(p4[i].w, v4[3].z, Oa[i][2]);
                Oa[i][3] = fmaf(p4[i].w, v4[3].w, Oa[i][3]);
            }
        }
    }

    float* zb = z + ((size_t)(b * SEQ + qt * 64)) * EMB + h * HDIM;
#pragma unroll
    for (int i = 0; i < 8; ++i) {
        const float inv = 1.0f / lrow[i];
        *(float4*)(zb + (size_t)(ty * 8 + i) * EMB + tx * 4) =
            make_float4(Oa[i][0] * inv, Oa[i][1] * inv,
                        Oa[i][2] * inv, Oa[i][3] * inv);
    }
}

// ===========================================================================
extern "C" void kernel_launch(void* const* d_in, const int* in_sizes, int n_in,
                              void* d_out, int out_size)
{
    (void)in_sizes; (void)n_in; (void)out_size;
    const float* x   = (const float*)d_in[0];
    const float* Wq  = (const float*)d_in[1];
    const float* Wk  = (const float*)d_in[2];
    const float* Wv  = (const float*)d_in[3];
    const float* Wo  = (const float*)d_in[4];
    const int*   isc = (const int*)d_in[5];

    float *q, *k, *v, *z;
    cudaGetSymbolAddress((void**)&q, g_q);
    cudaGetSymbolAddress((void**)&k, g_k);
    cudaGetSymbolAddress((void**)&v, g_v);
    cudaGetSymbolAddress((void**)&z, g_z);

    uint32_t *xh, *zh, *wqh, *wql, *wkh, *wkl, *wvh, *wvl, *woh, *wol;
    cudaGetSymbolAddress((void**)&xh,  g_xh);
    cudaGetSymbolAddress((void**)&zh,  g_zh);
    cudaGetSymbolAddress((void**)&wqh, g_wqh);
    cudaGetSymbolAddress((void**)&wql, g_wql);
    cudaGetSymbolAddress((void**)&wkh, g_wkh);
    cudaGetSymbolAddress((void**)&wkl, g_wkl);
    cudaGetSymbolAddress((void**)&wvh, g_wvh);
    cudaGetSymbolAddress((void**)&wvl, g_wvl);
    cudaGetSymbolAddress((void**)&woh, g_woh);
    cudaGetSymbolAddress((void**)&wol, g_wol);

    cudaFuncSetAttribute(qkv_gemm, cudaFuncAttributeMaxDynamicSharedMemorySize, GEMM_SMEM_BYTES);
    cudaFuncSetAttribute(o_gemm,   cudaFuncAttributeMaxDynamicSharedMemorySize, GEMM_SMEM_BYTES);
    cudaFuncSetAttribute(flash_attn2, cudaFuncAttributeMaxDynamicSharedMemorySize, FA_SMEM_BYTES);

    dim3 blk(256);

    // ---- pre-split operands (A: hi only; B: hi+lo) ----
    split_hi  <<<2048, 256>>>(x,  xh,  MROWS);
    split_hilo<<<1024, 256>>>(Wq, wqh, wql, EMB);
    split_hilo<<<512,  256>>>(Wk, wkh, wkl, KVDIM);
    split_hilo<<<512,  256>>>(Wv, wvh, wvl, KVDIM);
    split_hilo<<<1024, 256>>>(Wo, woh, wol, EMB);

    // ---- fused Q/K/V projection (one wave-packed launch) ----
    qkv_gemm<<<768, blk, GEMM_SMEM_BYTES>>>(xh, wqh, wql, wkh, wkl, wvh, wvl,
                                            q, k, v);

    // ---- attention ----
    flash_attn2<<<dim3(SEQ / 64, NHEADS, BATCH), blk, FA_SMEM_BYTES>>>(q, k, v, z, isc);

    // ---- output projection ----
    split_hi<<<2048, 256>>>(z, zh, MROWS);
    o_gemm<<<dim3(EMB / 128, MROWS / 128), blk, GEMM_SMEM_BYTES>>>(zh, woh, wol,
                                                                   (float*)d_out);
}

// round 8
// speedup vs baseline: 1.5217x; 1.0008x over previous
#include <cuda_runtime.h>
#include <math.h>
#include <stdint.h>

#define EMB    2048
#define SEQ    2048
#define BATCH  2
#define NHEADS 16
#define NKVH   4
#define HDIM   128
#define KVDIM  (NKVH * HDIM)      /* 512  */
#define MROWS  (BATCH * SEQ)      /* 4096 */
#define NKT    64                 /* K / 32 (K = 2048 for every GEMM) */

// -------- scratch (device globals: no allocations allowed) ----------------
__device__ float g_q[(size_t)MROWS * EMB];
__device__ float g_k[(size_t)MROWS * KVDIM];
__device__ float g_v[(size_t)MROWS * KVDIM];
__device__ float g_z[(size_t)MROWS * EMB];

// tf32 pre-split operand buffers (fragment-permuted tiled layout)
__device__ uint32_t g_xh[(size_t)MROWS * EMB];          // A operands: hi only
__device__ uint32_t g_zh[(size_t)MROWS * EMB];
__device__ uint32_t g_wqh[(size_t)EMB * EMB];           // B operands: hi+lo
__device__ uint32_t g_wql[(size_t)EMB * EMB];
__device__ uint32_t g_wkh[(size_t)KVDIM * EMB];
__device__ uint32_t g_wkl[(size_t)KVDIM * EMB];
__device__ uint32_t g_wvh[(size_t)KVDIM * EMB];
__device__ uint32_t g_wvl[(size_t)KVDIM * EMB];
__device__ uint32_t g_woh[(size_t)EMB * EMB];
__device__ uint32_t g_wol[(size_t)EMB * EMB];

// ===========================================================================
// helpers
// ===========================================================================
__device__ __forceinline__ uint32_t smem_u32(const void* p) {
    uint32_t a;
    asm("{ .reg .u64 t; cvta.to.shared.u64 t, %1; cvt.u32.u64 %0, t; }"
        : "=r"(a) : "l"(p));
    return a;
}

__device__ __forceinline__ void tf32_split(float x, uint32_t& h, uint32_t& l) {
    asm("cvt.rna.tf32.f32 %0, %1;" : "=r"(h) : "f"(x));
    float hf = __uint_as_float(h);
    float lo = x - hf;                 // exact in fp32
    asm("cvt.rna.tf32.f32 %0, %1;" : "=r"(l) : "f"(lo));
}
__device__ __forceinline__ uint32_t tf32_hi(float x) {
    uint32_t h;
    asm("cvt.rna.tf32.f32 %0, %1;" : "=r"(h) : "f"(x));
    return h;
}

__device__ __forceinline__ void mma_tf32(float* d,
                                         uint32_t a0, uint32_t a1,
                                         uint32_t a2, uint32_t a3,
                                         uint32_t b0, uint32_t b1) {
    asm volatile(
        "mma.sync.aligned.m16n8k8.row.col.f32.tf32.tf32.f32 "
        "{%0,%1,%2,%3}, {%4,%5,%6,%7}, {%8,%9}, {%0,%1,%2,%3};"
        : "+f"(d[0]), "+f"(d[1]), "+f"(d[2]), "+f"(d[3])
        : "r"(a0), "r"(a1), "r"(a2), "r"(a3), "r"(b0), "r"(b1));
}

__device__ __forceinline__ void cp16(uint32_t smem_dst, const void* gmem_src) {
    asm volatile("cp.async.cg.shared.global [%0], [%1], 16;"
                 :: "r"(smem_dst), "l"(gmem_src));
}
#define CP_COMMIT()  asm volatile("cp.async.commit_group;" ::: "memory")
#define CP_WAIT2()   asm volatile("cp.async.wait_group 2;" ::: "memory")

// ===========================================================================
// splits: fp32 row-major [Mrows][2048] -> tf32 fragment-permuted tile layout
//   word[(kt*Mrows + row)*32 + ((8*(k&3) + (k>>2)&7... ) ^ ((row&7)<<2))]
// (identical layout to the round-6 passing kernel)
// ===========================================================================
__global__ void split_hilo(const float* __restrict__ in, uint32_t* __restrict__ hi,
                           uint32_t* __restrict__ lo, int Mrows)
{
    const int n4 = Mrows * (EMB >> 2);
    for (int t = blockIdx.x * blockDim.x + threadIdx.x; t < n4;
         t += gridDim.x * blockDim.x) {
        const int cg  = t & ((EMB >> 2) - 1);
        const int row = t >> 9;
        float4 v = *(const float4*)(in + (size_t)row * EMB + cg * 4);
        const int kt = cg >> 3;
        const int c7 = cg & 7;
        const size_t base = ((size_t)kt * Mrows + row) * 32;
        const int sw = (row & 7) << 2;
        float va[4] = { v.x, v.y, v.z, v.w };
#pragma unroll
        for (int j = 0; j < 4; ++j) {
            uint32_t h, l;
            tf32_split(va[j], h, l);
            const int w = ((j << 3) + c7) ^ sw;
            hi[base + w] = h;
            lo[base + w] = l;
        }
    }
}

__global__ void split_hi(const float* __restrict__ in, uint32_t* __restrict__ hi,
                         int Mrows)
{
    const int n4 = Mrows * (EMB >> 2);
    for (int t = blockIdx.x * blockDim.x + threadIdx.x; t < n4;
         t += gridDim.x * blockDim.x) {
        const int cg  = t & ((EMB >> 2) - 1);
        const int row = t >> 9;
        float4 v = *(const float4*)(in + (size_t)row * EMB + cg * 4);
        const int kt = cg >> 3;
        const int c7 = cg & 7;
        const size_t base = ((size_t)kt * Mrows + row) * 32;
        const int sw = (row & 7) << 2;
        float va[4] = { v.x, v.y, v.z, v.w };
#pragma unroll
        for (int j = 0; j < 4; ++j)
            hi[base + (((j << 3) + c7) ^ sw)] = tf32_hi(va[j]);
    }
}

// ===========================================================================
// tf32x2 GEMM core (mma.sync): C[M,N] = A[M,K] * B[N,K]^T
// A truncated to tf32-hi; B = Bh + Bl (full precision).
// CTA 128x128, BK=32, 256 threads = 8 warps (2m x 4n), 4-stage cp.async.
// smem: 4 stages x {Ah,Bh,Bl} x 4096 words = 192 KB.
// ===========================================================================
#define STG_WORDS 12288                       /* 3 arrays * 4096 */
#define GEMM_SMEM_BYTES (4 * STG_WORDS * 4)   /* 196608 */

__device__ __forceinline__ void issue_stage(
    uint32_t sm_stage_byte,
    const uint32_t* __restrict__ Ah, const uint32_t* __restrict__ Bh,
    const uint32_t* __restrict__ Bl,
    int kt, int Md, int Nd, int arow0, int brow0, int tid)
{
    const uint32_t* srcs[3] = {
        Ah + ((size_t)kt * Md + arow0) * 32,
        Bh + ((size_t)kt * Nd + brow0) * 32,
        Bl + ((size_t)kt * Nd + brow0) * 32 };
#pragma unroll
    for (int arr = 0; arr < 3; ++arr) {
        const uint32_t dbase = sm_stage_byte + arr * 16384;
        const char* s = (const char*)srcs[arr];
#pragma unroll
        for (int i = 0; i < 4; ++i) {
            const int id = tid + i * 256;          // 16B chunk id, 0..1023
            cp16(dbase + id * 16, s + (size_t)id * 16);
        }
    }
}

__device__ __forceinline__ void gemm_core(
    const uint32_t* __restrict__ Ah, const uint32_t* __restrict__ Bh,
    const uint32_t* __restrict__ Bl, float* __restrict__ C,
    int Md, int Nd, int bm, int bn, bool rope, bool qsc, uint32_t* smx)
{
    const uint32_t sbyte = smem_u32(smx);
    const int tid  = threadIdx.x;
    const int wid  = tid >> 5;
    const int lane = tid & 31;
    const int g    = lane >> 2;
    const int tig  = lane & 3;
    const int wm   = wid >> 2;
    const int wn   = wid & 3;
    const int arow0 = bm * 128;
    const int brow0 = bn * 128;

    float acc[4][4][4];
#pragma unroll
    for (int mt = 0; mt < 4; ++mt)
#pragma unroll
        for (int nt = 0; nt < 4; ++nt)
#pragma unroll
            for (int e = 0; e < 4; ++e) acc[mt][nt][e] = 0.f;

#pragma unroll
    for (int s = 0; s < 3; ++s) {
        issue_stage(sbyte + s * STG_WORDS * 4, Ah, Bh, Bl, s,
                    Md, Nd, arow0, brow0, tid);
        CP_COMMIT();
    }

    const int gsw = g << 2;

    for (int kt = 0; kt < NKT; ++kt) {
        const int buf = kt & 3;
        CP_WAIT2();
        __syncthreads();

        const uint32_t* sAh = smx + buf * STG_WORDS;
        const uint32_t* sBh = sAh + 4096;
        const uint32_t* sBl = sAh + 8192;

#pragma unroll
        for (int kh = 0; kh < 2; ++kh) {
            const int wk = (tig * 8 + 4 * kh) ^ gsw;
            uint4 bh4[4], bl4[4];
#pragma unroll
            for (int nt = 0; nt < 4; ++nt) {
                const int rn = wn * 32 + nt * 8 + g;
                bh4[nt] = *(const uint4*)(sBh + rn * 32 + wk);
                bl4[nt] = *(const uint4*)(sBl + rn * 32 + wk);
            }
#pragma unroll
            for (int mt = 0; mt < 4; ++mt) {
                const int r = wm * 64 + mt * 16 + g;
                const uint4 ah0 = *(const uint4*)(sAh + r * 32 + wk);
                const uint4 ah1 = *(const uint4*)(sAh + (r + 8) * 32 + wk);
#pragma unroll
                for (int nt = 0; nt < 4; ++nt) {
                    mma_tf32(acc[mt][nt], ah0.x, ah1.x, ah0.y, ah1.y, bh4[nt].x, bh4[nt].y);
                    mma_tf32(acc[mt][nt], ah0.x, ah1.x, ah0.y, ah1.y, bl4[nt].x, bl4[nt].y);
                    mma_tf32(acc[mt][nt], ah0.z, ah1.z, ah0.w, ah1.w, bh4[nt].z, bh4[nt].w);
                    mma_tf32(acc[mt][nt], ah0.z, ah1.z, ah0.w, ah1.w, bl4[nt].z, bl4[nt].w);
                }
            }
        }

        __syncthreads();
        if (kt + 3 < NKT)
            issue_stage(sbyte + ((kt + 3) & 3) * STG_WORDS * 4, Ah, Bh, Bl,
                        kt + 3, Md, Nd, arow0, brow0, tid);
        CP_COMMIT();
    }

    // ------------------ epilogue: (RoPE/scale) + store -------------------
    const float qscale = 0.08838834764831844f;    // 1/sqrt(128)
    float freqv[4];
    if (rope) {
#pragma unroll
        for (int nt = 0; nt < 4; ++nt) {
            const int col = bn * 128 + wn * 32 + nt * 8 + tig * 2;
            const int p   = (col & 127) >> 1;
            freqv[nt] = (float)exp((double)p * -0.14391156831212787);
        }
    }
#pragma unroll
    for (int mt = 0; mt < 4; ++mt) {
        const int r0 = bm * 128 + wm * 64 + mt * 16 + g;
        const int r1 = r0 + 8;
        float t0 = 0.f, t1 = 0.f;
        if (rope) {
            t0 = (float)(r0 & (SEQ - 1)) * 6.28318530717958647692f;
            t1 = (float)(r1 & (SEQ - 1)) * 6.28318530717958647692f;
        }
#pragma unroll
        for (int nt = 0; nt < 4; ++nt) {
            float* a = acc[mt][nt];
            if (rope) {
#pragma unroll
                for (int hrow = 0; hrow < 2; ++hrow) {
                    const float ang = (hrow ? t1 : t0) * freqv[nt];
                    float kq = rintf(ang * 0.15915494309189535f);
                    float xx = fmaf(kq, -6.28125f, ang);
                    xx       = fmaf(kq, -0.0019353071795864769f, xx);
                    const float sn = sinf(xx), cs = cosf(xx);
                    const float v0 = a[hrow * 2 + 0], v1 = a[hrow * 2 + 1];
                    a[hrow * 2 + 0] = v0 * cs - v1 * sn;
                    a[hrow * 2 + 1] = v0 * sn + v1 * cs;
                }
            }
            if (qsc) {
#pragma unroll
                for (int e = 0; e < 4; ++e) a[e] *= qscale;
            }
            const int col = bn * 128 + wn * 32 + nt * 8 + tig * 2;
            *(float2*)(C + (size_t)r0 * Nd + col) = make_float2(a[0], a[1]);
            *(float2*)(C + (size_t)r1 * Nd + col) = make_float2(a[2], a[3]);
        }
    }
}

// fused Q/K/V projection: 768 CTAs (Q:512, K:128, V:128), one wave-packed launch
__global__ __launch_bounds__(256)
void qkv_gemm(const uint32_t* __restrict__ xh,
              const uint32_t* __restrict__ wqh, const uint32_t* __restrict__ wql,
              const uint32_t* __restrict__ wkh, const uint32_t* __restrict__ wkl,
              const uint32_t* __restrict__ wvh, const uint32_t* __restrict__ wvl,
              float* __restrict__ q, float* __restrict__ k, float* __restrict__ v)
{
    extern __shared__ uint32_t smx[];
    const int id = blockIdx.x;
    const uint32_t *Bh, *Bl;
    float* C;
    int bm, bn, Nd;
    bool rope, qsc;
    if (id < 512)      { bm = id >> 4;  bn = id & 15; Bh = wqh; Bl = wql; C = q; Nd = EMB;   rope = true;  qsc = true;  }
    else if (id < 640) { int t = id - 512; bm = t >> 2; bn = t & 3; Bh = wkh; Bl = wkl; C = k; Nd = KVDIM; rope = true;  qsc = false; }
    else               { int t = id - 640; bm = t >> 2; bn = t & 3; Bh = wvh; Bl = wvl; C = v; Nd = KVDIM; rope = false; qsc = false; }
    gemm_core(xh, Bh, Bl, C, MROWS, Nd, bm, bn, rope, qsc, smx);
}

__global__ __launch_bounds__(256)
void o_gemm(const uint32_t* __restrict__ zh,
            const uint32_t* __restrict__ woh, const uint32_t* __restrict__ wol,
            float* __restrict__ out)
{
    extern __shared__ uint32_t smx[];
    gemm_core(zh, woh, wol, out, MROWS, EMB, blockIdx.y, blockIdx.x,
              false, false, smx);
}

// ===========================================================================
// Flash attention v2.1, fp32, BM=64, BN=128, D=128, 256 threads (8x4/thread),
// GQA (kv = h/4). PV loop float4-blocked (12 LDS.128 + 128 FMA per j4 step).
// ===========================================================================
#define QT_STR 68
#define KT_STR 132
#define VS_STR 132
#define PS_STR 132
#define QT_OFF 0
#define KT_OFF 8704
#define VS_OFF 25600
#define PS_OFF 42496
#define FA_SMEM_BYTES (50944 * 4)    /* 203776 */

__global__ __launch_bounds__(256)
void flash_attn2(const float* __restrict__ q, const float* __restrict__ k,
                 const float* __restrict__ v, float* __restrict__ z,
                 const int* __restrict__ is_causal)
{
    extern __shared__ float smf[];
    float* Qt = smf + QT_OFF;
    float* Kt = smf + KT_OFF;
    float* Vs = smf + VS_OFF;
    float* Ps = smf + PS_OFF;

    const int tid = threadIdx.x;
    const int tx  = tid & 31;
    const int ty  = tid >> 5;
    const int qt  = blockIdx.x;
    const int h   = blockIdx.y;
    const int b   = blockIdx.z;
    const int kvh = h >> 2;
    const bool causal = (*is_causal) != 0;

    const float* qb = q + ((size_t)(b * SEQ + qt * 64)) * EMB + h * HDIM;
#pragma unroll
    for (int p = 0; p < 8; ++p) {
        const int idx = tid + p * 256;
        const int m = idx & 63, c = idx >> 6;
        float4 t4 = *(const float4*)(qb + (size_t)m * EMB + c * 4);
        Qt[(c * 4 + 0) * QT_STR + m] = t4.x;
        Qt[(c * 4 + 1) * QT_STR + m] = t4.y;
        Qt[(c * 4 + 2) * QT_STR + m] = t4.z;
        Qt[(c * 4 + 3) * QT_STR + m] = t4.w;
    }

    float mrow[8], lrow[8], Oa[8][4];
#pragma unroll
    for (int i = 0; i < 8; ++i) {
        mrow[i] = -1e30f; lrow[i] = 0.f;
#pragma unroll
        for (int c = 0; c < 4; ++c) Oa[i][c] = 0.f;
    }

    const int kend = causal ? (qt >> 1) : (SEQ / 128 - 1);
    for (int kn = 0; kn <= kend; ++kn) {
        __syncthreads();
        const float* kb = k + ((size_t)(b * SEQ + kn * 128)) * KVDIM + kvh * HDIM;
        const float* vb = v + ((size_t)(b * SEQ + kn * 128)) * KVDIM + kvh * HDIM;
#pragma unroll
        for (int p = 0; p < 16; ++p) {
            const int idx = tid + p * 256;
            const int n = idx & 127, c = idx >> 7;
            float4 k4 = *(const float4*)(kb + (size_t)n * KVDIM + c * 4);
            Kt[(c * 4 + 0) * KT_STR + n] = k4.x;
            Kt[(c * 4 + 1) * KT_STR + n] = k4.y;
            Kt[(c * 4 + 2) * KT_STR + n] = k4.z;
            Kt[(c * 4 + 3) * KT_STR + n] = k4.w;
        }
#pragma unroll
        for (int p = 0; p < 16; ++p) {
            const int idx = tid + p * 256;
            const int n = idx >> 5, c = idx & 31;
            float4 v4 = *(const float4*)(vb + (size_t)n * KVDIM + c * 4);
            *(float4*)(Vs + n * VS_STR + c * 4) = v4;
        }
        __syncthreads();

        // ---- scores S = Q K^T : 8x4 per thread ----
        float sc[8][4];
#pragma unroll
        for (int i = 0; i < 8; ++i)
#pragma unroll
            for (int j = 0; j < 4; ++j) sc[i][j] = 0.f;

#pragma unroll 2
        for (int kk = 0; kk < 128; ++kk) {
            float a[8], bf[4];
            *(float4*)(a)     = *(const float4*)(Qt + kk * QT_STR + ty * 8);
            *(float4*)(a + 4) = *(const float4*)(Qt + kk * QT_STR + ty * 8 + 4);
            *(float4*)(bf)    = *(const float4*)(Kt + kk * KT_STR + tx * 4);
#pragma unroll
            for (int i = 0; i < 8; ++i)
#pragma unroll
                for (int j = 0; j < 4; ++j)
                    sc[i][j] = fmaf(a[i], bf[j], sc[i][j]);
        }

        if (causal && kn == kend) {
            const int rbase = qt * 64 + ty * 8;
            const int cbase = kn * 128 + tx * 4;
#pragma unroll
            for (int i = 0; i < 8; ++i)
#pragma unroll
                for (int j = 0; j < 4; ++j)
                    if (cbase + j > rbase + i) sc[i][j] = -1e30f;
        }

        // ---- online softmax ----
#pragma unroll
        for (int i = 0; i < 8; ++i) {
            float tm = fmaxf(fmaxf(sc[i][0], sc[i][1]), fmaxf(sc[i][2], sc[i][3]));
#pragma unroll
            for (int off = 16; off > 0; off >>= 1)
                tm = fmaxf(tm, __shfl_xor_sync(0xffffffffu, tm, off));
            const float mnew  = fmaxf(mrow[i], tm);
            const float alpha = __expf(mrow[i] - mnew);
            mrow[i] = mnew;
            float ps = 0.f;
#pragma unroll
            for (int j = 0; j < 4; ++j) {
                sc[i][j] = __expf(sc[i][j] - mnew);
                ps += sc[i][j];
            }
#pragma unroll
            for (int off = 16; off > 0; off >>= 1)
                ps += __shfl_xor_sync(0xffffffffu, ps, off);
            lrow[i] = lrow[i] * alpha + ps;
#pragma unroll
            for (int c = 0; c < 4; ++c) Oa[i][c] *= alpha;
            *(float4*)(Ps + (ty * 8 + i) * PS_STR + tx * 4) =
                make_float4(sc[i][0], sc[i][1], sc[i][2], sc[i][3]);
        }
        __syncwarp();   // Ps rows are warp-private (same ty)

        // ---- O += P V : float4-blocked over j ----
#pragma unroll 2
        for (int j4 = 0; j4 < 32; ++j4) {
            float4 p4[8];
#pragma unroll
            for (int i = 0; i < 8; ++i)
                p4[i] = *(const float4*)(Ps + (ty * 8 + i) * PS_STR + j4 * 4);
            float4 v4[4];
#pragma unroll
            for (int jj = 0; jj < 4; ++jj)
                v4[jj] = *(const float4*)(Vs + (j4 * 4 + jj) * VS_STR + tx * 4);
#pragma unroll
            for (int i = 0; i < 8; ++i) {
                Oa[i][0] = fmaf(p4[i].x, v4[0].x, Oa[i][0]);
                Oa[i][1] = fmaf(p4[i].x, v4[0].y, Oa[i][1]);
                Oa[i][2] = fmaf(p4[i].x, v4[0].z, Oa[i][2]);
                Oa[i][3] = fmaf(p4[i].x, v4[0].w, Oa[i][3]);
                Oa[i][0] = fmaf(p4[i].y, v4[1].x, Oa[i][0]);
                Oa[i][1] = fmaf(p4[i].y, v4[1].y, Oa[i][1]);
                Oa[i][2] = fmaf(p4[i].y, v4[1].z, Oa[i][2]);
                Oa[i][3] = fmaf(p4[i].y, v4[1].w, Oa[i][3]);
                Oa[i][0] = fmaf(p4[i].z, v4[2].x, Oa[i][0]);
                Oa[i][1] = fmaf(p4[i].z, v4[2].y, Oa[i][1]);
                Oa[i][2] = fmaf(p4[i].z, v4[2].z, Oa[i][2]);
                Oa[i][3] = fmaf(p4[i].z, v4[2].w, Oa[i][3]);
                Oa[i][0] = fmaf(p4[i].w, v4[3].x, Oa[i][0]);
                Oa[i][1] = fmaf(p4[i].w, v4[3].y, Oa[i][1]);
                Oa[i][2] = fmaf(p4[i].w, v4[3].z, Oa[i][2]);
                Oa[i][3] = fmaf(p4[i].w, v4[3].w, Oa[i][3]);
            }
        }
    }

    float* zb = z + ((size_t)(b * SEQ + qt * 64)) * EMB + h * HDIM;
#pragma unroll
    for (int i = 0; i < 8; ++i) {
        const float inv = 1.0f / lrow[i];
        *(float4*)(zb + (size_t)(ty * 8 + i) * EMB + tx * 4) =
            make_float4(Oa[i][0] * inv, Oa[i][1] * inv,
                        Oa[i][2] * inv, Oa[i][3] * inv);
    }
}

// ===========================================================================
extern "C" void kernel_launch(void* const* d_in, const int* in_sizes, int n_in,
                              void* d_out, int out_size)
{
    (void)in_sizes; (void)n_in; (void)out_size;
    const float* x   = (const float*)d_in[0];
    const float* Wq  = (const float*)d_in[1];
    const float* Wk  = (const float*)d_in[2];
    const float* Wv  = (const float*)d_in[3];
    const float* Wo  = (const float*)d_in[4];
    const int*   isc = (const int*)d_in[5];

    float *q, *k, *v, *z;
    cudaGetSymbolAddress((void**)&q, g_q);
    cudaGetSymbolAddress((void**)&k, g_k);
    cudaGetSymbolAddress((void**)&v, g_v);
    cudaGetSymbolAddress((void**)&z, g_z);

    uint32_t *xh, *zh, *wqh, *wql, *wkh, *wkl, *wvh, *wvl, *woh, *wol;
    cudaGetSymbolAddress((void**)&xh,  g_xh);
    cudaGetSymbolAddress((void**)&zh,  g_zh);
    cudaGetSymbolAddress((void**)&wqh, g_wqh);
    cudaGetSymbolAddress((void**)&wql, g_wql);
    cudaGetSymbolAddress((void**)&wkh, g_wkh);
    cudaGetSymbolAddress((void**)&wkl, g_wkl);
    cudaGetSymbolAddress((void**)&wvh, g_wvh);
    cudaGetSymbolAddress((void**)&wvl, g_wvl);
    cudaGetSymbolAddress((void**)&woh, g_woh);
    cudaGetSymbolAddress((void**)&wol, g_wol);

    cudaFuncSetAttribute(qkv_gemm, cudaFuncAttributeMaxDynamicSharedMemorySize, GEMM_SMEM_BYTES);
    cudaFuncSetAttribute(o_gemm,   cudaFuncAttributeMaxDynamicSharedMemorySize, GEMM_SMEM_BYTES);
    cudaFuncSetAttribute(flash_attn2, cudaFuncAttributeMaxDynamicSharedMemorySize, FA_SMEM_BYTES);

    dim3 blk(256);

    // ---- pre-split operands (A: hi only; B: hi+lo) ----
    split_hi  <<<2048, 256>>>(x,  xh,  MROWS);
    split_hilo<<<1024, 256>>>(Wq, wqh, wql, EMB);
    split_hilo<<<512,  256>>>(Wk, wkh, wkl, KVDIM);
    split_hilo<<<512,  256>>>(Wv, wvh, wvl, KVDIM);
    split_hilo<<<1024, 256>>>(Wo, woh, wol, EMB);

    // ---- fused Q/K/V projection (one wave-packed launch) ----
    qkv_gemm<<<768, blk, GEMM_SMEM_BYTES>>>(xh, wqh, wql, wkh, wkl, wvh, wvl,
                                            q, k, v);

    // ---- attention ----
    flash_attn2<<<dim3(SEQ / 64, NHEADS, BATCH), blk, FA_SMEM_BYTES>>>(q, k, v, z, isc);

    // ---- output projection ----
    split_hi<<<2048, 256>>>(z, zh, MROWS);
    o_gemm<<<dim3(EMB / 128, MROWS / 128), blk, GEMM_SMEM_BYTES>>>(zh, woh, wol,
                                                                   (float*)d_out);
}

// round 9
// speedup vs baseline: 2.0079x; 1.3195x over previous
#include <cuda_runtime.h>
#include <math.h>
#include <stdint.h>

#define EMB    2048
#define SEQ    2048
#define BATCH  2
#define NHEADS 16
#define NKVH   4
#define HDIM   128
#define KVDIM  (NKVH * HDIM)      /* 512  */
#define MROWS  (BATCH * SEQ)      /* 4096 */
#define NKT    64                 /* K / 32 (K = 2048 for every GEMM) */

// -------- scratch (device globals: no allocations allowed) ----------------
__device__ float g_q[(size_t)MROWS * EMB];
__device__ float g_k[(size_t)MROWS * KVDIM];
__device__ float g_v[(size_t)MROWS * KVDIM];
__device__ float g_z[(size_t)MROWS * EMB];

// tf32 pre-split operand buffers (fragment-permuted tiled layout)
__device__ uint32_t g_xh[(size_t)MROWS * EMB];          // A operands: hi only
__device__ uint32_t g_zh[(size_t)MROWS * EMB];
__device__ uint32_t g_wqh[(size_t)EMB * EMB];           // B operands: hi+lo
__device__ uint32_t g_wql[(size_t)EMB * EMB];
__device__ uint32_t g_wkh[(size_t)KVDIM * EMB];
__device__ uint32_t g_wkl[(size_t)KVDIM * EMB];
__device__ uint32_t g_wvh[(size_t)KVDIM * EMB];
__device__ uint32_t g_wvl[(size_t)KVDIM * EMB];
__device__ uint32_t g_woh[(size_t)EMB * EMB];
__device__ uint32_t g_wol[(size_t)EMB * EMB];

// ===========================================================================
// helpers
// ===========================================================================
__device__ __forceinline__ uint32_t smem_u32(const void* p) {
    uint32_t a;
    asm("{ .reg .u64 t; cvta.to.shared.u64 t, %1; cvt.u32.u64 %0, t; }"
        : "=r"(a) : "l"(p));
    return a;
}

__device__ __forceinline__ void tf32_split(float x, uint32_t& h, uint32_t& l) {
    asm("cvt.rna.tf32.f32 %0, %1;" : "=r"(h) : "f"(x));
    float hf = __uint_as_float(h);
    float lo = x - hf;                 // exact in fp32
    asm("cvt.rna.tf32.f32 %0, %1;" : "=r"(l) : "f"(lo));
}
__device__ __forceinline__ uint32_t tf32_hi(float x) {
    uint32_t h;
    asm("cvt.rna.tf32.f32 %0, %1;" : "=r"(h) : "f"(x));
    return h;
}
__device__ __forceinline__ float tf32_rna(float x) {
    return __uint_as_float(tf32_hi(x));
}

__device__ __forceinline__ void mma_tf32(float* d,
                                         uint32_t a0, uint32_t a1,
                                         uint32_t a2, uint32_t a3,
                                         uint32_t b0, uint32_t b1) {
    asm volatile(
        "mma.sync.aligned.m16n8k8.row.col.f32.tf32.tf32.f32 "
        "{%0,%1,%2,%3}, {%4,%5,%6,%7}, {%8,%9}, {%0,%1,%2,%3};"
        : "+f"(d[0]), "+f"(d[1]), "+f"(d[2]), "+f"(d[3])
        : "r"(a0), "r"(a1), "r"(a2), "r"(a3), "r"(b0), "r"(b1));
}

__device__ __forceinline__ void cp16(uint32_t smem_dst, const void* gmem_src) {
    asm volatile("cp.async.cg.shared.global [%0], [%1], 16;"
                 :: "r"(smem_dst), "l"(gmem_src));
}
#define CP_COMMIT()  asm volatile("cp.async.commit_group;" ::: "memory")
#define CP_WAIT2()   asm volatile("cp.async.wait_group 2;" ::: "memory")

// ===========================================================================
// splits: fp32 row-major [Mrows][2048] -> tf32 fragment-permuted tile layout
// ===========================================================================
__global__ void split_hilo(const float* __restrict__ in, uint32_t* __restrict__ hi,
                           uint32_t* __restrict__ lo, int Mrows)
{
    const int n4 = Mrows * (EMB >> 2);
    for (int t = blockIdx.x * blockDim.x + threadIdx.x; t < n4;
         t += gridDim.x * blockDim.x) {
        const int cg  = t & ((EMB >> 2) - 1);
        const int row = t >> 9;
        float4 v = *(const float4*)(in + (size_t)row * EMB + cg * 4);
        const int kt = cg >> 3;
        const int c7 = cg & 7;
        const size_t base = ((size_t)kt * Mrows + row) * 32;
        const int sw = (row & 7) << 2;
        float va[4] = { v.x, v.y, v.z, v.w };
#pragma unroll
        for (int j = 0; j < 4; ++j) {
            uint32_t h, l;
            tf32_split(va[j], h, l);
            const int w = ((j << 3) + c7) ^ sw;
            hi[base + w] = h;
            lo[base + w] = l;
        }
    }
}

__global__ void split_hi(const float* __restrict__ in, uint32_t* __restrict__ hi,
                         int Mrows)
{
    const int n4 = Mrows * (EMB >> 2);
    for (int t = blockIdx.x * blockDim.x + threadIdx.x; t < n4;
         t += gridDim.x * blockDim.x) {
        const int cg  = t & ((EMB >> 2) - 1);
        const int row = t >> 9;
        float4 v = *(const float4*)(in + (size_t)row * EMB + cg * 4);
        const int kt = cg >> 3;
        const int c7 = cg & 7;
        const size_t base = ((size_t)kt * Mrows + row) * 32;
        const int sw = (row & 7) << 2;
        float va[4] = { v.x, v.y, v.z, v.w };
#pragma unroll
        for (int j = 0; j < 4; ++j)
            hi[base + (((j << 3) + c7) ^ sw)] = tf32_hi(va[j]);
    }
}

// ===========================================================================
// tf32x2 GEMM core (round-7 passing version + optional tf32-RNA output round)
// ===========================================================================
#define STG_WORDS 12288
#define GEMM_SMEM_BYTES (4 * STG_WORDS * 4)   /* 196608 */

__device__ __forceinline__ void issue_stage(
    uint32_t sm_stage_byte,
    const uint32_t* __restrict__ Ah, const uint32_t* __restrict__ Bh,
    const uint32_t* __restrict__ Bl,
    int kt, int Md, int Nd, int arow0, int brow0, int tid)
{
    const uint32_t* srcs[3] = {
        Ah + ((size_t)kt * Md + arow0) * 32,
        Bh + ((size_t)kt * Nd + brow0) * 32,
        Bl + ((size_t)kt * Nd + brow0) * 32 };
#pragma unroll
    for (int arr = 0; arr < 3; ++arr) {
        const uint32_t dbase = sm_stage_byte + arr * 16384;
        const char* s = (const char*)srcs[arr];
#pragma unroll
        for (int i = 0; i < 4; ++i) {
            const int id = tid + i * 256;
            cp16(dbase + id * 16, s + (size_t)id * 16);
        }
    }
}

__device__ __forceinline__ void gemm_core(
    const uint32_t* __restrict__ Ah, const uint32_t* __restrict__ Bh,
    const uint32_t* __restrict__ Bl, float* __restrict__ C,
    int Md, int Nd, int bm, int bn, bool rope, bool qsc, bool rnd,
    uint32_t* smx)
{
    const uint32_t sbyte = smem_u32(smx);
    const int tid  = threadIdx.x;
    const int wid  = tid >> 5;
    const int lane = tid & 31;
    const int g    = lane >> 2;
    const int tig  = lane & 3;
    const int wm   = wid >> 2;
    const int wn   = wid & 3;
    const int arow0 = bm * 128;
    const int brow0 = bn * 128;

    float acc[4][4][4];
#pragma unroll
    for (int mt = 0; mt < 4; ++mt)
#pragma unroll
        for (int nt = 0; nt < 4; ++nt)
#pragma unroll
            for (int e = 0; e < 4; ++e) acc[mt][nt][e] = 0.f;

#pragma unroll
    for (int s = 0; s < 3; ++s) {
        issue_stage(sbyte + s * STG_WORDS * 4, Ah, Bh, Bl, s,
                    Md, Nd, arow0, brow0, tid);
        CP_COMMIT();
    }

    const int gsw = g << 2;

    for (int kt = 0; kt < NKT; ++kt) {
        const int buf = kt & 3;
        CP_WAIT2();
        __syncthreads();

        const uint32_t* sAh = smx + buf * STG_WORDS;
        const uint32_t* sBh = sAh + 4096;
        const uint32_t* sBl = sAh + 8192;

#pragma unroll
        for (int kh = 0; kh < 2; ++kh) {
            const int wk = (tig * 8 + 4 * kh) ^ gsw;
            uint4 bh4[4], bl4[4];
#pragma unroll
            for (int nt = 0; nt < 4; ++nt) {
                const int rn = wn * 32 + nt * 8 + g;
                bh4[nt] = *(const uint4*)(sBh + rn * 32 + wk);
                bl4[nt] = *(const uint4*)(sBl + rn * 32 + wk);
            }
#pragma unroll
            for (int mt = 0; mt < 4; ++mt) {
                const int r = wm * 64 + mt * 16 + g;
                const uint4 ah0 = *(const uint4*)(sAh + r * 32 + wk);
                const uint4 ah1 = *(const uint4*)(sAh + (r + 8) * 32 + wk);
#pragma unroll
                for (int nt = 0; nt < 4; ++nt) {
                    mma_tf32(acc[mt][nt], ah0.x, ah1.x, ah0.y, ah1.y, bh4[nt].x, bh4[nt].y);
                    mma_tf32(acc[mt][nt], ah0.x, ah1.x, ah0.y, ah1.y, bl4[nt].x, bl4[nt].y);
                    mma_tf32(acc[mt][nt], ah0.z, ah1.z, ah0.w, ah1.w, bh4[nt].z, bh4[nt].w);
                    mma_tf32(acc[mt][nt], ah0.z, ah1.z, ah0.w, ah1.w, bl4[nt].z, bl4[nt].w);
                }
            }
        }

        __syncthreads();
        if (kt + 3 < NKT)
            issue_stage(sbyte + ((kt + 3) & 3) * STG_WORDS * 4, Ah, Bh, Bl,
                        kt + 3, Md, Nd, arow0, brow0, tid);
        CP_COMMIT();
    }

    // ---------------- epilogue: (RoPE/scale/round) + store -----------------
    const float qscale = 0.08838834764831844f;    // 1/sqrt(128)
    float freqv[4];
    if (rope) {
#pragma unroll
        for (int nt = 0; nt < 4; ++nt) {
            const int col = bn * 128 + wn * 32 + nt * 8 + tig * 2;
            const int p   = (col & 127) >> 1;
            freqv[nt] = (float)exp((double)p * -0.14391156831212787);
        }
    }
#pragma unroll
    for (int mt = 0; mt < 4; ++mt) {
        const int r0 = bm * 128 + wm * 64 + mt * 16 + g;
        const int r1 = r0 + 8;
        float t0 = 0.f, t1 = 0.f;
        if (rope) {
            t0 = (float)(r0 & (SEQ - 1)) * 6.28318530717958647692f;
            t1 = (float)(r1 & (SEQ - 1)) * 6.28318530717958647692f;
        }
#pragma unroll
        for (int nt = 0; nt < 4; ++nt) {
            float* a = acc[mt][nt];
            if (rope) {
#pragma unroll
                for (int hrow = 0; hrow < 2; ++hrow) {
                    const float ang = (hrow ? t1 : t0) * freqv[nt];
                    float kq = rintf(ang * 0.15915494309189535f);
                    float xx = fmaf(kq, -6.28125f, ang);
                    xx       = fmaf(kq, -0.0019353071795864769f, xx);
                    const float sn = sinf(xx), cs = cosf(xx);
                    const float v0 = a[hrow * 2 + 0], v1 = a[hrow * 2 + 1];
                    a[hrow * 2 + 0] = v0 * cs - v1 * sn;
                    a[hrow * 2 + 1] = v0 * sn + v1 * cs;
                }
            }
            if (qsc) {
#pragma unroll
                for (int e = 0; e < 4; ++e) a[e] *= qscale;
            }
            if (rnd) {
#pragma unroll
                for (int e = 0; e < 4; ++e) a[e] = tf32_rna(a[e]);
            }
            const int col = bn * 128 + wn * 32 + nt * 8 + tig * 2;
            *(float2*)(C + (size_t)r0 * Nd + col) = make_float2(a[0], a[1]);
            *(float2*)(C + (size_t)r1 * Nd + col) = make_float2(a[2], a[3]);
        }
    }
}

// fused Q/K/V projection: 768 CTAs (Q:512, K:128, V:128), one wave-packed launch
// outputs rounded to tf32-RNA so the tensor-core attention sees exact tf32 values
__global__ __launch_bounds__(256)
void qkv_gemm(const uint32_t* __restrict__ xh,
              const uint32_t* __restrict__ wqh, const uint32_t* __restrict__ wql,
              const uint32_t* __restrict__ wkh, const uint32_t* __restrict__ wkl,
              const uint32_t* __restrict__ wvh, const uint32_t* __restrict__ wvl,
              float* __restrict__ q, float* __restrict__ k, float* __restrict__ v)
{
    extern __shared__ uint32_t smx[];
    const int id = blockIdx.x;
    const uint32_t *Bh, *Bl;
    float* C;
    int bm, bn, Nd;
    bool rope, qsc;
    if (id < 512)      { bm = id >> 4;  bn = id & 15; Bh = wqh; Bl = wql; C = q; Nd = EMB;   rope = true;  qsc = true;  }
    else if (id < 640) { int t = id - 512; bm = t >> 2; bn = t & 3; Bh = wkh; Bl = wkl; C = k; Nd = KVDIM; rope = true;  qsc = false; }
    else               { int t = id - 640; bm = t >> 2; bn = t & 3; Bh = wvh; Bl = wvl; C = v; Nd = KVDIM; rope = false; qsc = false; }
    gemm_core(xh, Bh, Bl, C, MROWS, Nd, bm, bn, rope, qsc, true, smx);
}

__global__ __launch_bounds__(256)
void o_gemm(const uint32_t* __restrict__ zh,
            const uint32_t* __restrict__ woh, const uint32_t* __restrict__ wol,
            float* __restrict__ out)
{
    extern __shared__ uint32_t smx[];
    gemm_core(zh, woh, wol, out, MROWS, EMB, blockIdx.y, blockIdx.x,
              false, false, false, smx);
}

// ===========================================================================
// Flash attention v3 — tensor core (mma.sync tf32), BM=BN=64, D=128.
// 8 warps: QK warp tile 32m x 16n; PV warp tile 32m x 32d.
// smem (words): Qs 8192 | Ks 2x8192 | Vt 2x8192 | Ps 4096 | redm 256 | reds 256
// ===========================================================================
#define FA3_SMEM_BYTES (45568 * 4)   /* 182272 */

__global__ __launch_bounds__(256)
void flash_attn3(const float* __restrict__ q, const float* __restrict__ k,
                 const float* __restrict__ v, float* __restrict__ z,
                 const int* __restrict__ is_causal)
{
    extern __shared__ uint32_t sm[];
    uint32_t* Qs = sm;                 // 8192
    uint32_t* Ks = sm + 8192;          // 2 x 8192
    uint32_t* Vt = sm + 24576;         // 2 x 8192
    uint32_t* Ps = sm + 40960;         // 4096
    float* redm  = (float*)(sm + 45056);
    float* reds  = (float*)(sm + 45312);

    const int tid  = threadIdx.x;
    const int lane = tid & 31, wid = tid >> 5;
    const int g    = lane >> 2, tig = lane & 3;
    const int wm   = wid >> 2,  wn  = wid & 3;
    const int qt = blockIdx.x, h = blockIdx.y, b = blockIdx.z;
    const int kvh = h >> 2;
    const bool causal = (*is_causal) != 0;
    const int gsw = g << 2;

    // ---- stage Q (64 x 128) into fragment layout ----
    const float* qb = q + ((size_t)(b * SEQ + qt * 64)) * EMB + h * HDIM;
#pragma unroll
    for (int p = 0; p < 8; ++p) {
        const int idx = tid + p * 256;
        const int m = idx & 63, cg = idx >> 6;
        float4 t4 = *(const float4*)(qb + (size_t)m * EMB + cg * 4);
        const int kt = cg >> 3, c7 = cg & 7, sw = (m & 7) << 2;
        uint32_t* dst = Qs + (kt * 64 + m) * 32;
        dst[(c7     ) ^ sw] = __float_as_uint(t4.x);
        dst[(c7 +  8) ^ sw] = __float_as_uint(t4.y);
        dst[(c7 + 16) ^ sw] = __float_as_uint(t4.z);
        dst[(c7 + 24) ^ sw] = __float_as_uint(t4.w);
    }

    float mrow[2][2], lrow[2][2], Oa[2][4][4];
#pragma unroll
    for (int mt = 0; mt < 2; ++mt)
#pragma unroll
        for (int rh = 0; rh < 2; ++rh) { mrow[mt][rh] = -1e30f; lrow[mt][rh] = 0.f; }
#pragma unroll
    for (int mt = 0; mt < 2; ++mt)
#pragma unroll
        for (int nt = 0; nt < 4; ++nt)
#pragma unroll
            for (int e = 0; e < 4; ++e) Oa[mt][nt][e] = 0.f;

    const int kend = causal ? qt : (SEQ / 64 - 1);
    const float* kb0 = k + (size_t)(b * SEQ) * KVDIM + kvh * HDIM;
    const float* vb0 = v + (size_t)(b * SEQ) * KVDIM + kvh * HDIM;

    // ---- prefetch tile 0 into registers ----
    float4 kf[8], vf[8];
#pragma unroll
    for (int p = 0; p < 8; ++p) {
        const int ik = tid + p * 256;
        kf[p] = *(const float4*)(kb0 + (size_t)(ik >> 5) * KVDIM + (ik & 31) * 4);
        vf[p] = *(const float4*)(vb0 + (size_t)(ik & 63) * KVDIM + (ik >> 6) * 4);
    }

    for (int kn = 0; kn <= kend; ++kn) {
        const int buf = kn & 1;
        uint32_t* Kb = Ks + buf * 8192;
        uint32_t* Vb = Vt + buf * 8192;

        // ---- store staged K/V registers into fragment-layout smem ----
#pragma unroll
        for (int p = 0; p < 8; ++p) {
            const int ik = tid + p * 256;
            {   // K: row n = ik>>5, k-cols cg*4..cg*4+3
                const int n = ik >> 5, cg = ik & 31;
                const int kt = cg >> 3, c7 = cg & 7, sw = (n & 7) << 2;
                uint32_t* dst = Kb + (kt * 64 + n) * 32;
                dst[(c7     ) ^ sw] = __float_as_uint(kf[p].x);
                dst[(c7 +  8) ^ sw] = __float_as_uint(kf[p].y);
                dst[(c7 + 16) ^ sw] = __float_as_uint(kf[p].z);
                dst[(c7 + 24) ^ sw] = __float_as_uint(kf[p].w);
            }
            {   // V transposed: k-col n = ik&63, rows d = 4*(ik>>6)+j
                const int n = ik & 63, d4 = ik >> 6;
                const int ktp = n >> 5;
                const int w = ((n & 3) << 3) + ((n >> 2) & 7);
                const float vv[4] = { vf[p].x, vf[p].y, vf[p].z, vf[p].w };
#pragma unroll
                for (int j = 0; j < 4; ++j) {
                    const int d = d4 * 4 + j;
                    Vb[(ktp * 128 + d) * 32 + (w ^ ((d & 7) << 2))] =
                        __float_as_uint(vv[j]);
                }
            }
        }
        __syncthreads();

        // prefetch next tile (overlaps compute below)
        if (kn < kend) {
            const float* kb = kb0 + (size_t)(kn + 1) * 64 * KVDIM;
            const float* vb = vb0 + (size_t)(kn + 1) * 64 * KVDIM;
#pragma unroll
            for (int p = 0; p < 8; ++p) {
                const int ik = tid + p * 256;
                kf[p] = *(const float4*)(kb + (size_t)(ik >> 5) * KVDIM + (ik & 31) * 4);
                vf[p] = *(const float4*)(vb + (size_t)(ik & 63) * KVDIM + (ik >> 6) * 4);
            }
        }

        // ---- S = Q K^T (tensor core) ----
        float sa[2][2][4];
#pragma unroll
        for (int mt = 0; mt < 2; ++mt)
#pragma unroll
            for (int nt = 0; nt < 2; ++nt)
#pragma unroll
                for (int e = 0; e < 4; ++e) sa[mt][nt][e] = 0.f;

#pragma unroll
        for (int kt = 0; kt < 4; ++kt) {
            const uint32_t* sQ = Qs + kt * 2048;
            const uint32_t* sK = Kb + kt * 2048;
#pragma unroll
            for (int kh = 0; kh < 2; ++kh) {
                const int wk = (tig * 8 + 4 * kh) ^ gsw;
                uint4 bf[2];
#pragma unroll
                for (int nt = 0; nt < 2; ++nt) {
                    const int rn = wn * 16 + nt * 8 + g;
                    bf[nt] = *(const uint4*)(sK + rn * 32 + wk);
                }
#pragma unroll
                for (int mt = 0; mt < 2; ++mt) {
                    const int r = wm * 32 + mt * 16 + g;
                    const uint4 a0 = *(const uint4*)(sQ + r * 32 + wk);
                    const uint4 a1 = *(const uint4*)(sQ + (r + 8) * 32 + wk);
#pragma unroll
                    for (int nt = 0; nt < 2; ++nt) {
                        mma_tf32(sa[mt][nt], a0.x, a1.x, a0.y, a1.y, bf[nt].x, bf[nt].y);
                        mma_tf32(sa[mt][nt], a0.z, a1.z, a0.w, a1.w, bf[nt].z, bf[nt].w);
                    }
                }
            }
        }

        // ---- causal mask on the diagonal tile ----
        if (causal && kn == qt) {
#pragma unroll
            for (int mt = 0; mt < 2; ++mt)
#pragma unroll
                for (int nt = 0; nt < 2; ++nt)
#pragma unroll
                    for (int e = 0; e < 4; ++e) {
                        const int m  = wm * 32 + mt * 16 + g + 8 * (e >> 1);
                        const int nl = wn * 16 + nt * 8 + 2 * tig + (e & 1);
                        if (nl > m) sa[mt][nt][e] = -1e30f;
                    }
        }

        // ---- online softmax: cross-warp row reductions via smem ----
        float tmx[2][2];
#pragma unroll
        for (int mt = 0; mt < 2; ++mt)
#pragma unroll
            for (int rh = 0; rh < 2; ++rh) {
                float t = fmaxf(fmaxf(sa[mt][0][rh * 2], sa[mt][0][rh * 2 + 1]),
                                fmaxf(sa[mt][1][rh * 2], sa[mt][1][rh * 2 + 1]));
                t = fmaxf(t, __shfl_xor_sync(0xffffffffu, t, 1));
                t = fmaxf(t, __shfl_xor_sync(0xffffffffu, t, 2));
                tmx[mt][rh] = t;
            }
        if (tig == 0) {
#pragma unroll
            for (int mt = 0; mt < 2; ++mt)
#pragma unroll
                for (int rh = 0; rh < 2; ++rh)
                    redm[(wm * 32 + mt * 16 + g + 8 * rh) * 4 + wn] = tmx[mt][rh];
        }
        __syncthreads();

        float alpha[2][2];
#pragma unroll
        for (int mt = 0; mt < 2; ++mt)
#pragma unroll
            for (int rh = 0; rh < 2; ++rh) {
                const int m = wm * 32 + mt * 16 + g + 8 * rh;
                const float tm = fmaxf(fmaxf(redm[m * 4 + 0], redm[m * 4 + 1]),
                                       fmaxf(redm[m * 4 + 2], redm[m * 4 + 3]));
                const float mnew = fmaxf(mrow[mt][rh], tm);
                alpha[mt][rh] = __expf(mrow[mt][rh] - mnew);
                mrow[mt][rh]  = mnew;
            }

        float psum[2][2] = { {0.f, 0.f}, {0.f, 0.f} };
#pragma unroll
        for (int mt = 0; mt < 2; ++mt)
#pragma unroll
            for (int nt = 0; nt < 2; ++nt)
#pragma unroll
                for (int e = 0; e < 4; ++e) {
                    const int rh = e >> 1;
                    float pv = __expf(sa[mt][nt][e] - mrow[mt][rh]);
                    pv = tf32_rna(pv);    // round P; sums use rounded values
                    sa[mt][nt][e] = pv;
                    psum[mt][rh] += pv;
                }
#pragma unroll
        for (int mt = 0; mt < 2; ++mt)
#pragma unroll
            for (int rh = 0; rh < 2; ++rh) {
                psum[mt][rh] += __shfl_xor_sync(0xffffffffu, psum[mt][rh], 1);
                psum[mt][rh] += __shfl_xor_sync(0xffffffffu, psum[mt][rh], 2);
            }
        if (tig == 0) {
#pragma unroll
            for (int mt = 0; mt < 2; ++mt)
#pragma unroll
                for (int rh = 0; rh < 2; ++rh)
                    reds[(wm * 32 + mt * 16 + g + 8 * rh) * 4 + wn] = psum[mt][rh];
        }

        // ---- write P into fragment layout ----
#pragma unroll
        for (int mt = 0; mt < 2; ++mt)
#pragma unroll
            for (int nt = 0; nt < 2; ++nt)
#pragma unroll
                for (int e = 0; e < 4; ++e) {
                    const int m  = wm * 32 + mt * 16 + g + 8 * (e >> 1);
                    const int nl = wn * 16 + nt * 8 + 2 * tig + (e & 1);
                    const int ktp = nl >> 5;
                    const int w = ((nl & 3) << 3) + ((nl >> 2) & 7);
                    Ps[(ktp * 64 + m) * 32 + (w ^ gsw)] = __float_as_uint(sa[mt][nt][e]);
                }
        __syncthreads();

        // ---- fold in tile sums, rescale O accumulators ----
#pragma unroll
        for (int mt = 0; mt < 2; ++mt)
#pragma unroll
            for (int rh = 0; rh < 2; ++rh) {
                const int m = wm * 32 + mt * 16 + g + 8 * rh;
                const float s4 = (reds[m * 4 + 0] + reds[m * 4 + 1]) +
                                 (reds[m * 4 + 2] + reds[m * 4 + 3]);
                lrow[mt][rh] = lrow[mt][rh] * alpha[mt][rh] + s4;
            }
#pragma unroll
        for (int mt = 0; mt < 2; ++mt)
#pragma unroll
            for (int nt = 0; nt < 4; ++nt)
#pragma unroll
                for (int e = 0; e < 4; ++e)
                    Oa[mt][nt][e] *= alpha[mt][e >> 1];

        // ---- O += P V (tensor core) ----
#pragma unroll
        for (int ktp = 0; ktp < 2; ++ktp) {
            const uint32_t* sP = Ps + ktp * 2048;
            const uint32_t* sV = Vb + ktp * 4096;
#pragma unroll
            for (int kh = 0; kh < 2; ++kh) {
                const int wk = (tig * 8 + 4 * kh) ^ gsw;
                uint4 bf[4];
#pragma unroll
                for (int nt = 0; nt < 4; ++nt) {
                    const int rd = wn * 32 + nt * 8 + g;
                    bf[nt] = *(const uint4*)(sV + rd * 32 + wk);
                }
#pragma unroll
                for (int mt = 0; mt < 2; ++mt) {
                    const int r = wm * 32 + mt * 16 + g;
                    const uint4 a0 = *(const uint4*)(sP + r * 32 + wk);
                    const uint4 a1 = *(const uint4*)(sP + (r + 8) * 32 + wk);
#pragma unroll
                    for (int nt = 0; nt < 4; ++nt) {
                        mma_tf32(Oa[mt][nt], a0.x, a1.x, a0.y, a1.y, bf[nt].x, bf[nt].y);
                        mma_tf32(Oa[mt][nt], a0.z, a1.z, a0.w, a1.w, bf[nt].z, bf[nt].w);
                    }
                }
            }
        }
    }

    // ---- finalize: O / l -> z ----
    float* zb = z + ((size_t)(b * SEQ + qt * 64)) * EMB + h * HDIM;
#pragma unroll
    for (int mt = 0; mt < 2; ++mt) {
        const int r0 = wm * 32 + mt * 16 + g;
        const int r1 = r0 + 8;
        const float inv0 = 1.0f / lrow[mt][0];
        const float inv1 = 1.0f / lrow[mt][1];
#pragma unroll
        for (int nt = 0; nt < 4; ++nt) {
            const int d = wn * 32 + nt * 8 + 2 * tig;
            *(float2*)(zb + (size_t)r0 * EMB + d) =
                make_float2(Oa[mt][nt][0] * inv0, Oa[mt][nt][1] * inv0);
            *(float2*)(zb + (size_t)r1 * EMB + d) =
                make_float2(Oa[mt][nt][2] * inv1, Oa[mt][nt][3] * inv1);
        }
    }
}

// ===========================================================================
extern "C" void kernel_launch(void* const* d_in, const int* in_sizes, int n_in,
                              void* d_out, int out_size)
{
    (void)in_sizes; (void)n_in; (void)out_size;
    const float* x   = (const float*)d_in[0];
    const float* Wq  = (const float*)d_in[1];
    const float* Wk  = (const float*)d_in[2];
    const float* Wv  = (const float*)d_in[3];
    const float* Wo  = (const float*)d_in[4];
    const int*   isc = (const int*)d_in[5];

    float *q, *k, *v, *z;
    cudaGetSymbolAddress((void**)&q, g_q);
    cudaGetSymbolAddress((void**)&k, g_k);
    cudaGetSymbolAddress((void**)&v, g_v);
    cudaGetSymbolAddress((void**)&z, g_z);

    uint32_t *xh, *zh, *wqh, *wql, *wkh, *wkl, *wvh, *wvl, *woh, *wol;
    cudaGetSymbolAddress((void**)&xh,  g_xh);
    cudaGetSymbolAddress((void**)&zh,  g_zh);
    cudaGetSymbolAddress((void**)&wqh, g_wqh);
    cudaGetSymbolAddress((void**)&wql, g_wql);
    cudaGetSymbolAddress((void**)&wkh, g_wkh);
    cudaGetSymbolAddress((void**)&wkl, g_wkl);
    cudaGetSymbolAddress((void**)&wvh, g_wvh);
    cudaGetSymbolAddress((void**)&wvl, g_wvl);
    cudaGetSymbolAddress((void**)&woh, g_woh);
    cudaGetSymbolAddress((void**)&wol, g_wol);

    cudaFuncSetAttribute(qkv_gemm, cudaFuncAttributeMaxDynamicSharedMemorySize, GEMM_SMEM_BYTES);
    cudaFuncSetAttribute(o_gemm,   cudaFuncAttributeMaxDynamicSharedMemorySize, GEMM_SMEM_BYTES);
    cudaFuncSetAttribute(flash_attn3, cudaFuncAttributeMaxDynamicSharedMemorySize, FA3_SMEM_BYTES);

    dim3 blk(256);

    // ---- pre-split operands (A: hi only; B: hi+lo) ----
    split_hi  <<<2048, 256>>>(x,  xh,  MROWS);
    split_hilo<<<1024, 256>>>(Wq, wqh, wql, EMB);
    split_hilo<<<512,  256>>>(Wk, wkh, wkl, KVDIM);
    split_hilo<<<512,  256>>>(Wv, wvh, wvl, KVDIM);
    split_hilo<<<1024, 256>>>(Wo, woh, wol, EMB);

    // ---- fused Q/K/V projection (tf32-rounded outputs for fa3) ----
    qkv_gemm<<<768, blk, GEMM_SMEM_BYTES>>>(xh, wqh, wql, wkh, wkl, wvh, wvl,
                                            q, k, v);

    // ---- tensor-core flash attention ----
    flash_attn3<<<dim3(SEQ / 64, NHEADS, BATCH), blk, FA3_SMEM_BYTES>>>(q, k, v, z, isc);

    // ---- output projection ----
    split_hi<<<2048, 256>>>(z, zh, MROWS);
    o_gemm<<<dim3(EMB / 128, MROWS / 128), blk, GEMM_SMEM_BYTES>>>(zh, woh, wol,
                                                                   (float*)d_out);
}

// round 10
// speedup vs baseline: 2.3964x; 1.1935x over previous
#include <cuda_runtime.h>
#include <math.h>
#include <stdint.h>

#define EMB    2048
#define SEQ    2048
#define BATCH  2
#define NHEADS 16
#define NKVH   4
#define HDIM   128
#define KVDIM  (NKVH * HDIM)      /* 512  */
#define MROWS  (BATCH * SEQ)      /* 4096 */
#define NKT    64                 /* K / 32 (K = 2048 for every GEMM) */

// -------- scratch (device globals: no allocations allowed) ----------------
__device__ float g_q[(size_t)MROWS * EMB];
__device__ float g_k[(size_t)MROWS * KVDIM];
__device__ float g_v[(size_t)MROWS * KVDIM];
__device__ float g_z[(size_t)MROWS * EMB];

// tf32 pre-split operand buffers (fragment-permuted tiled layout)
__device__ uint32_t g_xh[(size_t)MROWS * EMB];          // A operands: hi only
__device__ uint32_t g_zh[(size_t)MROWS * EMB];
__device__ uint32_t g_wqh[(size_t)EMB * EMB];           // QKV weights: hi only
__device__ uint32_t g_wkh[(size_t)KVDIM * EMB];
__device__ uint32_t g_wvh[(size_t)KVDIM * EMB];
__device__ uint32_t g_woh[(size_t)EMB * EMB];           // O weights: hi+lo
__device__ uint32_t g_wol[(size_t)EMB * EMB];

// ===========================================================================
// helpers
// ===========================================================================
__device__ __forceinline__ uint32_t smem_u32(const void* p) {
    uint32_t a;
    asm("{ .reg .u64 t; cvta.to.shared.u64 t, %1; cvt.u32.u64 %0, t; }"
        : "=r"(a) : "l"(p));
    return a;
}

__device__ __forceinline__ void tf32_split(float x, uint32_t& h, uint32_t& l) {
    asm("cvt.rna.tf32.f32 %0, %1;" : "=r"(h) : "f"(x));
    float hf = __uint_as_float(h);
    float lo = x - hf;                 // exact in fp32
    asm("cvt.rna.tf32.f32 %0, %1;" : "=r"(l) : "f"(lo));
}
__device__ __forceinline__ uint32_t tf32_hi(float x) {
    uint32_t h;
    asm("cvt.rna.tf32.f32 %0, %1;" : "=r"(h) : "f"(x));
    return h;
}
__device__ __forceinline__ float tf32_rna(float x) {
    return __uint_as_float(tf32_hi(x));
}

__device__ __forceinline__ void mma_tf32(float* d,
                                         uint32_t a0, uint32_t a1,
                                         uint32_t a2, uint32_t a3,
                                         uint32_t b0, uint32_t b1) {
    asm volatile(
        "mma.sync.aligned.m16n8k8.row.col.f32.tf32.tf32.f32 "
        "{%0,%1,%2,%3}, {%4,%5,%6,%7}, {%8,%9}, {%0,%1,%2,%3};"
        : "+f"(d[0]), "+f"(d[1]), "+f"(d[2]), "+f"(d[3])
        : "r"(a0), "r"(a1), "r"(a2), "r"(a3), "r"(b0), "r"(b1));
}

__device__ __forceinline__ void cp16(uint32_t smem_dst, const void* gmem_src) {
    asm volatile("cp.async.cg.shared.global [%0], [%1], 16;"
                 :: "r"(smem_dst), "l"(gmem_src));
}
#define CP_COMMIT()  asm volatile("cp.async.commit_group;" ::: "memory")
#define CP_WAIT2()   asm volatile("cp.async.wait_group 2;" ::: "memory")

// ===========================================================================
// splits: fp32 row-major [Mrows][2048] -> tf32 fragment-permuted tile layout
// ===========================================================================
__global__ void split_hilo(const float* __restrict__ in, uint32_t* __restrict__ hi,
                           uint32_t* __restrict__ lo, int Mrows)
{
    const int n4 = Mrows * (EMB >> 2);
    for (int t = blockIdx.x * blockDim.x + threadIdx.x; t < n4;
         t += gridDim.x * blockDim.x) {
        const int cg  = t & ((EMB >> 2) - 1);
        const int row = t >> 9;
        float4 v = *(const float4*)(in + (size_t)row * EMB + cg * 4);
        const int kt = cg >> 3;
        const int c7 = cg & 7;
        const size_t base = ((size_t)kt * Mrows + row) * 32;
        const int sw = (row & 7) << 2;
        float va[4] = { v.x, v.y, v.z, v.w };
#pragma unroll
        for (int j = 0; j < 4; ++j) {
            uint32_t h, l;
            tf32_split(va[j], h, l);
            const int w = ((j << 3) + c7) ^ sw;
            hi[base + w] = h;
            lo[base + w] = l;
        }
    }
}

__global__ void split_hi(const float* __restrict__ in, uint32_t* __restrict__ hi,
                         int Mrows)
{
    const int n4 = Mrows * (EMB >> 2);
    for (int t = blockIdx.x * blockDim.x + threadIdx.x; t < n4;
         t += gridDim.x * blockDim.x) {
        const int cg  = t & ((EMB >> 2) - 1);
        const int row = t >> 9;
        float4 v = *(const float4*)(in + (size_t)row * EMB + cg * 4);
        const int kt = cg >> 3;
        const int c7 = cg & 7;
        const size_t base = ((size_t)kt * Mrows + row) * 32;
        const int sw = (row & 7) << 2;
        float va[4] = { v.x, v.y, v.z, v.w };
#pragma unroll
        for (int j = 0; j < 4; ++j)
            hi[base + (((j << 3) + c7) ^ sw)] = tf32_hi(va[j]);
    }
}

// ===========================================================================
// tf32 GEMM core (mma.sync): C[M,N] = A[M,K] * B[N,K]^T
// NB=1: A,B truncated (tf32x1).  NB=2: B = Bh + Bl (tf32x2).
// CTA 128x128, BK=32, 256 threads = 8 warps (2m x 4n), 4-stage cp.async.
// ===========================================================================
template <int NB>
__device__ __forceinline__ void issue_stage(
    uint32_t sm_stage_byte,
    const uint32_t* __restrict__ Ah, const uint32_t* __restrict__ Bh,
    const uint32_t* __restrict__ Bl,
    int kt, int Md, int Nd, int arow0, int brow0, int tid)
{
    const uint32_t* srcs[3] = {
        Ah + ((size_t)kt * Md + arow0) * 32,
        Bh + ((size_t)kt * Nd + brow0) * 32,
        (NB == 2) ? (Bl + ((size_t)kt * Nd + brow0) * 32) : (const uint32_t*)0 };
#pragma unroll
    for (int arr = 0; arr < 1 + NB; ++arr) {
        const uint32_t dbase = sm_stage_byte + arr * 16384;
        const char* s = (const char*)srcs[arr];
#pragma unroll
        for (int i = 0; i < 4; ++i) {
            const int id = tid + i * 256;
            cp16(dbase + id * 16, s + (size_t)id * 16);
        }
    }
}

template <int NB>
__device__ __forceinline__ void gemm_core(
    const uint32_t* __restrict__ Ah, const uint32_t* __restrict__ Bh,
    const uint32_t* __restrict__ Bl, float* __restrict__ C,
    int Md, int Nd, int bm, int bn, bool rope, bool qsc, bool rnd,
    uint32_t* smx)
{
    const int STG = (1 + NB) * 4096;          // words per stage
    const uint32_t sbyte = smem_u32(smx);
    const int tid  = threadIdx.x;
    const int wid  = tid >> 5;
    const int lane = tid & 31;
    const int g    = lane >> 2;
    const int tig  = lane & 3;
    const int wm   = wid >> 2;
    const int wn   = wid & 3;
    const int arow0 = bm * 128;
    const int brow0 = bn * 128;

    float acc[4][4][4];
#pragma unroll
    for (int mt = 0; mt < 4; ++mt)
#pragma unroll
        for (int nt = 0; nt < 4; ++nt)
#pragma unroll
            for (int e = 0; e < 4; ++e) acc[mt][nt][e] = 0.f;

#pragma unroll
    for (int s = 0; s < 3; ++s) {
        issue_stage<NB>(sbyte + s * STG * 4, Ah, Bh, Bl, s,
                        Md, Nd, arow0, brow0, tid);
        CP_COMMIT();
    }

    const int gsw = g << 2;

    for (int kt = 0; kt < NKT; ++kt) {
        const int buf = kt & 3;
        CP_WAIT2();
        __syncthreads();

        const uint32_t* sAh = smx + buf * STG;
        const uint32_t* sBh = sAh + 4096;
        const uint32_t* sBl = sAh + 8192;

#pragma unroll
        for (int kh = 0; kh < 2; ++kh) {
            const int wk = (tig * 8 + 4 * kh) ^ gsw;
            uint4 bh4[4], bl4[4];
#pragma unroll
            for (int nt = 0; nt < 4; ++nt) {
                const int rn = wn * 32 + nt * 8 + g;
                bh4[nt] = *(const uint4*)(sBh + rn * 32 + wk);
                if (NB == 2) bl4[nt] = *(const uint4*)(sBl + rn * 32 + wk);
            }
#pragma unroll
            for (int mt = 0; mt < 4; ++mt) {
                const int r = wm * 64 + mt * 16 + g;
                const uint4 ah0 = *(const uint4*)(sAh + r * 32 + wk);
                const uint4 ah1 = *(const uint4*)(sAh + (r + 8) * 32 + wk);
#pragma unroll
                for (int nt = 0; nt < 4; ++nt) {
                    mma_tf32(acc[mt][nt], ah0.x, ah1.x, ah0.y, ah1.y, bh4[nt].x, bh4[nt].y);
                    if (NB == 2)
                        mma_tf32(acc[mt][nt], ah0.x, ah1.x, ah0.y, ah1.y, bl4[nt].x, bl4[nt].y);
                    mma_tf32(acc[mt][nt], ah0.z, ah1.z, ah0.w, ah1.w, bh4[nt].z, bh4[nt].w);
                    if (NB == 2)
                        mma_tf32(acc[mt][nt], ah0.z, ah1.z, ah0.w, ah1.w, bl4[nt].z, bl4[nt].w);
                }
            }
        }

        __syncthreads();
        if (kt + 3 < NKT)
            issue_stage<NB>(sbyte + ((kt + 3) & 3) * STG * 4, Ah, Bh, Bl,
                            kt + 3, Md, Nd, arow0, brow0, tid);
        CP_COMMIT();
    }

    // ---------------- epilogue: (RoPE/scale/round) + store -----------------
    const float qscale = 0.08838834764831844f;    // 1/sqrt(128)
    float freqv[4];
    if (rope) {
#pragma unroll
        for (int nt = 0; nt < 4; ++nt) {
            const int col = bn * 128 + wn * 32 + nt * 8 + tig * 2;
            const int p   = (col & 127) >> 1;
            freqv[nt] = (float)exp((double)p * -0.14391156831212787);
        }
    }
#pragma unroll
    for (int mt = 0; mt < 4; ++mt) {
        const int r0 = bm * 128 + wm * 64 + mt * 16 + g;
        const int r1 = r0 + 8;
        float t0 = 0.f, t1 = 0.f;
        if (rope) {
            t0 = (float)(r0 & (SEQ - 1)) * 6.28318530717958647692f;
            t1 = (float)(r1 & (SEQ - 1)) * 6.28318530717958647692f;
        }
#pragma unroll
        for (int nt = 0; nt < 4; ++nt) {
            float* a = acc[mt][nt];
            if (rope) {
#pragma unroll
                for (int hrow = 0; hrow < 2; ++hrow) {
                    const float ang = (hrow ? t1 : t0) * freqv[nt];
                    float kq = rintf(ang * 0.15915494309189535f);
                    float xx = fmaf(kq, -6.28125f, ang);
                    xx       = fmaf(kq, -0.0019353071795864769f, xx);
                    const float sn = sinf(xx), cs = cosf(xx);
                    const float v0 = a[hrow * 2 + 0], v1 = a[hrow * 2 + 1];
                    a[hrow * 2 + 0] = v0 * cs - v1 * sn;
                    a[hrow * 2 + 1] = v0 * sn + v1 * cs;
                }
            }
            if (qsc) {
#pragma unroll
                for (int e = 0; e < 4; ++e) a[e] *= qscale;
            }
            if (rnd) {
#pragma unroll
                for (int e = 0; e < 4; ++e) a[e] = tf32_rna(a[e]);
            }
            const int col = bn * 128 + wn * 32 + nt * 8 + tig * 2;
            *(float2*)(C + (size_t)r0 * Nd + col) = make_float2(a[0], a[1]);
            *(float2*)(C + (size_t)r1 * Nd + col) = make_float2(a[2], a[3]);
        }
    }
}

#define QKV_SMEM_BYTES (4 * 8192 * 4)     /* 131072 : NB=1 */
#define O_SMEM_BYTES   (4 * 12288 * 4)    /* 196608 : NB=2 */

// fused Q/K/V projection: 768 CTAs (Q:512, K:128, V:128), tf32x1,
// outputs rounded to tf32-RNA so the tensor-core attention sees exact tf32
__global__ __launch_bounds__(256)
void qkv_gemm(const uint32_t* __restrict__ xh,
              const uint32_t* __restrict__ wqh,
              const uint32_t* __restrict__ wkh,
              const uint32_t* __restrict__ wvh,
              float* __restrict__ q, float* __restrict__ k, float* __restrict__ v)
{
    extern __shared__ uint32_t smx[];
    const int id = blockIdx.x;
    const uint32_t *Bh;
    float* C;
    int bm, bn, Nd;
    bool rope, qsc;
    if (id < 512)      { bm = id >> 4;  bn = id & 15; Bh = wqh; C = q; Nd = EMB;   rope = true;  qsc = true;  }
    else if (id < 640) { int t = id - 512; bm = t >> 2; bn = t & 3; Bh = wkh; C = k; Nd = KVDIM; rope = true;  qsc = false; }
    else               { int t = id - 640; bm = t >> 2; bn = t & 3; Bh = wvh; C = v; Nd = KVDIM; rope = false; qsc = false; }
    gemm_core<1>(xh, Bh, (const uint32_t*)0, C, MROWS, Nd, bm, bn,
                 rope, qsc, true, smx);
}

__global__ __launch_bounds__(256)
void o_gemm(const uint32_t* __restrict__ zh,
            const uint32_t* __restrict__ woh, const uint32_t* __restrict__ wol,
            float* __restrict__ out)
{
    extern __shared__ uint32_t smx[];
    gemm_core<2>(zh, woh, wol, out, MROWS, EMB, blockIdx.y, blockIdx.x,
                 false, false, false, smx);
}

// ===========================================================================
// Flash attention v3 — tensor core (mma.sync tf32), BM=BN=64, D=128.
// (identical to the round-9 passing version)
// ===========================================================================
#define FA3_SMEM_BYTES (45568 * 4)   /* 182272 */

__global__ __launch_bounds__(256)
void flash_attn3(const float* __restrict__ q, const float* __restrict__ k,
                 const float* __restrict__ v, float* __restrict__ z,
                 const int* __restrict__ is_causal)
{
    extern __shared__ uint32_t sm[];
    uint32_t* Qs = sm;                 // 8192
    uint32_t* Ks = sm + 8192;          // 2 x 8192
    uint32_t* Vt = sm + 24576;         // 2 x 8192
    uint32_t* Ps = sm + 40960;         // 4096
    float* redm  = (float*)(sm + 45056);
    float* reds  = (float*)(sm + 45312);

    const int tid  = threadIdx.x;
    const int lane = tid & 31, wid = tid >> 5;
    const int g    = lane >> 2, tig = lane & 3;
    const int wm   = wid >> 2,  wn  = wid & 3;
    const int qt = blockIdx.x, h = blockIdx.y, b = blockIdx.z;
    const int kvh = h >> 2;
    const bool causal = (*is_causal) != 0;
    const int gsw = g << 2;

    const float* qb = q + ((size_t)(b * SEQ + qt * 64)) * EMB + h * HDIM;
#pragma unroll
    for (int p = 0; p < 8; ++p) {
        const int idx = tid + p * 256;
        const int m = idx & 63, cg = idx >> 6;
        float4 t4 = *(const float4*)(qb + (size_t)m * EMB + cg * 4);
        const int kt = cg >> 3, c7 = cg & 7, sw = (m & 7) << 2;
        uint32_t* dst = Qs + (kt * 64 + m) * 32;
        dst[(c7     ) ^ sw] = __float_as_uint(t4.x);
        dst[(c7 +  8) ^ sw] = __float_as_uint(t4.y);
        dst[(c7 + 16) ^ sw] = __float_as_uint(t4.z);
        dst[(c7 + 24) ^ sw] = __float_as_uint(t4.w);
    }

    float mrow[2][2], lrow[2][2], Oa[2][4][4];
#pragma unroll
    for (int mt = 0; mt < 2; ++mt)
#pragma unroll
        for (int rh = 0; rh < 2; ++rh) { mrow[mt][rh] = -1e30f; lrow[mt][rh] = 0.f; }
#pragma unroll
    for (int mt = 0; mt < 2; ++mt)
#pragma unroll
        for (int nt = 0; nt < 4; ++nt)
#pragma unroll
            for (int e = 0; e < 4; ++e) Oa[mt][nt][e] = 0.f;

    const int kend = causal ? qt : (SEQ / 64 - 1);
    const float* kb0 = k + (size_t)(b * SEQ) * KVDIM + kvh * HDIM;
    const float* vb0 = v + (size_t)(b * SEQ) * KVDIM + kvh * HDIM;

    float4 kf[8], vf[8];
#pragma unroll
    for (int p = 0; p < 8; ++p) {
        const int ik = tid + p * 256;
        kf[p] = *(const float4*)(kb0 + (size_t)(ik >> 5) * KVDIM + (ik & 31) * 4);
        vf[p] = *(const float4*)(vb0 + (size_t)(ik & 63) * KVDIM + (ik >> 6) * 4);
    }

    for (int kn = 0; kn <= kend; ++kn) {
        const int buf = kn & 1;
        uint32_t* Kb = Ks + buf * 8192;
        uint32_t* Vb = Vt + buf * 8192;

#pragma unroll
        for (int p = 0; p < 8; ++p) {
            const int ik = tid + p * 256;
            {
                const int n = ik >> 5, cg = ik & 31;
                const int kt = cg >> 3, c7 = cg & 7, sw = (n & 7) << 2;
                uint32_t* dst = Kb + (kt * 64 + n) * 32;
                dst[(c7     ) ^ sw] = __float_as_uint(kf[p].x);
                dst[(c7 +  8) ^ sw] = __float_as_uint(kf[p].y);
                dst[(c7 + 16) ^ sw] = __float_as_uint(kf[p].z);
                dst[(c7 + 24) ^ sw] = __float_as_uint(kf[p].w);
            }
            {
                const int n = ik & 63, d4 = ik >> 6;
                const int ktp = n >> 5;
                const int w = ((n & 3) << 3) + ((n >> 2) & 7);
                const float vv[4] = { vf[p].x, vf[p].y, vf[p].z, vf[p].w };
#pragma unroll
                for (int j = 0; j < 4; ++j) {
                    const int d = d4 * 4 + j;
                    Vb[(ktp * 128 + d) * 32 + (w ^ ((d & 7) << 2))] =
                        __float_as_uint(vv[j]);
                }
            }
        }
        __syncthreads();

        if (kn < kend) {
            const float* kb = kb0 + (size_t)(kn + 1) * 64 * KVDIM;
            const float* vb = vb0 + (size_t)(kn + 1) * 64 * KVDIM;
#pragma unroll
            for (int p = 0; p < 8; ++p) {
                const int ik = tid + p * 256;
                kf[p] = *(const float4*)(kb + (size_t)(ik >> 5) * KVDIM + (ik & 31) * 4);
                vf[p] = *(const float4*)(vb + (size_t)(ik & 63) * KVDIM + (ik >> 6) * 4);
            }
        }

        float sa[2][2][4];
#pragma unroll
        for (int mt = 0; mt < 2; ++mt)
#pragma unroll
            for (int nt = 0; nt < 2; ++nt)
#pragma unroll
                for (int e = 0; e < 4; ++e) sa[mt][nt][e] = 0.f;

#pragma unroll
        for (int kt = 0; kt < 4; ++kt) {
            const uint32_t* sQ = Qs + kt * 2048;
            const uint32_t* sK = Kb + kt * 2048;
#pragma unroll
            for (int kh = 0; kh < 2; ++kh) {
                const int wk = (tig * 8 + 4 * kh) ^ gsw;
                uint4 bf[2];
#pragma unroll
                for (int nt = 0; nt < 2; ++nt) {
                    const int rn = wn * 16 + nt * 8 + g;
                    bf[nt] = *(const uint4*)(sK + rn * 32 + wk);
                }
#pragma unroll
                for (int mt = 0; mt < 2; ++mt) {
                    const int r = wm * 32 + mt * 16 + g;
                    const uint4 a0 = *(const uint4*)(sQ + r * 32 + wk);
                    const uint4 a1 = *(const uint4*)(sQ + (r + 8) * 32 + wk);
#pragma unroll
                    for (int nt = 0; nt < 2; ++nt) {
                        mma_tf32(sa[mt][nt], a0.x, a1.x, a0.y, a1.y, bf[nt].x, bf[nt].y);
                        mma_tf32(sa[mt][nt], a0.z, a1.z, a0.w, a1.w, bf[nt].z, bf[nt].w);
                    }
                }
            }
        }

        if (causal && kn == qt) {
#pragma unroll
            for (int mt = 0; mt < 2; ++mt)
#pragma unroll
                for (int nt = 0; nt < 2; ++nt)
#pragma unroll
                    for (int e = 0; e < 4; ++e) {
                        const int m  = wm * 32 + mt * 16 + g + 8 * (e >> 1);
                        const int nl = wn * 16 + nt * 8 + 2 * tig + (e & 1);
                        if (nl > m) sa[mt][nt][e] = -1e30f;
                    }
        }

        float tmx[2][2];
#pragma unroll
        for (int mt = 0; mt < 2; ++mt)
#pragma unroll
            for (int rh = 0; rh < 2; ++rh) {
                float t = fmaxf(fmaxf(sa[mt][0][rh * 2], sa[mt][0][rh * 2 + 1]),
                                fmaxf(sa[mt][1][rh * 2], sa[mt][1][rh * 2 + 1]));
                t = fmaxf(t, __shfl_xor_sync(0xffffffffu, t, 1));
                t = fmaxf(t, __shfl_xor_sync(0xffffffffu, t, 2));
                tmx[mt][rh] = t;
            }
        if (tig == 0) {
#pragma unroll
            for (int mt = 0; mt < 2; ++mt)
#pragma unroll
                for (int rh = 0; rh < 2; ++rh)
                    redm[(wm * 32 + mt * 16 + g + 8 * rh) * 4 + wn] = tmx[mt][rh];
        }
        __syncthreads();

        float alpha[2][2];
#pragma unroll
        for (int mt = 0; mt < 2; ++mt)
#pragma unroll
            for (int rh = 0; rh < 2; ++rh) {
                const int m = wm * 32 + mt * 16 + g + 8 * rh;
                const float tm = fmaxf(fmaxf(redm[m * 4 + 0], redm[m * 4 + 1]),
                                       fmaxf(redm[m * 4 + 2], redm[m * 4 + 3]));
                const float mnew = fmaxf(mrow[mt][rh], tm);
                alpha[mt][rh] = __expf(mrow[mt][rh] - mnew);
                mrow[mt][rh]  = mnew;
            }

        float psum[2][2] = { {0.f, 0.f}, {0.f, 0.f} };
#pragma unroll
        for (int mt = 0; mt < 2; ++mt)
#pragma unroll
            for (int nt = 0; nt < 2; ++nt)
#pragma unroll
                for (int e = 0; e < 4; ++e) {
                    const int rh = e >> 1;
                    float pv = __expf(sa[mt][nt][e] - mrow[mt][rh]);
                    pv = tf32_rna(pv);
                    sa[mt][nt][e] = pv;
                    psum[mt][rh] += pv;
                }
#pragma unroll
        for (int mt = 0; mt < 2; ++mt)
#pragma unroll
            for (int rh = 0; rh < 2; ++rh) {
                psum[mt][rh] += __shfl_xor_sync(0xffffffffu, psum[mt][rh], 1);
                psum[mt][rh] += __shfl_xor_sync(0xffffffffu, psum[mt][rh], 2);
            }
        if (tig == 0) {
#pragma unroll
            for (int mt = 0; mt < 2; ++mt)
#pragma unroll
                for (int rh = 0; rh < 2; ++rh)
                    reds[(wm * 32 + mt * 16 + g + 8 * rh) * 4 + wn] = psum[mt][rh];
        }

#pragma unroll
        for (int mt = 0; mt < 2; ++mt)
#pragma unroll
            for (int nt = 0; nt < 2; ++nt)
#pragma unroll
                for (int e = 0; e < 4; ++e) {
                    const int m  = wm * 32 + mt * 16 + g + 8 * (e >> 1);
                    const int nl = wn * 16 + nt * 8 + 2 * tig + (e & 1);
                    const int ktp = nl >> 5;
                    const int w = ((nl & 3) << 3) + ((nl >> 2) & 7);
                    Ps[(ktp * 64 + m) * 32 + (w ^ gsw)] = __float_as_uint(sa[mt][nt][e]);
                }
        __syncthreads();

#pragma unroll
        for (int mt = 0; mt < 2; ++mt)
#pragma unroll
            for (int rh = 0; rh < 2; ++rh) {
                const int m = wm * 32 + mt * 16 + g + 8 * rh;
                const float s4 = (reds[m * 4 + 0] + reds[m * 4 + 1]) +
                                 (reds[m * 4 + 2] + reds[m * 4 + 3]);
                lrow[mt][rh] = lrow[mt][rh] * alpha[mt][rh] + s4;
            }
#pragma unroll
        for (int mt = 0; mt < 2; ++mt)
#pragma unroll
            for (int nt = 0; nt < 4; ++nt)
#pragma unroll
                for (int e = 0; e < 4; ++e)
                    Oa[mt][nt][e] *= alpha[mt][e >> 1];

#pragma unroll
        for (int ktp = 0; ktp < 2; ++ktp) {
            const uint32_t* sP = Ps + ktp * 2048;
            const uint32_t* sV = Vb + ktp * 4096;
#pragma unroll
            for (int kh = 0; kh < 2; ++kh) {
                const int wk = (tig * 8 + 4 * kh) ^ gsw;
                uint4 bf[4];
#pragma unroll
                for (int nt = 0; nt < 4; ++nt) {
                    const int rd = wn * 32 + nt * 8 + g;
                    bf[nt] = *(const uint4*)(sV + rd * 32 + wk);
                }
#pragma unroll
                for (int mt = 0; mt < 2; ++mt) {
                    const int r = wm * 32 + mt * 16 + g;
                    const uint4 a0 = *(const uint4*)(sP + r * 32 + wk);
                    const uint4 a1 = *(const uint4*)(sP + (r + 8) * 32 + wk);
#pragma unroll
                    for (int nt = 0; nt < 4; ++nt) {
                        mma_tf32(Oa[mt][nt], a0.x, a1.x, a0.y, a1.y, bf[nt].x, bf[nt].y);
                        mma_tf32(Oa[mt][nt], a0.z, a1.z, a0.w, a1.w, bf[nt].z, bf[nt].w);
                    }
                }
            }
        }
    }

    float* zb = z + ((size_t)(b * SEQ + qt * 64)) * EMB + h * HDIM;
#pragma unroll
    for (int mt = 0; mt < 2; ++mt) {
        const int r0 = wm * 32 + mt * 16 + g;
        const int r1 = r0 + 8;
        const float inv0 = 1.0f / lrow[mt][0];
        const float inv1 = 1.0f / lrow[mt][1];
#pragma unroll
        for (int nt = 0; nt < 4; ++nt) {
            const int d = wn * 32 + nt * 8 + 2 * tig;
            *(float2*)(zb + (size_t)r0 * EMB + d) =
                make_float2(Oa[mt][nt][0] * inv0, Oa[mt][nt][1] * inv0);
            *(float2*)(zb + (size_t)r1 * EMB + d) =
                make_float2(Oa[mt][nt][2] * inv1, Oa[mt][nt][3] * inv1);
        }
    }
}

// ===========================================================================
extern "C" void kernel_launch(void* const* d_in, const int* in_sizes, int n_in,
                              void* d_out, int out_size)
{
    (void)in_sizes; (void)n_in; (void)out_size;
    const float* x   = (const float*)d_in[0];
    const float* Wq  = (const float*)d_in[1];
    const float* Wk  = (const float*)d_in[2];
    const float* Wv  = (const float*)d_in[3];
    const float* Wo  = (const float*)d_in[4];
    const int*   isc = (const int*)d_in[5];

    float *q, *k, *v, *z;
    cudaGetSymbolAddress((void**)&q, g_q);
    cudaGetSymbolAddress((void**)&k, g_k);
    cudaGetSymbolAddress((void**)&v, g_v);
    cudaGetSymbolAddress((void**)&z, g_z);

    uint32_t *xh, *zh, *wqh, *wkh, *wvh, *woh, *wol;
    cudaGetSymbolAddress((void**)&xh,  g_xh);
    cudaGetSymbolAddress((void**)&zh,  g_zh);
    cudaGetSymbolAddress((void**)&wqh, g_wqh);
    cudaGetSymbolAddress((void**)&wkh, g_wkh);
    cudaGetSymbolAddress((void**)&wvh, g_wvh);
    cudaGetSymbolAddress((void**)&woh, g_woh);
    cudaGetSymbolAddress((void**)&wol, g_wol);

    cudaFuncSetAttribute(qkv_gemm, cudaFuncAttributeMaxDynamicSharedMemorySize, QKV_SMEM_BYTES);
    cudaFuncSetAttribute(o_gemm,   cudaFuncAttributeMaxDynamicSharedMemorySize, O_SMEM_BYTES);
    cudaFuncSetAttribute(flash_attn3, cudaFuncAttributeMaxDynamicSharedMemorySize, FA3_SMEM_BYTES);

    dim3 blk(256);

    // ---- pre-split operands (x, Wq, Wk, Wv: hi only; Wo: hi+lo) ----
    split_hi  <<<2048, 256>>>(x,  xh,  MROWS);
    split_hi  <<<1024, 256>>>(Wq, wqh, EMB);
    split_hi  <<<512,  256>>>(Wk, wkh, KVDIM);
    split_hi  <<<512,  256>>>(Wv, wvh, KVDIM);
    split_hilo<<<1024, 256>>>(Wo, woh, wol, EMB);

    // ---- fused Q/K/V projection (tf32x1, outputs rounded for fa3) ----
    qkv_gemm<<<768, blk, QKV_SMEM_BYTES>>>(xh, wqh, wkh, wvh, q, k, v);

    // ---- tensor-core flash attention ----
    flash_attn3<<<dim3(SEQ / 64, NHEADS, BATCH), blk, FA3_SMEM_BYTES>>>(q, k, v, z, isc);

    // ---- output projection (tf32x2) ----
    split_hi<<<2048, 256>>>(z, zh, MROWS);
    o_gemm<<<dim3(EMB / 128, MROWS / 128), blk, O_SMEM_BYTES>>>(zh, woh, wol,
                                                                (float*)d_out);
}

// round 11
// speedup vs baseline: 3.2771x; 1.3675x over previous
#include <cuda_runtime.h>
#include <math.h>
#include <stdint.h>

#define EMB    2048
#define SEQ    2048
#define BATCH  2
#define NHEADS 16
#define NKVH   4
#define HDIM   128
#define KVDIM  (NKVH * HDIM)      /* 512  */
#define MROWS  (BATCH * SEQ)      /* 4096 */
#define NKT    64                 /* K / 32 (K = 2048 for every GEMM) */

// -------- scratch (device globals: no allocations allowed) ----------------
// tf32 fragment-permuted operand buffers
__device__ uint32_t g_xh[(size_t)MROWS * EMB];          // x   (A, hi)
__device__ uint32_t g_zh[(size_t)MROWS * EMB];          // z   (A, hi) - written by fa3
__device__ uint32_t g_wqh[(size_t)EMB * EMB];           // weights, hi only
__device__ uint32_t g_wkh[(size_t)KVDIM * EMB];
__device__ uint32_t g_wvh[(size_t)KVDIM * EMB];
__device__ uint32_t g_woh[(size_t)EMB * EMB];
// q/k/v in fa3 fragment layout (written by qkv_gemm epilogue)
__device__ uint32_t g_qp[(size_t)BATCH * NHEADS * SEQ * HDIM];  // [b,h][qtile][kt4][64][32]
__device__ uint32_t g_kp[(size_t)BATCH * NKVH  * SEQ * HDIM];   // [b,kvh][ktile][kt4][64][32]
__device__ uint32_t g_vp[(size_t)BATCH * NKVH  * SEQ * HDIM];   // [b,kvh][ktile][ktp2][128][32]

// ===========================================================================
// helpers
// ===========================================================================
__device__ __forceinline__ uint32_t smem_u32(const void* p) {
    uint32_t a;
    asm("{ .reg .u64 t; cvta.to.shared.u64 t, %1; cvt.u32.u64 %0, t; }"
        : "=r"(a) : "l"(p));
    return a;
}

__device__ __forceinline__ uint32_t tf32_hi(float x) {
    uint32_t h;
    asm("cvt.rna.tf32.f32 %0, %1;" : "=r"(h) : "f"(x));
    return h;
}

__device__ __forceinline__ void mma_tf32(float* d,
                                         uint32_t a0, uint32_t a1,
                                         uint32_t a2, uint32_t a3,
                                         uint32_t b0, uint32_t b1) {
    asm volatile(
        "mma.sync.aligned.m16n8k8.row.col.f32.tf32.tf32.f32 "
        "{%0,%1,%2,%3}, {%4,%5,%6,%7}, {%8,%9}, {%0,%1,%2,%3};"
        : "+f"(d[0]), "+f"(d[1]), "+f"(d[2]), "+f"(d[3])
        : "r"(a0), "r"(a1), "r"(a2), "r"(a3), "r"(b0), "r"(b1));
}

__device__ __forceinline__ void cp16(uint32_t smem_dst, const void* gmem_src) {
    asm volatile("cp.async.cg.shared.global [%0], [%1], 16;"
                 :: "r"(smem_dst), "l"(gmem_src));
}
#define CP_COMMIT()  asm volatile("cp.async.commit_group;" ::: "memory")
#define CP_WAIT2()   asm volatile("cp.async.wait_group 2;" ::: "memory")
#define CP_WAIT1()   asm volatile("cp.async.wait_group 1;" ::: "memory")
#define CP_WAIT0()   asm volatile("cp.async.wait_group 0;" ::: "memory")

// ===========================================================================
// split: fp32 row-major [Mrows][2048] -> tf32-hi fragment-permuted tile layout
//   word[(kt*Mrows + row)*32 + ((8*(col&3) + ((col>>2)&7)) ^ ((row&7)<<2))]
// ===========================================================================
__global__ void split_hi(const float* __restrict__ in, uint32_t* __restrict__ hi,
                         int Mrows)
{
    const int n4 = Mrows * (EMB >> 2);
    for (int t = blockIdx.x * blockDim.x + threadIdx.x; t < n4;
         t += gridDim.x * blockDim.x) {
        const int cg  = t & ((EMB >> 2) - 1);
        const int row = t >> 9;
        float4 v = *(const float4*)(in + (size_t)row * EMB + cg * 4);
        const int kt = cg >> 3;
        const int c7 = cg & 7;
        const size_t base = ((size_t)kt * Mrows + row) * 32;
        const int sw = (row & 7) << 2;
        float va[4] = { v.x, v.y, v.z, v.w };
#pragma unroll
        for (int j = 0; j < 4; ++j)
            hi[base + (((j << 3) + c7) ^ sw)] = tf32_hi(va[j]);
    }
}

// ===========================================================================
// tf32x1 GEMM core (mma.sync): C[M,N] = A[M,K] * B[N,K]^T
// CTA 128x128, BK=32, 256 threads = 8 warps (2m x 4n), 4-stage cp.async.
// mode 0: plain fp32 row-major output (o_gemm)
// mode 1: Q -> g_qp fragment layout (+RoPE, +1/sqrt(d))
// mode 2: K -> g_kp fragment layout (+RoPE)
// mode 3: V -> g_vp fragment layout (transposed V^T fragment layout)
// ===========================================================================
#define STG_WORDS 8192                        /* 2 arrays * 4096 */
#define GEMM_SMEM_BYTES (4 * STG_WORDS * 4)   /* 131072 */

__device__ __forceinline__ void issue_stage(
    uint32_t sm_stage_byte,
    const uint32_t* __restrict__ Ah, const uint32_t* __restrict__ Bh,
    int kt, int Md, int Nd, int arow0, int brow0, int tid)
{
    const uint32_t* srcs[2] = {
        Ah + ((size_t)kt * Md + arow0) * 32,
        Bh + ((size_t)kt * Nd + brow0) * 32 };
#pragma unroll
    for (int arr = 0; arr < 2; ++arr) {
        const uint32_t dbase = sm_stage_byte + arr * 16384;
        const char* s = (const char*)srcs[arr];
#pragma unroll
        for (int i = 0; i < 4; ++i) {
            const int id = tid + i * 256;
            cp16(dbase + id * 16, s + (size_t)id * 16);
        }
    }
}

__device__ __forceinline__ void gemm_core(
    const uint32_t* __restrict__ Ah, const uint32_t* __restrict__ Bh,
    float* __restrict__ Cf, uint32_t* __restrict__ Cp, int mode,
    int Md, int Nd, int bm, int bn, uint32_t* smx)
{
    const uint32_t sbyte = smem_u32(smx);
    const int tid  = threadIdx.x;
    const int wid  = tid >> 5;
    const int lane = tid & 31;
    const int g    = lane >> 2;
    const int tig  = lane & 3;
    const int wm   = wid >> 2;
    const int wn   = wid & 3;
    const int arow0 = bm * 128;
    const int brow0 = bn * 128;

    float acc[4][4][4];
#pragma unroll
    for (int mt = 0; mt < 4; ++mt)
#pragma unroll
        for (int nt = 0; nt < 4; ++nt)
#pragma unroll
            for (int e = 0; e < 4; ++e) acc[mt][nt][e] = 0.f;

#pragma unroll
    for (int s = 0; s < 3; ++s) {
        issue_stage(sbyte + s * STG_WORDS * 4, Ah, Bh, s,
                    Md, Nd, arow0, brow0, tid);
        CP_COMMIT();
    }

    const int gsw = g << 2;

    for (int kt = 0; kt < NKT; ++kt) {
        const int buf = kt & 3;
        CP_WAIT2();
        __syncthreads();

        const uint32_t* sAh = smx + buf * STG_WORDS;
        const uint32_t* sBh = sAh + 4096;

#pragma unroll
        for (int kh = 0; kh < 2; ++kh) {
            const int wk = (tig * 8 + 4 * kh) ^ gsw;
            uint4 bh4[4];
#pragma unroll
            for (int nt = 0; nt < 4; ++nt) {
                const int rn = wn * 32 + nt * 8 + g;
                bh4[nt] = *(const uint4*)(sBh + rn * 32 + wk);
            }
#pragma unroll
            for (int mt = 0; mt < 4; ++mt) {
                const int r = wm * 64 + mt * 16 + g;
                const uint4 ah0 = *(const uint4*)(sAh + r * 32 + wk);
                const uint4 ah1 = *(const uint4*)(sAh + (r + 8) * 32 + wk);
#pragma unroll
                for (int nt = 0; nt < 4; ++nt) {
                    mma_tf32(acc[mt][nt], ah0.x, ah1.x, ah0.y, ah1.y, bh4[nt].x, bh4[nt].y);
                    mma_tf32(acc[mt][nt], ah0.z, ah1.z, ah0.w, ah1.w, bh4[nt].z, bh4[nt].w);
                }
            }
        }

        __syncthreads();
        if (kt + 3 < NKT)
            issue_stage(sbyte + ((kt + 3) & 3) * STG_WORDS * 4, Ah, Bh,
                        kt + 3, Md, Nd, arow0, brow0, tid);
        CP_COMMIT();
    }

    // ---------------- epilogue -----------------
    const bool rope = (mode == 1 || mode == 2);
    const bool qsc  = (mode == 1);
    const float qscale = 0.08838834764831844f;    // 1/sqrt(128)
    float freqv[4];
    if (rope) {
#pragma unroll
        for (int nt = 0; nt < 4; ++nt) {
            const int cl = wn * 32 + nt * 8 + tig * 2;   // local col (head dim)
            freqv[nt] = (float)exp((double)(cl >> 1) * -0.14391156831212787);
        }
    }
#pragma unroll
    for (int mt = 0; mt < 4; ++mt) {
        const int r0 = bm * 128 + wm * 64 + mt * 16 + g;
        const int r1 = r0 + 8;
        float t0 = 0.f, t1 = 0.f;
        if (rope) {
            t0 = (float)(r0 & (SEQ - 1)) * 6.28318530717958647692f;
            t1 = (float)(r1 & (SEQ - 1)) * 6.28318530717958647692f;
        }
#pragma unroll
        for (int nt = 0; nt < 4; ++nt) {
            float* a = acc[mt][nt];
            if (rope) {
#pragma unroll
                for (int hrow = 0; hrow < 2; ++hrow) {
                    const float ang = (hrow ? t1 : t0) * freqv[nt];
                    float kq = rintf(ang * 0.15915494309189535f);
                    float xx = fmaf(kq, -6.28125f, ang);
                    xx       = fmaf(kq, -0.0019353071795864769f, xx);
                    const float sn = sinf(xx), cs = cosf(xx);
                    const float v0 = a[hrow * 2 + 0], v1 = a[hrow * 2 + 1];
                    a[hrow * 2 + 0] = v0 * cs - v1 * sn;
                    a[hrow * 2 + 1] = v0 * sn + v1 * cs;
                }
            }
            if (qsc) {
#pragma unroll
                for (int e = 0; e < 4; ++e) a[e] *= qscale;
            }
            if (mode == 0) {
                const int col = bn * 128 + wn * 32 + nt * 8 + tig * 2;
                *(float2*)(Cf + (size_t)r0 * Nd + col) = make_float2(a[0], a[1]);
                *(float2*)(Cf + (size_t)r1 * Nd + col) = make_float2(a[2], a[3]);
            } else {
                const int cl = wn * 32 + nt * 8 + tig * 2;   // 0..127, even
#pragma unroll
                for (int rp = 0; rp < 2; ++rp) {
                    const int gr = rp ? r1 : r0;             // global row
                    const uint32_t u0 = tf32_hi(a[rp * 2 + 0]);
                    const uint32_t u1 = tf32_hi(a[rp * 2 + 1]);
                    const int bb = gr >> 11, ss = gr & 2047;
                    const int tile = ss >> 6, n = ss & 63;
                    if (mode == 3) {
                        const int ktp = n >> 5;
                        const int w = ((n & 3) << 3) + ((n >> 2) & 7);
                        uint32_t* dst = Cp +
                            ((((size_t)(bb * 4 + bn) * 32 + tile) * 2 + ktp) * 128) * 32;
                        dst[(size_t)cl * 32 + (w ^ ((cl & 7) << 2))]             = u0;
                        dst[(size_t)(cl + 1) * 32 + (w ^ (((cl + 1) & 7) << 2))] = u1;
                    } else {
                        const int nh = (mode == 1) ? NHEADS : NKVH;
                        const int kt = cl >> 5;
                        const int sw = (n & 7) << 2;
                        uint32_t* dst = Cp +
                            ((((size_t)(bb * nh + bn) * 32 + tile) * 4 + kt) * 64 + n) * 32;
                        dst[((((cl    ) & 3) << 3) + (((cl    ) >> 2) & 7)) ^ sw] = u0;
                        dst[((((cl + 1) & 3) << 3) + (((cl + 1) >> 2) & 7)) ^ sw] = u1;
                    }
                }
            }
        }
    }
}

// fused Q/K/V projection: 768 CTAs (Q:512, K:128, V:128), tf32x1,
// outputs written directly into fa3 fragment-permuted layouts
__global__ __launch_bounds__(256)
void qkv_gemm(const uint32_t* __restrict__ xh,
              const uint32_t* __restrict__ wqh,
              const uint32_t* __restrict__ wkh,
              const uint32_t* __restrict__ wvh,
              uint32_t* __restrict__ qp, uint32_t* __restrict__ kp,
              uint32_t* __restrict__ vp)
{
    extern __shared__ uint32_t smx[];
    const int id = blockIdx.x;
    const uint32_t* Bh;
    uint32_t* Cp;
    int bm, bn, Nd, mode;
    if (id < 512)      { bm = id >> 4;  bn = id & 15; Bh = wqh; Cp = qp; Nd = EMB;   mode = 1; }
    else if (id < 640) { int t = id - 512; bm = t >> 2; bn = t & 3; Bh = wkh; Cp = kp; Nd = KVDIM; mode = 2; }
    else               { int t = id - 640; bm = t >> 2; bn = t & 3; Bh = wvh; Cp = vp; Nd = KVDIM; mode = 3; }
    gemm_core(xh, Bh, (float*)0, Cp, mode, MROWS, Nd, bm, bn, smx);
}

__global__ __launch_bounds__(256)
void o_gemm(const uint32_t* __restrict__ zh,
            const uint32_t* __restrict__ woh,
            float* __restrict__ out)
{
    extern __shared__ uint32_t smx[];
    gemm_core(zh, woh, out, (uint32_t*)0, 0, MROWS, EMB,
              blockIdx.y, blockIdx.x, smx);
}

// ===========================================================================
// Flash attention v4 — tensor core, pre-permuted operands + cp.async pipeline.
// BM=BN=64, D=128, 8 warps. Writes z directly in o_gemm's A layout (tf32 hi).
// smem (words): Qs 8192 | Ks 2x8192 | Vt 2x8192 | Ps 4096 | redm 256 | reds 256
// ===========================================================================
#define FA_SMEM_BYTES (45568 * 4)   /* 182272 */

__global__ __launch_bounds__(256)
void flash_attn4(const uint32_t* __restrict__ qp, const uint32_t* __restrict__ kp,
                 const uint32_t* __restrict__ vp, uint32_t* __restrict__ zh,
                 const int* __restrict__ is_causal)
{
    extern __shared__ uint32_t sm[];
    uint32_t* Qs = sm;                 // 8192
    uint32_t* Ks = sm + 8192;          // 2 x 8192
    uint32_t* Vt = sm + 24576;         // 2 x 8192
    uint32_t* Ps = sm + 40960;         // 4096
    float* redm  = (float*)(sm + 45056);
    float* reds  = (float*)(sm + 45312);

    const uint32_t sbyte = smem_u32(sm);
    const int tid  = threadIdx.x;
    const int lane = tid & 31, wid = tid >> 5;
    const int g    = lane >> 2, tig = lane & 3;
    const int wm   = wid >> 2,  wn  = wid & 3;
    const int qt = blockIdx.x, h = blockIdx.y, b = blockIdx.z;
    const int kvh = h >> 2;
    const bool causal = (*is_causal) != 0;
    const int gsw = g << 2;

    const int kend = causal ? qt : (SEQ / 64 - 1);
    const uint32_t* kbase = kp + ((size_t)(b * NKVH + kvh) * 32) * 8192;
    const uint32_t* vbase = vp + ((size_t)(b * NKVH + kvh) * 32) * 8192;

    // ---- group 0: Q + K0 + V0 (linear cp.async) ----
    {
        const uint32_t* qsrc = qp + (((size_t)(b * NHEADS + h) * 32) + qt) * 8192;
#pragma unroll
        for (int i = 0; i < 8; ++i) {
            const int id = tid + i * 256;
            cp16(sbyte + id * 16, qsrc + (size_t)id * 4);
        }
#pragma unroll
        for (int i = 0; i < 8; ++i) {
            const int id = tid + i * 256;
            cp16(sbyte + 32768 + id * 16, kbase + (size_t)id * 4);
        }
#pragma unroll
        for (int i = 0; i < 8; ++i) {
            const int id = tid + i * 256;
            cp16(sbyte + 98304 + id * 16, vbase + (size_t)id * 4);
        }
        CP_COMMIT();
    }

    float mrow[2][2], lrow[2][2], Oa[2][4][4];
#pragma unroll
    for (int mt = 0; mt < 2; ++mt)
#pragma unroll
        for (int rh = 0; rh < 2; ++rh) { mrow[mt][rh] = -1e30f; lrow[mt][rh] = 0.f; }
#pragma unroll
    for (int mt = 0; mt < 2; ++mt)
#pragma unroll
        for (int nt = 0; nt < 4; ++nt)
#pragma unroll
            for (int e = 0; e < 4; ++e) Oa[mt][nt][e] = 0.f;

    for (int kn = 0; kn <= kend; ++kn) {
        const int buf = kn & 1;
        if (kn < kend) {
            const int nb = (kn + 1) & 1;
            const uint32_t* ks = kbase + (size_t)(kn + 1) * 8192;
            const uint32_t* vs = vbase + (size_t)(kn + 1) * 8192;
#pragma unroll
            for (int i = 0; i < 8; ++i) {
                const int id = tid + i * 256;
                cp16(sbyte + 32768 + nb * 32768 + id * 16, ks + (size_t)id * 4);
            }
#pragma unroll
            for (int i = 0; i < 8; ++i) {
                const int id = tid + i * 256;
                cp16(sbyte + 98304 + nb * 32768 + id * 16, vs + (size_t)id * 4);
            }
            CP_COMMIT();
            CP_WAIT1();
        } else {
            CP_WAIT0();
        }
        __syncthreads();

        const uint32_t* Kb = Ks + buf * 8192;
        const uint32_t* Vb = Vt + buf * 8192;

        // ---- S = Q K^T ----
        float sa[2][2][4];
#pragma unroll
        for (int mt = 0; mt < 2; ++mt)
#pragma unroll
            for (int nt = 0; nt < 2; ++nt)
#pragma unroll
                for (int e = 0; e < 4; ++e) sa[mt][nt][e] = 0.f;

#pragma unroll
        for (int kt = 0; kt < 4; ++kt) {
            const uint32_t* sQ = Qs + kt * 2048;
            const uint32_t* sK = Kb + kt * 2048;
#pragma unroll
            for (int kh = 0; kh < 2; ++kh) {
                const int wk = (tig * 8 + 4 * kh) ^ gsw;
                uint4 bf[2];
#pragma unroll
                for (int nt = 0; nt < 2; ++nt) {
                    const int rn = wn * 16 + nt * 8 + g;
                    bf[nt] = *(const uint4*)(sK + rn * 32 + wk);
                }
#pragma unroll
                for (int mt = 0; mt < 2; ++mt) {
                    const int r = wm * 32 + mt * 16 + g;
                    const uint4 a0 = *(const uint4*)(sQ + r * 32 + wk);
                    const uint4 a1 = *(const uint4*)(sQ + (r + 8) * 32 + wk);
#pragma unroll
                    for (int nt = 0; nt < 2; ++nt) {
                        mma_tf32(sa[mt][nt], a0.x, a1.x, a0.y, a1.y, bf[nt].x, bf[nt].y);
                        mma_tf32(sa[mt][nt], a0.z, a1.z, a0.w, a1.w, bf[nt].z, bf[nt].w);
                    }
                }
            }
        }

        if (causal && kn == qt) {
#pragma unroll
            for (int mt = 0; mt < 2; ++mt)
#pragma unroll
                for (int nt = 0; nt < 2; ++nt)
#pragma unroll
                    for (int e = 0; e < 4; ++e) {
                        const int m  = wm * 32 + mt * 16 + g + 8 * (e >> 1);
                        const int nl = wn * 16 + nt * 8 + 2 * tig + (e & 1);
                        if (nl > m) sa[mt][nt][e] = -1e30f;
                    }
        }

        // ---- online softmax (cross-warp via smem) ----
        float tmx[2][2];
#pragma unroll
        for (int mt = 0; mt < 2; ++mt)
#pragma unroll
            for (int rh = 0; rh < 2; ++rh) {
                float t = fmaxf(fmaxf(sa[mt][0][rh * 2], sa[mt][0][rh * 2 + 1]),
                                fmaxf(sa[mt][1][rh * 2], sa[mt][1][rh * 2 + 1]));
                t = fmaxf(t, __shfl_xor_sync(0xffffffffu, t, 1));
                t = fmaxf(t, __shfl_xor_sync(0xffffffffu, t, 2));
                tmx[mt][rh] = t;
            }
        if (tig == 0) {
#pragma unroll
            for (int mt = 0; mt < 2; ++mt)
#pragma unroll
                for (int rh = 0; rh < 2; ++rh)
                    redm[(wm * 32 + mt * 16 + g + 8 * rh) * 4 + wn] = tmx[mt][rh];
        }
        __syncthreads();

        float alpha[2][2];
#pragma unroll
        for (int mt = 0; mt < 2; ++mt)
#pragma unroll
            for (int rh = 0; rh < 2; ++rh) {
                const int m = wm * 32 + mt * 16 + g + 8 * rh;
                const float tm = fmaxf(fmaxf(redm[m * 4 + 0], redm[m * 4 + 1]),
                                       fmaxf(redm[m * 4 + 2], redm[m * 4 + 3]));
                const float mnew = fmaxf(mrow[mt][rh], tm);
                alpha[mt][rh] = __expf(mrow[mt][rh] - mnew);
                mrow[mt][rh]  = mnew;
            }

        float psum[2][2] = { {0.f, 0.f}, {0.f, 0.f} };
#pragma unroll
        for (int mt = 0; mt < 2; ++mt)
#pragma unroll
            for (int nt = 0; nt < 2; ++nt)
#pragma unroll
                for (int e = 0; e < 4; ++e) {
                    const int rh = e >> 1;
                    float pv = __expf(sa[mt][nt][e] - mrow[mt][rh]);
                    pv = __uint_as_float(tf32_hi(pv));
                    sa[mt][nt][e] = pv;
                    psum[mt][rh] += pv;
                }
#pragma unroll
        for (int mt = 0; mt < 2; ++mt)
#pragma unroll
            for (int rh = 0; rh < 2; ++rh) {
                psum[mt][rh] += __shfl_xor_sync(0xffffffffu, psum[mt][rh], 1);
                psum[mt][rh] += __shfl_xor_sync(0xffffffffu, psum[mt][rh], 2);
            }
        if (tig == 0) {
#pragma unroll
            for (int mt = 0; mt < 2; ++mt)
#pragma unroll
                for (int rh = 0; rh < 2; ++rh)
                    reds[(wm * 32 + mt * 16 + g + 8 * rh) * 4 + wn] = psum[mt][rh];
        }

        // ---- write P into fragment layout ----
#pragma unroll
        for (int mt = 0; mt < 2; ++mt)
#pragma unroll
            for (int nt = 0; nt < 2; ++nt)
#pragma unroll
                for (int e = 0; e < 4; ++e) {
                    const int m  = wm * 32 + mt * 16 + g + 8 * (e >> 1);
                    const int nl = wn * 16 + nt * 8 + 2 * tig + (e & 1);
                    const int ktp = nl >> 5;
                    const int w = ((nl & 3) << 3) + ((nl >> 2) & 7);
                    Ps[(ktp * 64 + m) * 32 + (w ^ gsw)] = __float_as_uint(sa[mt][nt][e]);
                }
        __syncthreads();

#pragma unroll
        for (int mt = 0; mt < 2; ++mt)
#pragma unroll
            for (int rh = 0; rh < 2; ++rh) {
                const int m = wm * 32 + mt * 16 + g + 8 * rh;
                const float s4 = (reds[m * 4 + 0] + reds[m * 4 + 1]) +
                                 (reds[m * 4 + 2] + reds[m * 4 + 3]);
                lrow[mt][rh] = lrow[mt][rh] * alpha[mt][rh] + s4;
            }
#pragma unroll
        for (int mt = 0; mt < 2; ++mt)
#pragma unroll
            for (int nt = 0; nt < 4; ++nt)
#pragma unroll
                for (int e = 0; e < 4; ++e)
                    Oa[mt][nt][e] *= alpha[mt][e >> 1];

        // ---- O += P V ----
#pragma unroll
        for (int ktp = 0; ktp < 2; ++ktp) {
            const uint32_t* sP = Ps + ktp * 2048;
            const uint32_t* sV = Vb + ktp * 4096;
#pragma unroll
            for (int kh = 0; kh < 2; ++kh) {
                const int wk = (tig * 8 + 4 * kh) ^ gsw;
                uint4 bf[4];
#pragma unroll
                for (int nt = 0; nt < 4; ++nt) {
                    const int rd = wn * 32 + nt * 8 + g;
                    bf[nt] = *(const uint4*)(sV + rd * 32 + wk);
                }
#pragma unroll
                for (int mt = 0; mt < 2; ++mt) {
                    const int r = wm * 32 + mt * 16 + g;
                    const uint4 a0 = *(const uint4*)(sP + r * 32 + wk);
                    const uint4 a1 = *(const uint4*)(sP + (r + 8) * 32 + wk);
#pragma unroll
                    for (int nt = 0; nt < 4; ++nt) {
                        mma_tf32(Oa[mt][nt], a0.x, a1.x, a0.y, a1.y, bf[nt].x, bf[nt].y);
                        mma_tf32(Oa[mt][nt], a0.z, a1.z, a0.w, a1.w, bf[nt].z, bf[nt].w);
                    }
                }
            }
        }
        __syncthreads();   // protect K/V buffer reuse by next iteration's cp.async
    }

    // ---- finalize: O / l -> zh (o_gemm A layout, tf32 hi) ----
#pragma unroll
    for (int mt = 0; mt < 2; ++mt) {
        const int r0 = wm * 32 + mt * 16 + g;
        const int r1 = r0 + 8;
        const int gm0 = b * SEQ + qt * 64 + r0;
        const int gm1 = gm0 + 8;
        const float inv0 = 1.0f / lrow[mt][0];
        const float inv1 = 1.0f / lrow[mt][1];
        const int sw0 = (r0 & 7) << 2;
        const int sw1 = (r1 & 7) << 2;
#pragma unroll
        for (int nt = 0; nt < 4; ++nt) {
            const int d = wn * 32 + nt * 8 + 2 * tig;
            const int c = h * HDIM + d;
            const int kt = c >> 5;
            const int w0 = ((d & 3) << 3) + ((d >> 2) & 7);
            const int w1 = (((d + 1) & 3) << 3) + (((d + 1) >> 2) & 7);
            uint32_t* z0 = zh + ((size_t)kt * MROWS + gm0) * 32;
            uint32_t* z1 = zh + ((size_t)kt * MROWS + gm1) * 32;
            z0[w0 ^ sw0] = tf32_hi(Oa[mt][nt][0] * inv0);
            z0[w1 ^ sw0] = tf32_hi(Oa[mt][nt][1] * inv0);
            z1[w0 ^ sw1] = tf32_hi(Oa[mt][nt][2] * inv1);
            z1[w1 ^ sw1] = tf32_hi(Oa[mt][nt][3] * inv1);
        }
    }
}

// ===========================================================================
extern "C" void kernel_launch(void* const* d_in, const int* in_sizes, int n_in,
                              void* d_out, int out_size)
{
    (void)in_sizes; (void)n_in; (void)out_size;
    const float* x   = (const float*)d_in[0];
    const float* Wq  = (const float*)d_in[1];
    const float* Wk  = (const float*)d_in[2];
    const float* Wv  = (const float*)d_in[3];
    const float* Wo  = (const float*)d_in[4];
    const int*   isc = (const int*)d_in[5];

    uint32_t *xh, *zh, *wqh, *wkh, *wvh, *woh, *qpp, *kpp, *vpp;
    cudaGetSymbolAddress((void**)&xh,  g_xh);
    cudaGetSymbolAddress((void**)&zh,  g_zh);
    cudaGetSymbolAddress((void**)&wqh, g_wqh);
    cudaGetSymbolAddress((void**)&wkh, g_wkh);
    cudaGetSymbolAddress((void**)&wvh, g_wvh);
    cudaGetSymbolAddress((void**)&woh, g_woh);
    cudaGetSymbolAddress((void**)&qpp, g_qp);
    cudaGetSymbolAddress((void**)&kpp, g_kp);
    cudaGetSymbolAddress((void**)&vpp, g_vp);

    cudaFuncSetAttribute(qkv_gemm, cudaFuncAttributeMaxDynamicSharedMemorySize, GEMM_SMEM_BYTES);
    cudaFuncSetAttribute(o_gemm,   cudaFuncAttributeMaxDynamicSharedMemorySize, GEMM_SMEM_BYTES);
    cudaFuncSetAttribute(flash_attn4, cudaFuncAttributeMaxDynamicSharedMemorySize, FA_SMEM_BYTES);

    dim3 blk(256);

    // ---- pre-split operands (all hi-only now) ----
    split_hi<<<2048, 256>>>(x,  xh,  MROWS);
    split_hi<<<1024, 256>>>(Wq, wqh, EMB);
    split_hi<<<512,  256>>>(Wk, wkh, KVDIM);
    split_hi<<<512,  256>>>(Wv, wvh, KVDIM);
    split_hi<<<1024, 256>>>(Wo, woh, EMB);

    // ---- fused Q/K/V projection (outputs in fa4 fragment layouts) ----
    qkv_gemm<<<768, blk, GEMM_SMEM_BYTES>>>(xh, wqh, wkh, wvh, qpp, kpp, vpp);

    // ---- tensor-core flash attention (writes zh in o_gemm A layout) ----
    flash_attn4<<<dim3(SEQ / 64, NHEADS, BATCH), blk, FA_SMEM_BYTES>>>(qpp, kpp, vpp, zh, isc);

    // ---- output projection (tf32x1) ----
    o_gemm<<<dim3(EMB / 128, MROWS / 128), blk, GEMM_SMEM_BYTES>>>(zh, woh, (float*)d_out);
}